// round 1
// baseline (speedup 1.0000x reference)
#include <cuda_runtime.h>
#include <math.h>
#include <stdint.h>

#define BB   4
#define LL   4096
#define DM   1024
#define DI   1024
#define DTR  64
#define RTOT 66          // DT_RANK + 2*D_STATE
#define RPAD 68          // padded row stride for x_dbl (multiple of 4 for float4)
#define NTOK (BB*LL)     // 16384

// ---------------- scratch (device globals: allocation-free) ----------------
__device__ __align__(16) float g_xz  [(size_t)NTOK * 2 * DI]; // [tok, 2048]  xc|z pre-conv
__device__ __align__(16) float g_xc  [(size_t)NTOK * DI];     // conv+silu activations
__device__ __align__(16) float g_xdbl[(size_t)NTOK * RPAD];   // [tok, 68]: dts(64), Bs, Cs
__device__ __align__(16) float g_dt  [(size_t)NTOK * DI];     // dt proj, then overwritten with dA
__device__ __align__(16) float g_dbu [(size_t)NTOK * DI];     // delta*Bs*u
__device__ __align__(16) float g_y   [(size_t)NTOK * DI];     // scan output (pre-LN)
__device__ __align__(16) float g_yln [(size_t)NTOK * DI];     // post-LN, gated
__device__ __align__(16) float g_A   [DI];                    // -exp(A_logs)

// ---------------- generic fp32 GEMM:  C[M,N] = A[M,K] * B[N,K]^T ----------------
// A row-major lda, B row-major ldb (weights are [out,in]), C row-major ldc.
// Requires: M % BM == 0, K % BK == 0, lda/ldb %4 == 0, pointers 16B aligned.
// N may be ragged (guarded loads/stores on the B/N direction).
template<int BM, int BN, int BK, int TM, int TN>
__global__ void __launch_bounds__((BM/TM)*(BN/TN))
gemm_tn(const float* __restrict__ A, int lda,
        const float* __restrict__ B, int ldb,
        float* __restrict__ C, int ldc,
        int N, int K)
{
    constexpr int THREADS = (BM/TM) * (BN/TN);
    __shared__ float As[BK][BM + 1];
    __shared__ float Bs[BK][BN + 1];

    const int tid = threadIdx.x;
    const int m0  = blockIdx.y * BM;
    const int n0  = blockIdx.x * BN;
    const int tx  = tid % (BN / TN);
    const int ty  = tid / (BN / TN);

    float acc[TM][TN];
#pragma unroll
    for (int i = 0; i < TM; i++)
#pragma unroll
        for (int j = 0; j < TN; j++) acc[i][j] = 0.f;

    for (int k0 = 0; k0 < K; k0 += BK) {
        // load A tile (transposed into smem)
#pragma unroll
        for (int i = tid; i < BM * BK / 4; i += THREADS) {
            int row = i / (BK / 4);
            int kc  = (i % (BK / 4)) * 4;
            float4 v = *reinterpret_cast<const float4*>(A + (size_t)(m0 + row) * lda + k0 + kc);
            As[kc + 0][row] = v.x; As[kc + 1][row] = v.y;
            As[kc + 2][row] = v.z; As[kc + 3][row] = v.w;
        }
        // load B tile (transposed), ragged-N guarded
#pragma unroll
        for (int i = tid; i < BN * BK / 4; i += THREADS) {
            int row = i / (BK / 4);
            int kc  = (i % (BK / 4)) * 4;
            float4 v = make_float4(0.f, 0.f, 0.f, 0.f);
            if (n0 + row < N)
                v = *reinterpret_cast<const float4*>(B + (size_t)(n0 + row) * ldb + k0 + kc);
            Bs[kc + 0][row] = v.x; Bs[kc + 1][row] = v.y;
            Bs[kc + 2][row] = v.z; Bs[kc + 3][row] = v.w;
        }
        __syncthreads();

#pragma unroll
        for (int kk = 0; kk < BK; kk++) {
            float ra[TM], rb[TN];
#pragma unroll
            for (int i = 0; i < TM; i++) ra[i] = As[kk][ty * TM + i];
#pragma unroll
            for (int j = 0; j < TN; j++) rb[j] = Bs[kk][tx * TN + j];
#pragma unroll
            for (int i = 0; i < TM; i++)
#pragma unroll
                for (int j = 0; j < TN; j++)
                    acc[i][j] = fmaf(ra[i], rb[j], acc[i][j]);
        }
        __syncthreads();
    }

#pragma unroll
    for (int i = 0; i < TM; i++) {
        int m = m0 + ty * TM + i;
#pragma unroll
        for (int j = 0; j < TN; j++) {
            int n = n0 + tx * TN + j;
            if (n < N) C[(size_t)m * ldc + n] = acc[i][j];
        }
    }
}

// ---------------- depthwise conv (k=2, left pad 1) + SiLU ----------------
__global__ void conv_silu_kernel(const float* __restrict__ cw, const float* __restrict__ cb)
{
    int idx = blockIdx.x * blockDim.x + threadIdx.x;
    if (idx >= NTOK * DI) return;
    int d   = idx & (DI - 1);
    int tok = idx >> 10;
    int l   = tok & (LL - 1);
    float cur  = g_xz[(size_t)tok * (2 * DI) + d];
    float prev = (l > 0) ? g_xz[(size_t)(tok - 1) * (2 * DI) + d] : 0.f;
    float v = fmaf(cw[2 * d], prev, fmaf(cw[2 * d + 1], cur, cb[d]));
    g_xc[idx] = v / (1.f + expf(-v));   // silu
}

// ---------------- precompute A = -exp(A_logs) ----------------
__global__ void precomp_A_kernel(const float* __restrict__ Alogs)
{
    int d = blockIdx.x * blockDim.x + threadIdx.x;
    if (d < DI) g_A[d] = -expf(Alogs[d]);   // D_STATE=1 -> one entry per d
}

// ---------------- elementwise prep: delta, dA, dBu ----------------
__global__ void ssm_prep_kernel(const float* __restrict__ dtb)
{
    int idx = blockIdx.x * blockDim.x + threadIdx.x;
    if (idx >= NTOK * DI) return;
    int d   = idx & (DI - 1);
    int tok = idx >> 10;
    float dtv   = g_dt[idx] + dtb[d];
    float delta = (dtv > 20.f) ? dtv : log1pf(expf(dtv));  // softplus
    float u     = g_xc[idx];
    float Bsv   = g_xdbl[(size_t)tok * RPAD + DTR];        // Bs scalar (n=1)
    float dA    = expf(delta * g_A[d]);                    // precise: error compounds in scan
    g_dt[idx]  = dA;                                       // overwrite in place
    g_dbu[idx] = delta * Bsv * u;
}

// ---------------- sequential scan: h = dA*h + dBu ; y = h*Cs + u*Ds ----------------
__global__ void scan_kernel(const float* __restrict__ Ds)
{
    int t = blockIdx.x * blockDim.x + threadIdx.x;   // 0 .. B*DI-1 (4096)
    int b = t >> 10;
    int d = t & (DI - 1);
    float Dd = Ds[d];
    float h = 0.f;
    size_t tok = (size_t)b * LL;
#pragma unroll 8
    for (int l = 0; l < LL; l++, tok++) {
        size_t off = tok * DI + d;
        float dA  = g_dt[off];
        float dbu = g_dbu[off];
        float u   = g_xc[off];
        float Cs  = g_xdbl[tok * RPAD + DTR + 1];
        h = fmaf(dA, h, dbu);
        g_y[off] = fmaf(h, Cs, u * Dd);
    }
}

// ---------------- LayerNorm over d + SiLU(z) gating ----------------
__global__ void __launch_bounds__(256) ln_gate_kernel(const float* __restrict__ lnw,
                                                      const float* __restrict__ lnb)
{
    int tok = blockIdx.x;
    int tid = threadIdx.x;
    size_t base = (size_t)tok * DI;

    float v[4];
    float s = 0.f, q = 0.f;
#pragma unroll
    for (int i = 0; i < 4; i++) {
        float x = g_y[base + tid + i * 256];
        v[i] = x; s += x; q += x * x;
    }
#pragma unroll
    for (int o = 16; o; o >>= 1) {
        s += __shfl_xor_sync(0xffffffffu, s, o);
        q += __shfl_xor_sync(0xffffffffu, q, o);
    }
    __shared__ float ss[8], sq[8];
    if ((tid & 31) == 0) { ss[tid >> 5] = s; sq[tid >> 5] = q; }
    __syncthreads();
    float S = 0.f, Q = 0.f;
#pragma unroll
    for (int w = 0; w < 8; w++) { S += ss[w]; Q += sq[w]; }

    float mu  = S * (1.f / DI);
    float var = Q * (1.f / DI) - mu * mu;
    float rs  = rsqrtf(var + 1e-5f);
#pragma unroll
    for (int i = 0; i < 4; i++) {
        int d = tid + i * 256;
        float z  = g_xz[(size_t)tok * (2 * DI) + DI + d];
        float gt = z / (1.f + expf(-z));   // silu(z)
        g_yln[base + d] = fmaf((v[i] - mu) * rs, lnw[d], lnb[d]) * gt;
    }
}

// ---------------- launch ----------------
extern "C" void kernel_launch(void* const* d_in, const int* in_sizes, int n_in,
                              void* d_out, int out_size)
{
    const float* x      = (const float*)d_in[0];
    const float* w_in   = (const float*)d_in[1];
    const float* conv_w = (const float*)d_in[2];
    const float* conv_b = (const float*)d_in[3];
    const float* xproj  = (const float*)d_in[4];
    const float* dtw    = (const float*)d_in[5];
    const float* dtb    = (const float*)d_in[6];
    const float* Alogs  = (const float*)d_in[7];
    const float* Ds     = (const float*)d_in[8];
    const float* lnw    = (const float*)d_in[9];
    const float* lnb    = (const float*)d_in[10];
    const float* wout   = (const float*)d_in[11];
    float* out = (float*)d_out;

    float *xz, *xc, *xdbl, *dtf, *yln;
    cudaGetSymbolAddress((void**)&xz,   g_xz);
    cudaGetSymbolAddress((void**)&xc,   g_xc);
    cudaGetSymbolAddress((void**)&xdbl, g_xdbl);
    cudaGetSymbolAddress((void**)&dtf,  g_dt);
    cudaGetSymbolAddress((void**)&yln,  g_yln);

    const int EW_BLOCKS = (NTOK * DI + 255) / 256;

    // 1) xz = x @ w_in^T   (M=16384, N=2048, K=1024)
    gemm_tn<128,128,16,8,8><<<dim3(2048/128, NTOK/128), 256>>>(x, DM, w_in, DM, xz, 2*DI, 2*DI, DM);

    // 2) depthwise conv + silu -> g_xc
    conv_silu_kernel<<<EW_BLOCKS, 256>>>(conv_w, conv_b);

    // 3) x_dbl = xc @ xproj^T   (N=66 ragged, padded tile 80, ldc=68)
    gemm_tn<128,80,16,8,5><<<dim3(1, NTOK/128), 256>>>(xc, DI, xproj, DI, xdbl, RPAD, RTOT, DI);

    // 4) dt = x_dbl[:, :64] @ dtw^T   (M=16384, N=1024, K=64, lda=68)
    gemm_tn<128,128,16,8,8><<<dim3(DI/128, NTOK/128), 256>>>(xdbl, RPAD, dtw, DTR, dtf, DI, DI, DTR);

    // 5) A = -exp(A_logs)
    precomp_A_kernel<<<4, 256>>>(Alogs);

    // 6) delta/dA/dBu elementwise
    ssm_prep_kernel<<<EW_BLOCKS, 256>>>(dtb);

    // 7) sequential scan per (b, d)
    scan_kernel<<<(BB * DI) / 128, 128>>>(Ds);

    // 8) LayerNorm + silu(z) gate
    ln_gate_kernel<<<NTOK, 256>>>(lnw, lnb);

    // 9) out = yln @ w_out^T   (M=16384, N=1024, K=1024)
    gemm_tn<128,128,16,8,8><<<dim3(DI/128, NTOK/128), 256>>>(yln, DI, wout, DM, out, DM, DM, DI);
}

// round 2
// speedup vs baseline: 1.7640x; 1.7640x over previous
#include <cuda_runtime.h>
#include <math.h>
#include <stdint.h>

#define BB   4
#define LL   4096
#define DM   1024
#define DI   1024
#define DTR  64
#define RTOT 66          // DT_RANK + 2*D_STATE
#define RPAD 68          // padded row stride for x_dbl
#define NTOK (BB*LL)     // 16384
#define CH   512         // scan chunk length
#define NCH  (LL/CH)     // 8 chunks per sequence

// ---------------- scratch (device globals: allocation-free) ----------------
__device__ __align__(16) float g_xz  [(size_t)NTOK * 2 * DI]; // [tok, 2048]  xc|z pre-conv
__device__ __align__(16) float g_xc  [(size_t)NTOK * DI];     // conv+silu activations
__device__ __align__(16) float g_xdbl[(size_t)NTOK * RPAD];   // [tok, 68]: dts(64), Bs, Cs
__device__ __align__(16) float g_dt  [(size_t)NTOK * DI];     // dA after fused epilogue
__device__ __align__(16) float g_dbu [(size_t)NTOK * DI];     // delta*Bs*u
__device__ __align__(16) float g_y   [(size_t)NTOK * DI];     // scan output (pre-LN)
__device__ __align__(16) float g_yln [(size_t)NTOK * DI];     // post-LN, gated
__device__ __align__(16) float g_A   [DI];                    // -exp(A_logs)
__device__ __align__(16) float g_Ac  [BB * NCH * DI];         // per-chunk prod(dA)
__device__ __align__(16) float g_Bc  [BB * NCH * DI];         // per-chunk local h
__device__ __align__(16) float g_h0  [BB * NCH * DI];         // entering state per chunk

// ============ pipelined fp32 GEMM: C[M,N] = A[M,K] * B[N,K]^T ============
// Full tiles in M and N (no guards). Double-buffered smem + register staging.
// Smem rows padded to +4 so per-thread 8-float chunks are 16B-aligned -> LDS.128.
// FUSE: apply the SSM prep (softplus -> dA, dBu) on the accumulators.
template<int BM, int BN, int BK, int TM, int TN, bool FUSE>
__global__ void __launch_bounds__((BM/TM)*(BN/TN))
gemm_pipe(const float* __restrict__ A, int lda,
          const float* __restrict__ B, int ldb,
          float* __restrict__ C, int ldc, int K,
          const float* __restrict__ dtb, float* __restrict__ dbu_out)
{
    constexpr int THREADS = (BM/TM) * (BN/TN);
    constexpr int KV = BK / 4;                  // float4 per k-row
    constexpr int NA = (BM * KV) / THREADS;     // staged float4 (A) per thread
    constexpr int NB = (BN * KV) / THREADS;
    static_assert((BM * KV) % THREADS == 0 && (BN * KV) % THREADS == 0, "tile");

    __shared__ float As[2][BK][BM + 4];
    __shared__ float Bs[2][BK][BN + 4];

    const int tid = threadIdx.x;
    const int m0 = blockIdx.y * BM;
    const int n0 = blockIdx.x * BN;
    const int tx = tid % (BN / TN);
    const int ty = tid / (BN / TN);

    float acc[TM][TN];
#pragma unroll
    for (int i = 0; i < TM; i++)
#pragma unroll
        for (int j = 0; j < TN; j++) acc[i][j] = 0.f;

    float4 stA[NA], stB[NB];

    // ---- prologue: load tile 0 ----
#pragma unroll
    for (int t = 0; t < NA; t++) {
        int i = tid + t * THREADS;
        int row = i / KV, kc = (i % KV) * 4;
        stA[t] = *reinterpret_cast<const float4*>(A + (size_t)(m0 + row) * lda + kc);
    }
#pragma unroll
    for (int t = 0; t < NB; t++) {
        int i = tid + t * THREADS;
        int row = i / KV, kc = (i % KV) * 4;
        stB[t] = *reinterpret_cast<const float4*>(B + (size_t)(n0 + row) * ldb + kc);
    }
#pragma unroll
    for (int t = 0; t < NA; t++) {
        int i = tid + t * THREADS;
        int row = i / KV, kc = (i % KV) * 4;
        As[0][kc+0][row] = stA[t].x; As[0][kc+1][row] = stA[t].y;
        As[0][kc+2][row] = stA[t].z; As[0][kc+3][row] = stA[t].w;
    }
#pragma unroll
    for (int t = 0; t < NB; t++) {
        int i = tid + t * THREADS;
        int row = i / KV, kc = (i % KV) * 4;
        Bs[0][kc+0][row] = stB[t].x; Bs[0][kc+1][row] = stB[t].y;
        Bs[0][kc+2][row] = stB[t].z; Bs[0][kc+3][row] = stB[t].w;
    }
    __syncthreads();

    const int nk = K / BK;
    for (int kt = 0; kt < nk; kt++) {
        const int cur = kt & 1, nxt = cur ^ 1;
        if (kt + 1 < nk) {
            const int k0 = (kt + 1) * BK;
#pragma unroll
            for (int t = 0; t < NA; t++) {
                int i = tid + t * THREADS;
                int row = i / KV, kc = (i % KV) * 4;
                stA[t] = *reinterpret_cast<const float4*>(A + (size_t)(m0 + row) * lda + k0 + kc);
            }
#pragma unroll
            for (int t = 0; t < NB; t++) {
                int i = tid + t * THREADS;
                int row = i / KV, kc = (i % KV) * 4;
                stB[t] = *reinterpret_cast<const float4*>(B + (size_t)(n0 + row) * ldb + k0 + kc);
            }
        }

#pragma unroll
        for (int kk = 0; kk < BK; kk++) {
            float ra[TM], rb[TN];
            const float4* pa = reinterpret_cast<const float4*>(&As[cur][kk][ty * TM]);
            const float4* pb = reinterpret_cast<const float4*>(&Bs[cur][kk][tx * TN]);
#pragma unroll
            for (int v = 0; v < TM / 4; v++) {
                float4 q = pa[v];
                ra[v*4+0] = q.x; ra[v*4+1] = q.y; ra[v*4+2] = q.z; ra[v*4+3] = q.w;
            }
#pragma unroll
            for (int v = 0; v < TN / 4; v++) {
                float4 q = pb[v];
                rb[v*4+0] = q.x; rb[v*4+1] = q.y; rb[v*4+2] = q.z; rb[v*4+3] = q.w;
            }
#pragma unroll
            for (int i = 0; i < TM; i++)
#pragma unroll
                for (int j = 0; j < TN; j++)
                    acc[i][j] = fmaf(ra[i], rb[j], acc[i][j]);
        }

        if (kt + 1 < nk) {
#pragma unroll
            for (int t = 0; t < NA; t++) {
                int i = tid + t * THREADS;
                int row = i / KV, kc = (i % KV) * 4;
                As[nxt][kc+0][row] = stA[t].x; As[nxt][kc+1][row] = stA[t].y;
                As[nxt][kc+2][row] = stA[t].z; As[nxt][kc+3][row] = stA[t].w;
            }
#pragma unroll
            for (int t = 0; t < NB; t++) {
                int i = tid + t * THREADS;
                int row = i / KV, kc = (i % KV) * 4;
                Bs[nxt][kc+0][row] = stB[t].x; Bs[nxt][kc+1][row] = stB[t].y;
                Bs[nxt][kc+2][row] = stB[t].z; Bs[nxt][kc+3][row] = stB[t].w;
            }
        }
        __syncthreads();
    }

    // ---- epilogue ----
    if constexpr (FUSE) {
#pragma unroll
        for (int i = 0; i < TM; i++) {
            int m = m0 + ty * TM + i;
            float Bsv = g_xdbl[(size_t)m * RPAD + DTR];
#pragma unroll
            for (int j = 0; j < TN; j++) {
                int n = n0 + tx * TN + j;
                float dtv   = acc[i][j] + dtb[n];
                float delta = (dtv > 20.f) ? dtv : log1pf(expf(dtv));
                float dA    = expf(delta * g_A[n]);
                float u     = g_xc[(size_t)m * DI + n];
                C[(size_t)m * ldc + n]       = dA;
                dbu_out[(size_t)m * ldc + n] = delta * Bsv * u;
            }
        }
    } else {
#pragma unroll
        for (int i = 0; i < TM; i++) {
            int m = m0 + ty * TM + i;
#pragma unroll
            for (int j = 0; j < TN; j++)
                C[(size_t)m * ldc + n0 + tx * TN + j] = acc[i][j];
        }
    }
}

// ============ simple GEMM (ragged N) for the tiny x_dbl projection ============
template<int BM, int BN, int BK, int TM, int TN>
__global__ void __launch_bounds__((BM/TM)*(BN/TN))
gemm_tn(const float* __restrict__ A, int lda,
        const float* __restrict__ B, int ldb,
        float* __restrict__ C, int ldc,
        int N, int K)
{
    constexpr int THREADS = (BM/TM) * (BN/TN);
    __shared__ float As[BK][BM + 4];
    __shared__ float Bs[BK][BN + 4];

    const int tid = threadIdx.x;
    const int m0  = blockIdx.y * BM;
    const int n0  = blockIdx.x * BN;
    const int tx  = tid % (BN / TN);
    const int ty  = tid / (BN / TN);

    float acc[TM][TN];
#pragma unroll
    for (int i = 0; i < TM; i++)
#pragma unroll
        for (int j = 0; j < TN; j++) acc[i][j] = 0.f;

    for (int k0 = 0; k0 < K; k0 += BK) {
        for (int i = tid; i < BM * BK / 4; i += THREADS) {
            int row = i / (BK / 4);
            int kc  = (i % (BK / 4)) * 4;
            float4 v = *reinterpret_cast<const float4*>(A + (size_t)(m0 + row) * lda + k0 + kc);
            As[kc + 0][row] = v.x; As[kc + 1][row] = v.y;
            As[kc + 2][row] = v.z; As[kc + 3][row] = v.w;
        }
        for (int i = tid; i < BN * BK / 4; i += THREADS) {
            int row = i / (BK / 4);
            int kc  = (i % (BK / 4)) * 4;
            float4 v = make_float4(0.f, 0.f, 0.f, 0.f);
            if (n0 + row < N)
                v = *reinterpret_cast<const float4*>(B + (size_t)(n0 + row) * ldb + k0 + kc);
            Bs[kc + 0][row] = v.x; Bs[kc + 1][row] = v.y;
            Bs[kc + 2][row] = v.z; Bs[kc + 3][row] = v.w;
        }
        __syncthreads();

#pragma unroll
        for (int kk = 0; kk < BK; kk++) {
            float ra[TM], rb[TN];
#pragma unroll
            for (int i = 0; i < TM; i++) ra[i] = As[kk][ty * TM + i];
#pragma unroll
            for (int j = 0; j < TN; j++) rb[j] = Bs[kk][tx * TN + j];
#pragma unroll
            for (int i = 0; i < TM; i++)
#pragma unroll
                for (int j = 0; j < TN; j++)
                    acc[i][j] = fmaf(ra[i], rb[j], acc[i][j]);
        }
        __syncthreads();
    }

#pragma unroll
    for (int i = 0; i < TM; i++) {
        int m = m0 + ty * TM + i;
#pragma unroll
        for (int j = 0; j < TN; j++) {
            int n = n0 + tx * TN + j;
            if (n < N) C[(size_t)m * ldc + n] = acc[i][j];
        }
    }
}

// ---------------- depthwise conv (k=2, left pad 1) + SiLU ----------------
__global__ void conv_silu_kernel(const float* __restrict__ cw, const float* __restrict__ cb)
{
    int idx = blockIdx.x * blockDim.x + threadIdx.x;
    if (idx >= NTOK * DI) return;
    int d   = idx & (DI - 1);
    int tok = idx >> 10;
    int l   = tok & (LL - 1);
    float cur  = g_xz[(size_t)tok * (2 * DI) + d];
    float prev = (l > 0) ? g_xz[(size_t)(tok - 1) * (2 * DI) + d] : 0.f;
    float v = fmaf(cw[2 * d], prev, fmaf(cw[2 * d + 1], cur, cb[d]));
    g_xc[idx] = v / (1.f + expf(-v));   // silu
}

// ---------------- precompute A = -exp(A_logs) ----------------
__global__ void precomp_A_kernel(const float* __restrict__ Alogs)
{
    int d = blockIdx.x * blockDim.x + threadIdx.x;
    if (d < DI) g_A[d] = -expf(Alogs[d]);
}

// ---------------- chunked scan, pass 1: per-chunk (prod dA, local h) ----------------
__global__ void scan_pass1_kernel()
{
    int t = blockIdx.x * blockDim.x + threadIdx.x;   // 0 .. BB*NCH*DI-1
    if (t >= BB * NCH * DI) return;
    int d = t & (DI - 1);
    int c = (t >> 10) & (NCH - 1);
    int b = t >> 13;                                  // /(DI*NCH)
    size_t base = ((size_t)b * LL + (size_t)c * CH) * DI + d;
    float aprod = 1.f, h = 0.f;
#pragma unroll 4
    for (int l = 0; l < CH; l++) {
        float a  = g_dt [base + (size_t)l * DI];
        float bu = g_dbu[base + (size_t)l * DI];
        h = fmaf(a, h, bu);
        aprod *= a;
    }
    g_Ac[t] = aprod;
    g_Bc[t] = h;
}

// ---------------- pass 2: chain chunk states (NCH steps per (b,d)) ----------------
__global__ void scan_pass2_kernel()
{
    int t = blockIdx.x * blockDim.x + threadIdx.x;   // 0 .. BB*DI-1
    if (t >= BB * DI) return;
    int d = t & (DI - 1);
    int b = t >> 10;
    float h = 0.f;
#pragma unroll
    for (int c = 0; c < NCH; c++) {
        int idx = ((b * NCH) + c) * DI + d;
        g_h0[idx] = h;
        h = fmaf(g_Ac[idx], h, g_Bc[idx]);
    }
}

// ---------------- pass 3: recompute with correct h0, emit y ----------------
__global__ void scan_pass3_kernel(const float* __restrict__ Ds)
{
    int t = blockIdx.x * blockDim.x + threadIdx.x;
    if (t >= BB * NCH * DI) return;
    int d = t & (DI - 1);
    int c = (t >> 10) & (NCH - 1);
    int b = t >> 13;
    float Dd = Ds[d];
    float h = g_h0[t];
    size_t tok0 = (size_t)b * LL + (size_t)c * CH;
    size_t base = tok0 * DI + d;
#pragma unroll 4
    for (int l = 0; l < CH; l++) {
        float a  = g_dt [base + (size_t)l * DI];
        float bu = g_dbu[base + (size_t)l * DI];
        float u  = g_xc [base + (size_t)l * DI];
        float Cs = g_xdbl[(tok0 + l) * RPAD + DTR + 1];
        h = fmaf(a, h, bu);
        g_y[base + (size_t)l * DI] = fmaf(h, Cs, u * Dd);
    }
}

// ---------------- LayerNorm over d + SiLU(z) gating ----------------
__global__ void __launch_bounds__(256) ln_gate_kernel(const float* __restrict__ lnw,
                                                      const float* __restrict__ lnb)
{
    int tok = blockIdx.x;
    int tid = threadIdx.x;
    size_t base = (size_t)tok * DI;

    float v[4];
    float s = 0.f, q = 0.f;
#pragma unroll
    for (int i = 0; i < 4; i++) {
        float x = g_y[base + tid + i * 256];
        v[i] = x; s += x; q += x * x;
    }
#pragma unroll
    for (int o = 16; o; o >>= 1) {
        s += __shfl_xor_sync(0xffffffffu, s, o);
        q += __shfl_xor_sync(0xffffffffu, q, o);
    }
    __shared__ float ss[8], sq[8];
    if ((tid & 31) == 0) { ss[tid >> 5] = s; sq[tid >> 5] = q; }
    __syncthreads();
    float S = 0.f, Q = 0.f;
#pragma unroll
    for (int w = 0; w < 8; w++) { S += ss[w]; Q += sq[w]; }

    float mu  = S * (1.f / DI);
    float var = Q * (1.f / DI) - mu * mu;
    float rs  = rsqrtf(var + 1e-5f);
#pragma unroll
    for (int i = 0; i < 4; i++) {
        int d = tid + i * 256;
        float z  = g_xz[(size_t)tok * (2 * DI) + DI + d];
        float gt = z / (1.f + expf(-z));
        g_yln[base + d] = fmaf((v[i] - mu) * rs, lnw[d], lnb[d]) * gt;
    }
}

// ---------------- launch ----------------
extern "C" void kernel_launch(void* const* d_in, const int* in_sizes, int n_in,
                              void* d_out, int out_size)
{
    const float* x      = (const float*)d_in[0];
    const float* w_in   = (const float*)d_in[1];
    const float* conv_w = (const float*)d_in[2];
    const float* conv_b = (const float*)d_in[3];
    const float* xproj  = (const float*)d_in[4];
    const float* dtw    = (const float*)d_in[5];
    const float* dtb    = (const float*)d_in[6];
    const float* Alogs  = (const float*)d_in[7];
    const float* Ds     = (const float*)d_in[8];
    const float* lnw    = (const float*)d_in[9];
    const float* lnb    = (const float*)d_in[10];
    const float* wout   = (const float*)d_in[11];
    float* out = (float*)d_out;

    float *xz, *xc, *xdbl, *dtf, *dbu, *yln;
    cudaGetSymbolAddress((void**)&xz,   g_xz);
    cudaGetSymbolAddress((void**)&xc,   g_xc);
    cudaGetSymbolAddress((void**)&xdbl, g_xdbl);
    cudaGetSymbolAddress((void**)&dtf,  g_dt);
    cudaGetSymbolAddress((void**)&dbu,  g_dbu);
    cudaGetSymbolAddress((void**)&yln,  g_yln);

    const int EW_BLOCKS = (NTOK * DI + 255) / 256;

    // 1) xz = x @ w_in^T   (M=16384, N=2048, K=1024)
    gemm_pipe<128,128,16,8,8,false><<<dim3(2048/128, NTOK/128), 256>>>(
        x, DM, w_in, DM, xz, 2*DI, DM, nullptr, nullptr);

    // 2) depthwise conv + silu -> g_xc
    conv_silu_kernel<<<EW_BLOCKS, 256>>>(conv_w, conv_b);

    // 3) x_dbl = xc @ xproj^T   (N=66 ragged, ldc=68)
    gemm_tn<128,80,16,8,5><<<dim3(1, NTOK/128), 256>>>(xc, DI, xproj, DI, xdbl, RPAD, RTOT, DI);

    // 4) A = -exp(A_logs)  (needed by the fused epilogue of step 5)
    precomp_A_kernel<<<4, 256>>>(Alogs);

    // 5) dt GEMM + fused SSM prep:  g_dt <- dA, g_dbu <- delta*Bs*u
    gemm_pipe<128,128,16,8,8,true><<<dim3(DI/128, NTOK/128), 256>>>(
        xdbl, RPAD, dtw, DTR, dtf, DI, DTR, dtb, dbu);

    // 6) chunked scan
    scan_pass1_kernel<<<(BB * NCH * DI + 255) / 256, 256>>>();
    scan_pass2_kernel<<<(BB * DI + 255) / 256, 256>>>();
    scan_pass3_kernel<<<(BB * NCH * DI + 255) / 256, 256>>>(Ds);

    // 7) LayerNorm + silu(z) gate
    ln_gate_kernel<<<NTOK, 256>>>(lnw, lnb);

    // 8) out = yln @ w_out^T   (M=16384, N=1024, K=1024)
    gemm_pipe<128,128,16,8,8,false><<<dim3(DI/128, NTOK/128), 256>>>(
        yln, DI, wout, DM, out, DM, DI, nullptr, nullptr);
}

// round 4
// speedup vs baseline: 2.6846x; 1.5218x over previous
#include <cuda_runtime.h>
#include <cuda_bf16.h>
#include <math.h>
#include <stdint.h>

#define BB   4
#define LL   4096
#define DM   1024
#define DI   1024
#define DTR  64
#define RTOT 66
#define RPAD 68
#define NTOK (BB*LL)     // 16384
#define CH   512
#define NCH  (LL/CH)

// ---------------- scratch ----------------
__device__ __align__(16) float g_xz  [(size_t)NTOK * 2 * DI];
__device__ __align__(16) float g_xc  [(size_t)NTOK * DI];
__device__ __align__(16) float g_xdbl[(size_t)NTOK * RPAD];
__device__ __align__(16) float g_dt  [(size_t)NTOK * DI];
__device__ __align__(16) float g_dbu [(size_t)NTOK * DI];
__device__ __align__(16) float g_y   [(size_t)NTOK * DI];
__device__ __align__(16) float g_A   [DI];
__device__ __align__(16) float g_Ac  [BB * NCH * DI];
__device__ __align__(16) float g_Bc  [BB * NCH * DI];
__device__ __align__(16) float g_h0  [BB * NCH * DI];
// bf16 split buffers
__device__ __align__(16) __nv_bfloat16 g_xhi [(size_t)NTOK * DM];
__device__ __align__(16) __nv_bfloat16 g_xlo [(size_t)NTOK * DM];
__device__ __align__(16) __nv_bfloat16 g_w1hi[(size_t)2 * DI * DM];
__device__ __align__(16) __nv_bfloat16 g_w1lo[(size_t)2 * DI * DM];
__device__ __align__(16) __nv_bfloat16 g_yhi [(size_t)NTOK * DI];
__device__ __align__(16) __nv_bfloat16 g_ylo [(size_t)NTOK * DI];
__device__ __align__(16) __nv_bfloat16 g_wohi[(size_t)DM * DI];
__device__ __align__(16) __nv_bfloat16 g_wolo[(size_t)DM * DI];

// ================= warp-mma helpers =================
__device__ __forceinline__ uint32_t smem_u32(const void* p) {
    uint32_t a;
    asm("{ .reg .u64 t; cvta.to.shared.u64 t, %1; cvt.u32.u64 %0, t; }" : "=r"(a) : "l"(p));
    return a;
}

__device__ __forceinline__ void ldsm4(uint32_t* r, uint32_t addr) {
    asm volatile("ldmatrix.sync.aligned.m8n8.x4.shared.b16 {%0,%1,%2,%3}, [%4];"
                 : "=r"(r[0]), "=r"(r[1]), "=r"(r[2]), "=r"(r[3]) : "r"(addr));
}

__device__ __forceinline__ void mma16816(float* d, const uint32_t* a, uint32_t b0, uint32_t b1) {
    asm volatile("mma.sync.aligned.m16n8k16.row.col.f32.bf16.bf16.f32 "
                 "{%0,%1,%2,%3}, {%4,%5,%6,%7}, {%8,%9}, {%0,%1,%2,%3};"
                 : "+f"(d[0]), "+f"(d[1]), "+f"(d[2]), "+f"(d[3])
                 : "r"(a[0]), "r"(a[1]), "r"(a[2]), "r"(a[3]), "r"(b0), "r"(b1));
}

// ============ tensor-core (HMMA) split GEMM ============
// C[M,N] = A[M,K] @ B[N,K]^T with A,B fp32 pre-split into bf16 hi/lo.
// 3-term accumulation: Ahi*Bhi + Ahi*Blo + Alo*Bhi in fp32 accumulators.
// grid (N/128, M/128), 256 threads (8 warps, 2x4 -> 64x32 warp tiles), BK=32.
#define ROWB   80                   // smem row stride bytes (conflict-free LDSM)
#define ARRB   (128 * ROWB)         // 10240 bytes per operand array
#define STAGEB (4 * ARRB)           // Ahi,Alo,Bhi,Blo
__global__ void __launch_bounds__(256)
mma_gemm(const __nv_bfloat16* __restrict__ Ahi, const __nv_bfloat16* __restrict__ Alo,
         const __nv_bfloat16* __restrict__ Bhi, const __nv_bfloat16* __restrict__ Blo,
         float* __restrict__ C, int ldc, int K)
{
    extern __shared__ __align__(16) char dynsm[];
    const uint32_t sbase = smem_u32(dynsm);

    const int tid  = threadIdx.x;
    const int lane = tid & 31;
    const int wid  = tid >> 5;
    const int wm   = wid & 1;       // 2 warps in M
    const int wn   = wid >> 1;      // 4 warps in N
    const int m0   = blockIdx.y * 128;
    const int n0   = blockIdx.x * 128;

    const __nv_bfloat16* gptr[4] = {Ahi, Alo, Bhi, Blo};

    float acc[4][4][4];
#pragma unroll
    for (int i = 0; i < 4; i++)
#pragma unroll
        for (int j = 0; j < 4; j++)
#pragma unroll
            for (int v = 0; v < 4; v++) acc[i][j][v] = 0.f;

    // ldmatrix lane-address components (element offsets within tile)
    const int a_row = lane & 15;            // + matom*16
    const int a_kc  = (lane >> 4) * 8;      // + kstep*16
    const int b_row = (lane & 7) + ((lane >> 3) & 1) * 8;  // + pair*16
    const int b_kc  = (lane >> 4) * 8;

    uint4 st[4][2];

    // ---- prologue: load chunk 0 ----
#pragma unroll
    for (int arr = 0; arr < 4; arr++) {
        const int rbase = (arr < 2) ? m0 : n0;
#pragma unroll
        for (int t = 0; t < 2; t++) {
            int i = tid + t * 256, row = i >> 2, c = i & 3;
            st[arr][t] = *(const uint4*)(gptr[arr] + (size_t)(rbase + row) * K + c * 8);
        }
    }
#pragma unroll
    for (int arr = 0; arr < 4; arr++)
#pragma unroll
        for (int t = 0; t < 2; t++) {
            int i = tid + t * 256, row = i >> 2, c = i & 3;
            *(uint4*)(dynsm + arr * ARRB + row * ROWB + c * 16) = st[arr][t];
        }
    __syncthreads();

    const int NK = K / 32;
    for (int kt = 0; kt < NK; kt++) {
        const int cur = kt & 1, nxt = cur ^ 1;
        if (kt + 1 < NK) {
            const int koff = (kt + 1) * 32;
#pragma unroll
            for (int arr = 0; arr < 4; arr++) {
                const int rbase = (arr < 2) ? m0 : n0;
#pragma unroll
                for (int t = 0; t < 2; t++) {
                    int i = tid + t * 256, row = i >> 2, c = i & 3;
                    st[arr][t] = *(const uint4*)(gptr[arr] + (size_t)(rbase + row) * K + koff + c * 8);
                }
            }
        }

        const uint32_t stg = sbase + cur * STAGEB;
#pragma unroll
        for (int ks = 0; ks < 2; ks++) {
            // B fragments: 2 pairs (n 0-15, 16-31 within warp tile) x hi/lo
            uint32_t bh[2][4], bl[2][4];
#pragma unroll
            for (int p = 0; p < 2; p++) {
                uint32_t boff = (uint32_t)(wn * 32 + p * 16 + b_row) * ROWB + (ks * 16 + b_kc) * 2;
                ldsm4(bh[p], stg + 2 * ARRB + boff);
                ldsm4(bl[p], stg + 3 * ARRB + boff);
            }
#pragma unroll
            for (int m = 0; m < 4; m++) {
                uint32_t ah[4], al[4];
                uint32_t aoff = (uint32_t)(wm * 64 + m * 16 + a_row) * ROWB + (ks * 16 + a_kc) * 2;
                ldsm4(ah, stg + 0 * ARRB + aoff);
                ldsm4(al, stg + 1 * ARRB + aoff);
#pragma unroll
                for (int n = 0; n < 4; n++) {
                    const int p = n >> 1, q = n & 1;
                    mma16816(acc[m][n], ah, bh[p][q], bh[p][q + 2]);
                    mma16816(acc[m][n], ah, bl[p][q], bl[p][q + 2]);
                    mma16816(acc[m][n], al, bh[p][q], bh[p][q + 2]);
                }
            }
        }

        if (kt + 1 < NK) {
            char* dst = dynsm + nxt * STAGEB;
#pragma unroll
            for (int arr = 0; arr < 4; arr++)
#pragma unroll
                for (int t = 0; t < 2; t++) {
                    int i = tid + t * 256, row = i >> 2, c = i & 3;
                    *(uint4*)(dst + arr * ARRB + row * ROWB + c * 16) = st[arr][t];
                }
        }
        __syncthreads();
    }

    // ---- epilogue ----
#pragma unroll
    for (int m = 0; m < 4; m++) {
        const int row = m0 + wm * 64 + m * 16 + (lane >> 2);
#pragma unroll
        for (int n = 0; n < 4; n++) {
            const int col = n0 + wn * 32 + n * 8 + (lane & 3) * 2;
            *(float2*)(C + (size_t)row * ldc + col)       = make_float2(acc[m][n][0], acc[m][n][1]);
            *(float2*)(C + (size_t)(row + 8) * ldc + col) = make_float2(acc[m][n][2], acc[m][n][3]);
        }
    }
}

// ================= fp32 split kernel =================
__global__ void split_kernel(const float* __restrict__ src,
                             __nv_bfloat16* __restrict__ hi,
                             __nv_bfloat16* __restrict__ lo, int n4)
{
    int i = blockIdx.x * blockDim.x + threadIdx.x;
    if (i >= n4) return;
    float4 v = ((const float4*)src)[i];
    __nv_bfloat16 h0 = __float2bfloat16(v.x), h1 = __float2bfloat16(v.y);
    __nv_bfloat16 h2 = __float2bfloat16(v.z), h3 = __float2bfloat16(v.w);
    __nv_bfloat162* H = (__nv_bfloat162*)hi;
    __nv_bfloat162* L = (__nv_bfloat162*)lo;
    H[i*2+0] = __nv_bfloat162(h0, h1);
    H[i*2+1] = __nv_bfloat162(h2, h3);
    L[i*2+0] = __nv_bfloat162(__float2bfloat16(v.x - __bfloat162float(h0)),
                              __float2bfloat16(v.y - __bfloat162float(h1)));
    L[i*2+1] = __nv_bfloat162(__float2bfloat16(v.z - __bfloat162float(h2)),
                              __float2bfloat16(v.w - __bfloat162float(h3)));
}

// ============ pipelined fp32 GEMM (dt GEMM, fused SSM prep) ============
template<int BM, int BN, int BK, int TM, int TN, bool FUSE>
__global__ void __launch_bounds__((BM/TM)*(BN/TN))
gemm_pipe(const float* __restrict__ A, int lda,
          const float* __restrict__ B, int ldb,
          float* __restrict__ C, int ldc, int K,
          const float* __restrict__ dtb, float* __restrict__ dbu_out)
{
    constexpr int THREADS = (BM/TM) * (BN/TN);
    constexpr int KV = BK / 4;
    constexpr int NA = (BM * KV) / THREADS;
    constexpr int NB = (BN * KV) / THREADS;

    __shared__ float As[2][BK][BM + 4];
    __shared__ float Bs[2][BK][BN + 4];

    const int tid = threadIdx.x;
    const int m0 = blockIdx.y * BM;
    const int n0 = blockIdx.x * BN;
    const int tx = tid % (BN / TN);
    const int ty = tid / (BN / TN);

    float acc[TM][TN];
#pragma unroll
    for (int i = 0; i < TM; i++)
#pragma unroll
        for (int j = 0; j < TN; j++) acc[i][j] = 0.f;

    float4 stA[NA], stB[NB];
#pragma unroll
    for (int t = 0; t < NA; t++) {
        int i = tid + t * THREADS; int row = i / KV, kc = (i % KV) * 4;
        stA[t] = *reinterpret_cast<const float4*>(A + (size_t)(m0 + row) * lda + kc);
    }
#pragma unroll
    for (int t = 0; t < NB; t++) {
        int i = tid + t * THREADS; int row = i / KV, kc = (i % KV) * 4;
        stB[t] = *reinterpret_cast<const float4*>(B + (size_t)(n0 + row) * ldb + kc);
    }
#pragma unroll
    for (int t = 0; t < NA; t++) {
        int i = tid + t * THREADS; int row = i / KV, kc = (i % KV) * 4;
        As[0][kc+0][row] = stA[t].x; As[0][kc+1][row] = stA[t].y;
        As[0][kc+2][row] = stA[t].z; As[0][kc+3][row] = stA[t].w;
    }
#pragma unroll
    for (int t = 0; t < NB; t++) {
        int i = tid + t * THREADS; int row = i / KV, kc = (i % KV) * 4;
        Bs[0][kc+0][row] = stB[t].x; Bs[0][kc+1][row] = stB[t].y;
        Bs[0][kc+2][row] = stB[t].z; Bs[0][kc+3][row] = stB[t].w;
    }
    __syncthreads();

    const int nk = K / BK;
    for (int kt = 0; kt < nk; kt++) {
        const int cur = kt & 1, nxt = cur ^ 1;
        if (kt + 1 < nk) {
            const int k0 = (kt + 1) * BK;
#pragma unroll
            for (int t = 0; t < NA; t++) {
                int i = tid + t * THREADS; int row = i / KV, kc = (i % KV) * 4;
                stA[t] = *reinterpret_cast<const float4*>(A + (size_t)(m0 + row) * lda + k0 + kc);
            }
#pragma unroll
            for (int t = 0; t < NB; t++) {
                int i = tid + t * THREADS; int row = i / KV, kc = (i % KV) * 4;
                stB[t] = *reinterpret_cast<const float4*>(B + (size_t)(n0 + row) * ldb + k0 + kc);
            }
        }
#pragma unroll
        for (int kk = 0; kk < BK; kk++) {
            float ra[TM], rb[TN];
            const float4* pa = reinterpret_cast<const float4*>(&As[cur][kk][ty * TM]);
            const float4* pb = reinterpret_cast<const float4*>(&Bs[cur][kk][tx * TN]);
#pragma unroll
            for (int v = 0; v < TM / 4; v++) {
                float4 q = pa[v];
                ra[v*4+0]=q.x; ra[v*4+1]=q.y; ra[v*4+2]=q.z; ra[v*4+3]=q.w;
            }
#pragma unroll
            for (int v = 0; v < TN / 4; v++) {
                float4 q = pb[v];
                rb[v*4+0]=q.x; rb[v*4+1]=q.y; rb[v*4+2]=q.z; rb[v*4+3]=q.w;
            }
#pragma unroll
            for (int i = 0; i < TM; i++)
#pragma unroll
                for (int j = 0; j < TN; j++)
                    acc[i][j] = fmaf(ra[i], rb[j], acc[i][j]);
        }
        if (kt + 1 < nk) {
#pragma unroll
            for (int t = 0; t < NA; t++) {
                int i = tid + t * THREADS; int row = i / KV, kc = (i % KV) * 4;
                As[nxt][kc+0][row] = stA[t].x; As[nxt][kc+1][row] = stA[t].y;
                As[nxt][kc+2][row] = stA[t].z; As[nxt][kc+3][row] = stA[t].w;
            }
#pragma unroll
            for (int t = 0; t < NB; t++) {
                int i = tid + t * THREADS; int row = i / KV, kc = (i % KV) * 4;
                Bs[nxt][kc+0][row] = stB[t].x; Bs[nxt][kc+1][row] = stB[t].y;
                Bs[nxt][kc+2][row] = stB[t].z; Bs[nxt][kc+3][row] = stB[t].w;
            }
        }
        __syncthreads();
    }

    if constexpr (FUSE) {
#pragma unroll
        for (int i = 0; i < TM; i++) {
            int m = m0 + ty * TM + i;
            float Bsv = g_xdbl[(size_t)m * RPAD + DTR];
#pragma unroll
            for (int j = 0; j < TN; j++) {
                int n = n0 + tx * TN + j;
                float dtv   = acc[i][j] + dtb[n];
                float delta = (dtv > 20.f) ? dtv : log1pf(expf(dtv));
                float dA    = expf(delta * g_A[n]);
                float u     = g_xc[(size_t)m * DI + n];
                C[(size_t)m * ldc + n]       = dA;
                dbu_out[(size_t)m * ldc + n] = delta * Bsv * u;
            }
        }
    } else {
#pragma unroll
        for (int i = 0; i < TM; i++) {
            int m = m0 + ty * TM + i;
#pragma unroll
            for (int j = 0; j < TN; j++)
                C[(size_t)m * ldc + n0 + tx * TN + j] = acc[i][j];
        }
    }
}

// ============ ragged-N fp32 GEMM (x_dbl projection) ============
template<int BM, int BN, int BK, int TM, int TN>
__global__ void __launch_bounds__((BM/TM)*(BN/TN))
gemm_tn(const float* __restrict__ A, int lda,
        const float* __restrict__ B, int ldb,
        float* __restrict__ C, int ldc,
        int N, int K)
{
    constexpr int THREADS = (BM/TM) * (BN/TN);
    __shared__ float As[BK][BM + 4];
    __shared__ float Bs[BK][BN + 4];

    const int tid = threadIdx.x;
    const int m0 = blockIdx.y * BM;
    const int n0 = blockIdx.x * BN;
    const int tx = tid % (BN / TN);
    const int ty = tid / (BN / TN);

    float acc[TM][TN];
#pragma unroll
    for (int i = 0; i < TM; i++)
#pragma unroll
        for (int j = 0; j < TN; j++) acc[i][j] = 0.f;

    for (int k0 = 0; k0 < K; k0 += BK) {
        for (int i = tid; i < BM * BK / 4; i += THREADS) {
            int row = i / (BK / 4), kc = (i % (BK / 4)) * 4;
            float4 v = *reinterpret_cast<const float4*>(A + (size_t)(m0 + row) * lda + k0 + kc);
            As[kc+0][row] = v.x; As[kc+1][row] = v.y; As[kc+2][row] = v.z; As[kc+3][row] = v.w;
        }
        for (int i = tid; i < BN * BK / 4; i += THREADS) {
            int row = i / (BK / 4), kc = (i % (BK / 4)) * 4;
            float4 v = make_float4(0.f, 0.f, 0.f, 0.f);
            if (n0 + row < N)
                v = *reinterpret_cast<const float4*>(B + (size_t)(n0 + row) * ldb + k0 + kc);
            Bs[kc+0][row] = v.x; Bs[kc+1][row] = v.y; Bs[kc+2][row] = v.z; Bs[kc+3][row] = v.w;
        }
        __syncthreads();
#pragma unroll
        for (int kk = 0; kk < BK; kk++) {
            float ra[TM], rb[TN];
#pragma unroll
            for (int i = 0; i < TM; i++) ra[i] = As[kk][ty * TM + i];
#pragma unroll
            for (int j = 0; j < TN; j++) rb[j] = Bs[kk][tx * TN + j];
#pragma unroll
            for (int i = 0; i < TM; i++)
#pragma unroll
                for (int j = 0; j < TN; j++)
                    acc[i][j] = fmaf(ra[i], rb[j], acc[i][j]);
        }
        __syncthreads();
    }
#pragma unroll
    for (int i = 0; i < TM; i++) {
        int m = m0 + ty * TM + i;
#pragma unroll
        for (int j = 0; j < TN; j++) {
            int n = n0 + tx * TN + j;
            if (n < N) C[(size_t)m * ldc + n] = acc[i][j];
        }
    }
}

// ---------------- depthwise conv (k=2) + SiLU ----------------
__global__ void conv_silu_kernel(const float* __restrict__ cw, const float* __restrict__ cb)
{
    int idx = blockIdx.x * blockDim.x + threadIdx.x;
    if (idx >= NTOK * DI) return;
    int d = idx & (DI - 1);
    int tok = idx >> 10;
    int l = tok & (LL - 1);
    float cur  = g_xz[(size_t)tok * (2 * DI) + d];
    float prev = (l > 0) ? g_xz[(size_t)(tok - 1) * (2 * DI) + d] : 0.f;
    float v = fmaf(cw[2 * d], prev, fmaf(cw[2 * d + 1], cur, cb[d]));
    g_xc[idx] = v / (1.f + expf(-v));
}

__global__ void precomp_A_kernel(const float* __restrict__ Alogs)
{
    int d = blockIdx.x * blockDim.x + threadIdx.x;
    if (d < DI) g_A[d] = -expf(Alogs[d]);
}

// ---------------- chunked scan ----------------
__global__ void scan_pass1_kernel()
{
    int t = blockIdx.x * blockDim.x + threadIdx.x;
    if (t >= BB * NCH * DI) return;
    int d = t & (DI - 1);
    int c = (t >> 10) & (NCH - 1);
    int b = t >> 13;
    size_t base = ((size_t)b * LL + (size_t)c * CH) * DI + d;
    float aprod = 1.f, h = 0.f;
#pragma unroll 4
    for (int l = 0; l < CH; l++) {
        float a  = g_dt [base + (size_t)l * DI];
        float bu = g_dbu[base + (size_t)l * DI];
        h = fmaf(a, h, bu);
        aprod *= a;
    }
    g_Ac[t] = aprod;
    g_Bc[t] = h;
}

__global__ void scan_pass2_kernel()
{
    int t = blockIdx.x * blockDim.x + threadIdx.x;
    if (t >= BB * DI) return;
    int d = t & (DI - 1);
    int b = t >> 10;
    float h = 0.f;
#pragma unroll
    for (int c = 0; c < NCH; c++) {
        int idx = ((b * NCH) + c) * DI + d;
        g_h0[idx] = h;
        h = fmaf(g_Ac[idx], h, g_Bc[idx]);
    }
}

__global__ void scan_pass3_kernel(const float* __restrict__ Ds)
{
    int t = blockIdx.x * blockDim.x + threadIdx.x;
    if (t >= BB * NCH * DI) return;
    int d = t & (DI - 1);
    int c = (t >> 10) & (NCH - 1);
    int b = t >> 13;
    float Dd = Ds[d];
    float h = g_h0[t];
    size_t tok0 = (size_t)b * LL + (size_t)c * CH;
    size_t base = tok0 * DI + d;
#pragma unroll 4
    for (int l = 0; l < CH; l++) {
        float a  = g_dt [base + (size_t)l * DI];
        float bu = g_dbu[base + (size_t)l * DI];
        float u  = g_xc [base + (size_t)l * DI];
        float Cs = g_xdbl[(tok0 + l) * RPAD + DTR + 1];
        h = fmaf(a, h, bu);
        g_y[base + (size_t)l * DI] = fmaf(h, Cs, u * Dd);
    }
}

// ---------------- LayerNorm + SiLU gate, fused bf16 split output ----------------
__global__ void __launch_bounds__(256) ln_gate_kernel(const float* __restrict__ lnw,
                                                      const float* __restrict__ lnb)
{
    int tok = blockIdx.x;
    int tid = threadIdx.x;
    size_t base = (size_t)tok * DI;

    float v[4];
    float s = 0.f, q = 0.f;
#pragma unroll
    for (int i = 0; i < 4; i++) {
        float x = g_y[base + tid + i * 256];
        v[i] = x; s += x; q += x * x;
    }
#pragma unroll
    for (int o = 16; o; o >>= 1) {
        s += __shfl_xor_sync(0xffffffffu, s, o);
        q += __shfl_xor_sync(0xffffffffu, q, o);
    }
    __shared__ float ss[8], sq[8];
    if ((tid & 31) == 0) { ss[tid >> 5] = s; sq[tid >> 5] = q; }
    __syncthreads();
    float S = 0.f, Q = 0.f;
#pragma unroll
    for (int w = 0; w < 8; w++) { S += ss[w]; Q += sq[w]; }

    float mu  = S * (1.f / DI);
    float var = Q * (1.f / DI) - mu * mu;
    float rs  = rsqrtf(var + 1e-5f);
#pragma unroll
    for (int i = 0; i < 4; i++) {
        int d = tid + i * 256;
        float z  = g_xz[(size_t)tok * (2 * DI) + DI + d];
        float gt = z / (1.f + expf(-z));
        float val = fmaf((v[i] - mu) * rs, lnw[d], lnb[d]) * gt;
        __nv_bfloat16 h = __float2bfloat16(val);
        g_yhi[base + d] = h;
        g_ylo[base + d] = __float2bfloat16(val - __bfloat162float(h));
    }
}

// ---------------- launch ----------------
extern "C" void kernel_launch(void* const* d_in, const int* in_sizes, int n_in,
                              void* d_out, int out_size)
{
    const float* x      = (const float*)d_in[0];
    const float* w_in   = (const float*)d_in[1];
    const float* conv_w = (const float*)d_in[2];
    const float* conv_b = (const float*)d_in[3];
    const float* xproj  = (const float*)d_in[4];
    const float* dtw    = (const float*)d_in[5];
    const float* dtb    = (const float*)d_in[6];
    const float* Alogs  = (const float*)d_in[7];
    const float* Ds     = (const float*)d_in[8];
    const float* lnw    = (const float*)d_in[9];
    const float* lnb    = (const float*)d_in[10];
    const float* wout   = (const float*)d_in[11];
    float* out = (float*)d_out;

    float *xz, *xc, *xdbl, *dtf, *dbu;
    __nv_bfloat16 *xhi, *xlo, *w1hi, *w1lo, *yhi, *ylo, *wohi, *wolo;
    cudaGetSymbolAddress((void**)&xz,   g_xz);
    cudaGetSymbolAddress((void**)&xc,   g_xc);
    cudaGetSymbolAddress((void**)&xdbl, g_xdbl);
    cudaGetSymbolAddress((void**)&dtf,  g_dt);
    cudaGetSymbolAddress((void**)&dbu,  g_dbu);
    cudaGetSymbolAddress((void**)&xhi,  g_xhi);
    cudaGetSymbolAddress((void**)&xlo,  g_xlo);
    cudaGetSymbolAddress((void**)&w1hi, g_w1hi);
    cudaGetSymbolAddress((void**)&w1lo, g_w1lo);
    cudaGetSymbolAddress((void**)&yhi,  g_yhi);
    cudaGetSymbolAddress((void**)&ylo,  g_ylo);
    cudaGetSymbolAddress((void**)&wohi, g_wohi);
    cudaGetSymbolAddress((void**)&wolo, g_wolo);

    const int SMEM_MMA = 2 * STAGEB;   // 81920 bytes
    cudaFuncSetAttribute(mma_gemm, cudaFuncAttributeMaxDynamicSharedMemorySize, SMEM_MMA);

    const int EW_BLOCKS = (NTOK * DI + 255) / 256;

    // 0) split fp32 -> bf16 hi/lo
    split_kernel<<<(NTOK * DM / 4 + 255) / 256, 256>>>(x, xhi, xlo, NTOK * DM / 4);
    split_kernel<<<(2 * DI * DM / 4 + 255) / 256, 256>>>(w_in, w1hi, w1lo, 2 * DI * DM / 4);
    split_kernel<<<(DM * DI / 4 + 255) / 256, 256>>>(wout, wohi, wolo, DM * DI / 4);

    // 1) xz = x @ w_in^T  (HMMA, split-accumulate)
    mma_gemm<<<dim3(2 * DI / 128, NTOK / 128), 256, SMEM_MMA>>>(xhi, xlo, w1hi, w1lo, xz, 2 * DI, DM);

    // 2) depthwise conv + silu
    conv_silu_kernel<<<EW_BLOCKS, 256>>>(conv_w, conv_b);

    // 3) x_dbl = xc @ xproj^T
    gemm_tn<128,80,16,8,5><<<dim3(1, NTOK/128), 256>>>(xc, DI, xproj, DI, xdbl, RPAD, RTOT, DI);

    // 4) A = -exp(A_logs)
    precomp_A_kernel<<<4, 256>>>(Alogs);

    // 5) dt GEMM + fused SSM prep
    gemm_pipe<128,128,16,8,8,true><<<dim3(DI/128, NTOK/128), 256>>>(
        xdbl, RPAD, dtw, DTR, dtf, DI, DTR, dtb, dbu);

    // 6) chunked scan
    scan_pass1_kernel<<<(BB * NCH * DI + 255) / 256, 256>>>();
    scan_pass2_kernel<<<(BB * DI + 255) / 256, 256>>>();
    scan_pass3_kernel<<<(BB * NCH * DI + 255) / 256, 256>>>(Ds);

    // 7) LayerNorm + gate, emits bf16 hi/lo
    ln_gate_kernel<<<NTOK, 256>>>(lnw, lnb);

    // 8) out = yln @ w_out^T  (HMMA)
    mma_gemm<<<dim3(DI / 128, NTOK / 128), 256, SMEM_MMA>>>(yhi, ylo, wohi, wolo, out, DM, DI);
}

// round 8
// speedup vs baseline: 2.9115x; 1.0845x over previous
#include <cuda_runtime.h>
#include <cuda_bf16.h>
#include <math.h>
#include <stdint.h>

#define BB   4
#define LL   4096
#define DM   1024
#define DI   1024
#define DTR  64
#define RTOT 66
#define RPAD 68
#define NTOK (BB*LL)     // 16384
#define CH   512
#define NCH  (LL/CH)

// ---------------- scratch ----------------
__device__ __align__(16) float g_xz  [(size_t)NTOK * 2 * DI];
__device__ __align__(16) float g_xc  [(size_t)NTOK * DI];
__device__ __align__(16) float g_xdbl[(size_t)NTOK * RPAD];
__device__ __align__(16) float g_dt  [(size_t)NTOK * DI];
__device__ __align__(16) float g_dbu [(size_t)NTOK * DI];
__device__ __align__(16) float g_y   [(size_t)NTOK * DI];
__device__ __align__(16) float g_A   [DI];
__device__ __align__(16) float g_Ac  [BB * NCH * DI];
__device__ __align__(16) float g_Bc  [BB * NCH * DI];
__device__ __align__(16) float g_h0  [BB * NCH * DI];
// bf16 split buffers
__device__ __align__(16) __nv_bfloat16 g_xhi [(size_t)NTOK * DM];
__device__ __align__(16) __nv_bfloat16 g_xlo [(size_t)NTOK * DM];
__device__ __align__(16) __nv_bfloat16 g_w1hi[(size_t)2 * DI * DM];
__device__ __align__(16) __nv_bfloat16 g_w1lo[(size_t)2 * DI * DM];
__device__ __align__(16) __nv_bfloat16 g_yhi [(size_t)NTOK * DI];
__device__ __align__(16) __nv_bfloat16 g_ylo [(size_t)NTOK * DI];
__device__ __align__(16) __nv_bfloat16 g_wohi[(size_t)DM * DI];
__device__ __align__(16) __nv_bfloat16 g_wolo[(size_t)DM * DI];

// ================= helpers =================
__device__ __forceinline__ uint32_t smem_u32(const void* p) {
    uint32_t a;
    asm("{ .reg .u64 t; cvta.to.shared.u64 t, %1; cvt.u32.u64 %0, t; }" : "=r"(a) : "l"(p));
    return a;
}
__device__ __forceinline__ void ldsm4(uint32_t* r, uint32_t addr) {
    asm volatile("ldmatrix.sync.aligned.m8n8.x4.shared.b16 {%0,%1,%2,%3}, [%4];"
                 : "=r"(r[0]), "=r"(r[1]), "=r"(r[2]), "=r"(r[3]) : "r"(addr));
}
__device__ __forceinline__ void mma16816(float* d, const uint32_t* a, uint32_t b0, uint32_t b1) {
    asm volatile("mma.sync.aligned.m16n8k16.row.col.f32.bf16.bf16.f32 "
                 "{%0,%1,%2,%3}, {%4,%5,%6,%7}, {%8,%9}, {%0,%1,%2,%3};"
                 : "+f"(d[0]), "+f"(d[1]), "+f"(d[2]), "+f"(d[3])
                 : "r"(a[0]), "r"(a[1]), "r"(a[2]), "r"(a[3]), "r"(b0), "r"(b1));
}
#define SWZ(o) ((o) ^ (((o) >> 3) & 0x70))
#define CP16(dst, src) asm volatile("cp.async.cg.shared.global [%0], [%1], 16;" :: "r"(dst), "l"(src))
#define CP_COMMIT()    asm volatile("cp.async.commit_group;" ::: "memory")
#define CP_WAIT1()     asm volatile("cp.async.wait_group 1;" ::: "memory")

// ============ HMMA split GEMM v2: cp.async 3-stage, 64x64 warp tiles ============
// C[M,N] = A[M,K] @ B[N,K]^T, fp32 pre-split into bf16 hi/lo, 3-term accumulate.
// grid (N/128, M/128), 128 threads (4 warps 2x2). BK=32. Stage = 32KB (A:16K, B:16K).
// Smem row: 128B = 64B hi | 64B lo of one matrix row's 32-k chunk, SW128-swizzled.
// Invariant: exactly ONE commit_group per mainloop iteration (empty group when
// nothing to load), so wait_group 1 at iteration kt guarantees stage kt complete.
#define STG_B  32768
__global__ void __launch_bounds__(128)
mma_gemm(const __nv_bfloat16* __restrict__ Ahi, const __nv_bfloat16* __restrict__ Alo,
         const __nv_bfloat16* __restrict__ Bhi, const __nv_bfloat16* __restrict__ Blo,
         float* __restrict__ C, int ldc, int K)
{
    extern __shared__ __align__(1024) char dynsm[];
    const uint32_t sb = smem_u32(dynsm);

    const int tid  = threadIdx.x;
    const int lane = tid & 31;
    const int wid  = tid >> 5;
    const int wm   = wid & 1;
    const int wn   = wid >> 1;
    const int m0   = blockIdx.y * 128;
    const int n0   = blockIdx.x * 128;

    float acc[4][8][4];
#pragma unroll
    for (int m = 0; m < 4; m++)
#pragma unroll
        for (int n = 0; n < 8; n++)
#pragma unroll
            for (int v = 0; v < 4; v++) acc[m][n][v] = 0.f;

    const int a_row = lane & 15;
    const int b_row = (lane & 7) + ((lane >> 3) & 1) * 8;
    const int cb    = (lane >> 4) * 16;      // 16B column half within 32B k-chunk

    // stage loader: 2048 x 16B chunks, 16 per thread
#define LOAD_STAGE(s, koff) do {                                               \
    const uint32_t sdst = sb + (s) * STG_B;                                    \
    _Pragma("unroll")                                                          \
    for (int it = 0; it < 16; it++) {                                          \
        int i = tid + it * 128;                                                \
        int arr = i >> 10;                                                     \
        int j = i & 1023;                                                      \
        int row = j >> 3;                                                      \
        int half = (j >> 2) & 1, c = j & 3;                                    \
        const __nv_bfloat16* g = arr ? (half ? Blo : Bhi) : (half ? Alo : Ahi);\
        int rb = arr ? n0 : m0;                                                \
        const void* gp = g + (size_t)(rb + row) * K + (koff) + c * 8;          \
        uint32_t d = sdst + arr * 16384 + SWZ(row * 128 + half * 64 + c * 16); \
        CP16(d, gp);                                                           \
    }                                                                          \
    CP_COMMIT();                                                               \
} while (0)

    LOAD_STAGE(0, 0);
    LOAD_STAGE(1, 32);

    const int NK = K / 32;
    for (int kt = 0; kt < NK; kt++) {
        CP_WAIT1();
        __syncthreads();
        if (kt + 2 < NK) LOAD_STAGE((kt + 2) % 3, (kt + 2) * 32);
        else             CP_COMMIT();   // empty group keeps the wait invariant

        const uint32_t stg = sb + (kt % 3) * STG_B;
#pragma unroll
        for (int ks = 0; ks < 2; ks++) {
            uint32_t bh[4][4], bl[4][4];
#pragma unroll
            for (int p = 0; p < 4; p++) {
                uint32_t off = (uint32_t)(wn * 64 + p * 16 + b_row) * 128 + ks * 32 + cb;
                ldsm4(bh[p], stg + 16384 + SWZ(off));
                ldsm4(bl[p], stg + 16384 + SWZ(off + 64));
            }
#pragma unroll
            for (int m = 0; m < 4; m++) {
                uint32_t ah[4], al[4];
                uint32_t off = (uint32_t)(wm * 64 + m * 16 + a_row) * 128 + ks * 32 + cb;
                ldsm4(ah, stg + SWZ(off));
                ldsm4(al, stg + SWZ(off + 64));
#pragma unroll
                for (int n = 0; n < 8; n++) {
                    const int p = n >> 1, q = n & 1;
                    mma16816(acc[m][n], ah, bh[p][q], bh[p][q + 2]);
                    mma16816(acc[m][n], ah, bl[p][q], bl[p][q + 2]);
                    mma16816(acc[m][n], al, bh[p][q], bh[p][q + 2]);
                }
            }
        }
        __syncthreads();   // all warps done reading stage (kt%3) before it is refilled
    }

    // ---- epilogue ----
#pragma unroll
    for (int m = 0; m < 4; m++) {
        const int row = m0 + wm * 64 + m * 16 + (lane >> 2);
#pragma unroll
        for (int n = 0; n < 8; n++) {
            const int col = n0 + wn * 64 + n * 8 + (lane & 3) * 2;
            *(float2*)(C + (size_t)row * ldc + col)       = make_float2(acc[m][n][0], acc[m][n][1]);
            *(float2*)(C + (size_t)(row + 8) * ldc + col) = make_float2(acc[m][n][2], acc[m][n][3]);
        }
    }
}

// ================= fp32 split kernel =================
__global__ void split_kernel(const float* __restrict__ src,
                             __nv_bfloat16* __restrict__ hi,
                             __nv_bfloat16* __restrict__ lo, int n4)
{
    int i = blockIdx.x * blockDim.x + threadIdx.x;
    if (i >= n4) return;
    float4 v = ((const float4*)src)[i];
    __nv_bfloat16 h0 = __float2bfloat16(v.x), h1 = __float2bfloat16(v.y);
    __nv_bfloat16 h2 = __float2bfloat16(v.z), h3 = __float2bfloat16(v.w);
    __nv_bfloat162* H = (__nv_bfloat162*)hi;
    __nv_bfloat162* L = (__nv_bfloat162*)lo;
    H[i*2+0] = __nv_bfloat162(h0, h1);
    H[i*2+1] = __nv_bfloat162(h2, h3);
    L[i*2+0] = __nv_bfloat162(__float2bfloat16(v.x - __bfloat162float(h0)),
                              __float2bfloat16(v.y - __bfloat162float(h1)));
    L[i*2+1] = __nv_bfloat162(__float2bfloat16(v.z - __bfloat162float(h2)),
                              __float2bfloat16(v.w - __bfloat162float(h3)));
}

// ============ pipelined fp32 GEMM (dt GEMM, fused SSM prep) ============
template<int BM, int BN, int BK, int TM, int TN, bool FUSE>
__global__ void __launch_bounds__((BM/TM)*(BN/TN))
gemm_pipe(const float* __restrict__ A, int lda,
          const float* __restrict__ B, int ldb,
          float* __restrict__ C, int ldc, int K,
          const float* __restrict__ dtb, float* __restrict__ dbu_out)
{
    constexpr int THREADS = (BM/TM) * (BN/TN);
    constexpr int KV = BK / 4;
    constexpr int NA = (BM * KV) / THREADS;
    constexpr int NB = (BN * KV) / THREADS;

    __shared__ float As[2][BK][BM + 4];
    __shared__ float Bs[2][BK][BN + 4];

    const int tid = threadIdx.x;
    const int m0 = blockIdx.y * BM;
    const int n0 = blockIdx.x * BN;
    const int tx = tid % (BN / TN);
    const int ty = tid / (BN / TN);

    float acc[TM][TN];
#pragma unroll
    for (int i = 0; i < TM; i++)
#pragma unroll
        for (int j = 0; j < TN; j++) acc[i][j] = 0.f;

    float4 stA[NA], stB[NB];
#pragma unroll
    for (int t = 0; t < NA; t++) {
        int i = tid + t * THREADS; int row = i / KV, kc = (i % KV) * 4;
        stA[t] = *reinterpret_cast<const float4*>(A + (size_t)(m0 + row) * lda + kc);
    }
#pragma unroll
    for (int t = 0; t < NB; t++) {
        int i = tid + t * THREADS; int row = i / KV, kc = (i % KV) * 4;
        stB[t] = *reinterpret_cast<const float4*>(B + (size_t)(n0 + row) * ldb + kc);
    }
#pragma unroll
    for (int t = 0; t < NA; t++) {
        int i = tid + t * THREADS; int row = i / KV, kc = (i % KV) * 4;
        As[0][kc+0][row] = stA[t].x; As[0][kc+1][row] = stA[t].y;
        As[0][kc+2][row] = stA[t].z; As[0][kc+3][row] = stA[t].w;
    }
#pragma unroll
    for (int t = 0; t < NB; t++) {
        int i = tid + t * THREADS; int row = i / KV, kc = (i % KV) * 4;
        Bs[0][kc+0][row] = stB[t].x; Bs[0][kc+1][row] = stB[t].y;
        Bs[0][kc+2][row] = stB[t].z; Bs[0][kc+3][row] = stB[t].w;
    }
    __syncthreads();

    const int nk = K / BK;
    for (int kt = 0; kt < nk; kt++) {
        const int cur = kt & 1, nxt = cur ^ 1;
        if (kt + 1 < nk) {
            const int k0 = (kt + 1) * BK;
#pragma unroll
            for (int t = 0; t < NA; t++) {
                int i = tid + t * THREADS; int row = i / KV, kc = (i % KV) * 4;
                stA[t] = *reinterpret_cast<const float4*>(A + (size_t)(m0 + row) * lda + k0 + kc);
            }
#pragma unroll
            for (int t = 0; t < NB; t++) {
                int i = tid + t * THREADS; int row = i / KV, kc = (i % KV) * 4;
                stB[t] = *reinterpret_cast<const float4*>(B + (size_t)(n0 + row) * ldb + k0 + kc);
            }
        }
#pragma unroll
        for (int kk = 0; kk < BK; kk++) {
            float ra[TM], rb[TN];
            const float4* pa = reinterpret_cast<const float4*>(&As[cur][kk][ty * TM]);
            const float4* pb = reinterpret_cast<const float4*>(&Bs[cur][kk][tx * TN]);
#pragma unroll
            for (int v = 0; v < TM / 4; v++) {
                float4 q = pa[v];
                ra[v*4+0]=q.x; ra[v*4+1]=q.y; ra[v*4+2]=q.z; ra[v*4+3]=q.w;
            }
#pragma unroll
            for (int v = 0; v < TN / 4; v++) {
                float4 q = pb[v];
                rb[v*4+0]=q.x; rb[v*4+1]=q.y; rb[v*4+2]=q.z; rb[v*4+3]=q.w;
            }
#pragma unroll
            for (int i = 0; i < TM; i++)
#pragma unroll
                for (int j = 0; j < TN; j++)
                    acc[i][j] = fmaf(ra[i], rb[j], acc[i][j]);
        }
        if (kt + 1 < nk) {
#pragma unroll
            for (int t = 0; t < NA; t++) {
                int i = tid + t * THREADS; int row = i / KV, kc = (i % KV) * 4;
                As[nxt][kc+0][row] = stA[t].x; As[nxt][kc+1][row] = stA[t].y;
                As[nxt][kc+2][row] = stA[t].z; As[nxt][kc+3][row] = stA[t].w;
            }
#pragma unroll
            for (int t = 0; t < NB; t++) {
                int i = tid + t * THREADS; int row = i / KV, kc = (i % KV) * 4;
                Bs[nxt][kc+0][row] = stB[t].x; Bs[nxt][kc+1][row] = stB[t].y;
                Bs[nxt][kc+2][row] = stB[t].z; Bs[nxt][kc+3][row] = stB[t].w;
            }
        }
        __syncthreads();
    }

    if constexpr (FUSE) {
#pragma unroll
        for (int i = 0; i < TM; i++) {
            int m = m0 + ty * TM + i;
            float Bsv = g_xdbl[(size_t)m * RPAD + DTR];
#pragma unroll
            for (int j = 0; j < TN; j++) {
                int n = n0 + tx * TN + j;
                float dtv   = acc[i][j] + dtb[n];
                float delta = (dtv > 20.f) ? dtv : log1pf(expf(dtv));
                float dA    = expf(delta * g_A[n]);
                float u     = g_xc[(size_t)m * DI + n];
                C[(size_t)m * ldc + n]       = dA;
                dbu_out[(size_t)m * ldc + n] = delta * Bsv * u;
            }
        }
    } else {
#pragma unroll
        for (int i = 0; i < TM; i++) {
            int m = m0 + ty * TM + i;
#pragma unroll
            for (int j = 0; j < TN; j++)
                C[(size_t)m * ldc + n0 + tx * TN + j] = acc[i][j];
        }
    }
}

// ============ ragged-N fp32 GEMM (x_dbl projection) ============
template<int BM, int BN, int BK, int TM, int TN>
__global__ void __launch_bounds__((BM/TM)*(BN/TN))
gemm_tn(const float* __restrict__ A, int lda,
        const float* __restrict__ B, int ldb,
        float* __restrict__ C, int ldc,
        int N, int K)
{
    constexpr int THREADS = (BM/TM) * (BN/TN);
    __shared__ float As[BK][BM + 4];
    __shared__ float Bs[BK][BN + 4];

    const int tid = threadIdx.x;
    const int m0 = blockIdx.y * BM;
    const int n0 = blockIdx.x * BN;
    const int tx = tid % (BN / TN);
    const int ty = tid / (BN / TN);

    float acc[TM][TN];
#pragma unroll
    for (int i = 0; i < TM; i++)
#pragma unroll
        for (int j = 0; j < TN; j++) acc[i][j] = 0.f;

    for (int k0 = 0; k0 < K; k0 += BK) {
        for (int i = tid; i < BM * BK / 4; i += THREADS) {
            int row = i / (BK / 4), kc = (i % (BK / 4)) * 4;
            float4 v = *reinterpret_cast<const float4*>(A + (size_t)(m0 + row) * lda + k0 + kc);
            As[kc+0][row] = v.x; As[kc+1][row] = v.y; As[kc+2][row] = v.z; As[kc+3][row] = v.w;
        }
        for (int i = tid; i < BN * BK / 4; i += THREADS) {
            int row = i / (BK / 4), kc = (i % (BK / 4)) * 4;
            float4 v = make_float4(0.f, 0.f, 0.f, 0.f);
            if (n0 + row < N)
                v = *reinterpret_cast<const float4*>(B + (size_t)(n0 + row) * ldb + k0 + kc);
            Bs[kc+0][row] = v.x; Bs[kc+1][row] = v.y; Bs[kc+2][row] = v.z; Bs[kc+3][row] = v.w;
        }
        __syncthreads();
#pragma unroll
        for (int kk = 0; kk < BK; kk++) {
            float ra[TM], rb[TN];
#pragma unroll
            for (int i = 0; i < TM; i++) ra[i] = As[kk][ty * TM + i];
#pragma unroll
            for (int j = 0; j < TN; j++) rb[j] = Bs[kk][tx * TN + j];
#pragma unroll
            for (int i = 0; i < TM; i++)
#pragma unroll
                for (int j = 0; j < TN; j++)
                    acc[i][j] = fmaf(ra[i], rb[j], acc[i][j]);
        }
        __syncthreads();
    }
#pragma unroll
    for (int i = 0; i < TM; i++) {
        int m = m0 + ty * TM + i;
#pragma unroll
        for (int j = 0; j < TN; j++) {
            int n = n0 + tx * TN + j;
            if (n < N) C[(size_t)m * ldc + n] = acc[i][j];
        }
    }
}

// ---------------- depthwise conv (k=2) + SiLU ----------------
__global__ void conv_silu_kernel(const float* __restrict__ cw, const float* __restrict__ cb)
{
    int idx = blockIdx.x * blockDim.x + threadIdx.x;
    if (idx >= NTOK * DI) return;
    int d = idx & (DI - 1);
    int tok = idx >> 10;
    int l = tok & (LL - 1);
    float cur  = g_xz[(size_t)tok * (2 * DI) + d];
    float prev = (l > 0) ? g_xz[(size_t)(tok - 1) * (2 * DI) + d] : 0.f;
    float v = fmaf(cw[2 * d], prev, fmaf(cw[2 * d + 1], cur, cb[d]));
    g_xc[idx] = v / (1.f + expf(-v));
}

__global__ void precomp_A_kernel(const float* __restrict__ Alogs)
{
    int d = blockIdx.x * blockDim.x + threadIdx.x;
    if (d < DI) g_A[d] = -expf(Alogs[d]);
}

// ---------------- chunked scan ----------------
__global__ void scan_pass1_kernel()
{
    int t = blockIdx.x * blockDim.x + threadIdx.x;
    if (t >= BB * NCH * DI) return;
    int d = t & (DI - 1);
    int c = (t >> 10) & (NCH - 1);
    int b = t >> 13;
    size_t base = ((size_t)b * LL + (size_t)c * CH) * DI + d;
    float aprod = 1.f, h = 0.f;
#pragma unroll 4
    for (int l = 0; l < CH; l++) {
        float a  = g_dt [base + (size_t)l * DI];
        float bu = g_dbu[base + (size_t)l * DI];
        h = fmaf(a, h, bu);
        aprod *= a;
    }
    g_Ac[t] = aprod;
    g_Bc[t] = h;
}

__global__ void scan_pass2_kernel()
{
    int t = blockIdx.x * blockDim.x + threadIdx.x;
    if (t >= BB * DI) return;
    int d = t & (DI - 1);
    int b = t >> 10;
    float h = 0.f;
#pragma unroll
    for (int c = 0; c < NCH; c++) {
        int idx = ((b * NCH) + c) * DI + d;
        g_h0[idx] = h;
        h = fmaf(g_Ac[idx], h, g_Bc[idx]);
    }
}

__global__ void scan_pass3_kernel(const float* __restrict__ Ds)
{
    int t = blockIdx.x * blockDim.x + threadIdx.x;
    if (t >= BB * NCH * DI) return;
    int d = t & (DI - 1);
    int c = (t >> 10) & (NCH - 1);
    int b = t >> 13;
    float Dd = Ds[d];
    float h = g_h0[t];
    size_t tok0 = (size_t)b * LL + (size_t)c * CH;
    size_t base = tok0 * DI + d;
#pragma unroll 4
    for (int l = 0; l < CH; l++) {
        float a  = g_dt [base + (size_t)l * DI];
        float bu = g_dbu[base + (size_t)l * DI];
        float u  = g_xc [base + (size_t)l * DI];
        float Cs = g_xdbl[(tok0 + l) * RPAD + DTR + 1];
        h = fmaf(a, h, bu);
        g_y[base + (size_t)l * DI] = fmaf(h, Cs, u * Dd);
    }
}

// ---------------- LayerNorm + SiLU gate, fused bf16 split output ----------------
__global__ void __launch_bounds__(256) ln_gate_kernel(const float* __restrict__ lnw,
                                                      const float* __restrict__ lnb)
{
    int tok = blockIdx.x;
    int tid = threadIdx.x;
    size_t base = (size_t)tok * DI;

    float v[4];
    float s = 0.f, q = 0.f;
#pragma unroll
    for (int i = 0; i < 4; i++) {
        float x = g_y[base + tid + i * 256];
        v[i] = x; s += x; q += x * x;
    }
#pragma unroll
    for (int o = 16; o; o >>= 1) {
        s += __shfl_xor_sync(0xffffffffu, s, o);
        q += __shfl_xor_sync(0xffffffffu, q, o);
    }
    __shared__ float ss[8], sq[8];
    if ((tid & 31) == 0) { ss[tid >> 5] = s; sq[tid >> 5] = q; }
    __syncthreads();
    float S = 0.f, Q = 0.f;
#pragma unroll
    for (int w = 0; w < 8; w++) { S += ss[w]; Q += sq[w]; }

    float mu  = S * (1.f / DI);
    float var = Q * (1.f / DI) - mu * mu;
    float rs  = rsqrtf(var + 1e-5f);
#pragma unroll
    for (int i = 0; i < 4; i++) {
        int d = tid + i * 256;
        float z  = g_xz[(size_t)tok * (2 * DI) + DI + d];
        float gt = z / (1.f + expf(-z));
        float val = fmaf((v[i] - mu) * rs, lnw[d], lnb[d]) * gt;
        __nv_bfloat16 h = __float2bfloat16(val);
        g_yhi[base + d] = h;
        g_ylo[base + d] = __float2bfloat16(val - __bfloat162float(h));
    }
}

// ---------------- launch ----------------
extern "C" void kernel_launch(void* const* d_in, const int* in_sizes, int n_in,
                              void* d_out, int out_size)
{
    const float* x      = (const float*)d_in[0];
    const float* w_in   = (const float*)d_in[1];
    const float* conv_w = (const float*)d_in[2];
    const float* conv_b = (const float*)d_in[3];
    const float* xproj  = (const float*)d_in[4];
    const float* dtw    = (const float*)d_in[5];
    const float* dtb    = (const float*)d_in[6];
    const float* Alogs  = (const float*)d_in[7];
    const float* Ds     = (const float*)d_in[8];
    const float* lnw    = (const float*)d_in[9];
    const float* lnb    = (const float*)d_in[10];
    const float* wout   = (const float*)d_in[11];
    float* out = (float*)d_out;

    float *xz, *xc, *xdbl, *dtf, *dbu;
    __nv_bfloat16 *xhi, *xlo, *w1hi, *w1lo, *yhi, *ylo, *wohi, *wolo;
    cudaGetSymbolAddress((void**)&xz,   g_xz);
    cudaGetSymbolAddress((void**)&xc,   g_xc);
    cudaGetSymbolAddress((void**)&xdbl, g_xdbl);
    cudaGetSymbolAddress((void**)&dtf,  g_dt);
    cudaGetSymbolAddress((void**)&dbu,  g_dbu);
    cudaGetSymbolAddress((void**)&xhi,  g_xhi);
    cudaGetSymbolAddress((void**)&xlo,  g_xlo);
    cudaGetSymbolAddress((void**)&w1hi, g_w1hi);
    cudaGetSymbolAddress((void**)&w1lo, g_w1lo);
    cudaGetSymbolAddress((void**)&yhi,  g_yhi);
    cudaGetSymbolAddress((void**)&ylo,  g_ylo);
    cudaGetSymbolAddress((void**)&wohi, g_wohi);
    cudaGetSymbolAddress((void**)&wolo, g_wolo);

    const int SMEM_MMA = 3 * STG_B;   // 98304 bytes, 2 CTAs/SM
    cudaFuncSetAttribute(mma_gemm, cudaFuncAttributeMaxDynamicSharedMemorySize, SMEM_MMA);

    const int EW_BLOCKS = (NTOK * DI + 255) / 256;

    // 0) split fp32 -> bf16 hi/lo
    split_kernel<<<(NTOK * DM / 4 + 255) / 256, 256>>>(x, xhi, xlo, NTOK * DM / 4);
    split_kernel<<<(2 * DI * DM / 4 + 255) / 256, 256>>>(w_in, w1hi, w1lo, 2 * DI * DM / 4);
    split_kernel<<<(DM * DI / 4 + 255) / 256, 256>>>(wout, wohi, wolo, DM * DI / 4);

    // 1) xz = x @ w_in^T  (HMMA, split-accumulate)
    mma_gemm<<<dim3(2 * DI / 128, NTOK / 128), 128, SMEM_MMA>>>(xhi, xlo, w1hi, w1lo, xz, 2 * DI, DM);

    // 2) depthwise conv + silu
    conv_silu_kernel<<<EW_BLOCKS, 256>>>(conv_w, conv_b);

    // 3) x_dbl = xc @ xproj^T
    gemm_tn<128,80,16,8,5><<<dim3(1, NTOK/128), 256>>>(xc, DI, xproj, DI, xdbl, RPAD, RTOT, DI);

    // 4) A = -exp(A_logs)
    precomp_A_kernel<<<4, 256>>>(Alogs);

    // 5) dt GEMM + fused SSM prep
    gemm_pipe<128,128,16,8,8,true><<<dim3(DI/128, NTOK/128), 256>>>(
        xdbl, RPAD, dtw, DTR, dtf, DI, DTR, dtb, dbu);

    // 6) chunked scan
    scan_pass1_kernel<<<(BB * NCH * DI + 255) / 256, 256>>>();
    scan_pass2_kernel<<<(BB * DI + 255) / 256, 256>>>();
    scan_pass3_kernel<<<(BB * NCH * DI + 255) / 256, 256>>>(Ds);

    // 7) LayerNorm + gate, emits bf16 hi/lo
    ln_gate_kernel<<<NTOK, 256>>>(lnw, lnb);

    // 8) out = yln @ w_out^T  (HMMA)
    mma_gemm<<<dim3(DI / 128, NTOK / 128), 128, SMEM_MMA>>>(yhi, ylo, wohi, wolo, out, DM, DI);
}

// round 9
// speedup vs baseline: 3.1966x; 1.0979x over previous
#include <cuda_runtime.h>
#include <cuda_bf16.h>
#include <math.h>
#include <stdint.h>

#define BB   4
#define LL   4096
#define DM   1024
#define DI   1024
#define DTR  64
#define RTOT 66
#define RPAD 68
#define NTOK (BB*LL)     // 16384
#define CH   512
#define NCH  (LL/CH)

// ---------------- scratch ----------------
__device__ __align__(16) float g_xz  [(size_t)NTOK * 2 * DI];
__device__ __align__(16) float g_xc  [(size_t)NTOK * DI];
__device__ __align__(16) float g_xdbl[(size_t)NTOK * RPAD];
__device__ __align__(16) float g_dt  [(size_t)NTOK * DI];
__device__ __align__(16) float g_dbu [(size_t)NTOK * DI];
__device__ __align__(16) float g_y   [(size_t)NTOK * DI];
__device__ __align__(16) float g_A   [DI];
__device__ __align__(16) float g_Ac  [BB * NCH * DI];
__device__ __align__(16) float g_Bc  [BB * NCH * DI];
__device__ __align__(16) float g_h0  [BB * NCH * DI];
// bf16 split buffers
__device__ __align__(16) __nv_bfloat16 g_xhi [(size_t)NTOK * DM];
__device__ __align__(16) __nv_bfloat16 g_xlo [(size_t)NTOK * DM];
__device__ __align__(16) __nv_bfloat16 g_w1hi[(size_t)2 * DI * DM];
__device__ __align__(16) __nv_bfloat16 g_w1lo[(size_t)2 * DI * DM];
__device__ __align__(16) __nv_bfloat16 g_yhi [(size_t)NTOK * DI];
__device__ __align__(16) __nv_bfloat16 g_ylo [(size_t)NTOK * DI];
__device__ __align__(16) __nv_bfloat16 g_wohi[(size_t)DM * DI];
__device__ __align__(16) __nv_bfloat16 g_wolo[(size_t)DM * DI];
// xc bf16 split (for HMMA x_dbl)
__device__ __align__(16) __nv_bfloat16 g_xchi[(size_t)NTOK * DI];
__device__ __align__(16) __nv_bfloat16 g_xclo[(size_t)NTOK * DI];
// x_proj split, zero-padded to 128 rows (rows 66..127 stay zero: static init)
__device__ __align__(16) __nv_bfloat16 g_xphi[(size_t)128 * DI];
__device__ __align__(16) __nv_bfloat16 g_xplo[(size_t)128 * DI];

// ================= helpers =================
__device__ __forceinline__ uint32_t smem_u32(const void* p) {
    uint32_t a;
    asm("{ .reg .u64 t; cvta.to.shared.u64 t, %1; cvt.u32.u64 %0, t; }" : "=r"(a) : "l"(p));
    return a;
}
__device__ __forceinline__ void ldsm4(uint32_t* r, uint32_t addr) {
    asm volatile("ldmatrix.sync.aligned.m8n8.x4.shared.b16 {%0,%1,%2,%3}, [%4];"
                 : "=r"(r[0]), "=r"(r[1]), "=r"(r[2]), "=r"(r[3]) : "r"(addr));
}
__device__ __forceinline__ void mma16816(float* d, const uint32_t* a, uint32_t b0, uint32_t b1) {
    asm volatile("mma.sync.aligned.m16n8k16.row.col.f32.bf16.bf16.f32 "
                 "{%0,%1,%2,%3}, {%4,%5,%6,%7}, {%8,%9}, {%0,%1,%2,%3};"
                 : "+f"(d[0]), "+f"(d[1]), "+f"(d[2]), "+f"(d[3])
                 : "r"(a[0]), "r"(a[1]), "r"(a[2]), "r"(a[3]), "r"(b0), "r"(b1));
}
#define SWZ(o) ((o) ^ (((o) >> 3) & 0x70))
#define CP16(dst, src) asm volatile("cp.async.cg.shared.global [%0], [%1], 16;" :: "r"(dst), "l"(src))
#define CP_COMMIT()    asm volatile("cp.async.commit_group;" ::: "memory")
#define CP_WAIT1()     asm volatile("cp.async.wait_group 1;" ::: "memory")

// ============ HMMA split GEMM v3 ============
// C[M,N] = A[M,K] @ B[N,K]^T, fp32 pre-split bf16 hi/lo, 3-term accumulate.
// grid (N/128, M/128), 128 threads (4 warps 2x2, 64x64 warp tiles), BK=32.
// Per-iteration commit invariant (empty group on tail) -> wait_group 1 safe.
// nvalid: # valid C columns (ragged-N support for x_dbl; stores guarded).
#define STG_B  32768
__global__ void __launch_bounds__(128)
mma_gemm(const __nv_bfloat16* __restrict__ Ahi, const __nv_bfloat16* __restrict__ Alo,
         const __nv_bfloat16* __restrict__ Bhi, const __nv_bfloat16* __restrict__ Blo,
         float* __restrict__ C, int ldc, int K, int nvalid)
{
    extern __shared__ __align__(1024) char dynsm[];
    const uint32_t sb = smem_u32(dynsm);

    const int tid  = threadIdx.x;
    const int lane = tid & 31;
    const int wid  = tid >> 5;
    const int wm   = wid & 1;
    const int wn   = wid >> 1;
    const int m0   = blockIdx.y * 128;
    const int n0   = blockIdx.x * 128;

    float acc[4][8][4];
#pragma unroll
    for (int m = 0; m < 4; m++)
#pragma unroll
        for (int n = 0; n < 8; n++)
#pragma unroll
            for (int v = 0; v < 4; v++) acc[m][n][v] = 0.f;

    const int a_row = lane & 15;
    const int b_row = (lane & 7) + ((lane >> 3) & 1) * 8;
    const int cb    = (lane >> 4) * 16;

    // precomputed swizzled fragment offsets (lo = hi ^ 64; carry-free)
    uint32_t aoff[2][4], boff[2][4];
#pragma unroll
    for (int ks = 0; ks < 2; ks++) {
#pragma unroll
        for (int m = 0; m < 4; m++)
            aoff[ks][m] = SWZ((uint32_t)(wm * 64 + m * 16 + a_row) * 128 + ks * 32 + cb);
#pragma unroll
        for (int p = 0; p < 4; p++)
            boff[ks][p] = 16384u + SWZ((uint32_t)(wn * 64 + p * 16 + b_row) * 128 + ks * 32 + cb);
    }

#define LOAD_STAGE(s, koff) do {                                               \
    const uint32_t sdst = sb + (s) * STG_B;                                    \
    _Pragma("unroll")                                                          \
    for (int it = 0; it < 16; it++) {                                          \
        int i = tid + it * 128;                                                \
        int arr = i >> 10;                                                     \
        int j = i & 1023;                                                      \
        int row = j >> 3;                                                      \
        int half = (j >> 2) & 1, c = j & 3;                                    \
        const __nv_bfloat16* g = arr ? (half ? Blo : Bhi) : (half ? Alo : Ahi);\
        int rb = arr ? n0 : m0;                                                \
        const void* gp = g + (size_t)(rb + row) * K + (koff) + c * 8;          \
        uint32_t d = sdst + arr * 16384 + SWZ(row * 128 + half * 64 + c * 16); \
        CP16(d, gp);                                                           \
    }                                                                          \
    CP_COMMIT();                                                               \
} while (0)

    LOAD_STAGE(0, 0);
    LOAD_STAGE(1, 32);

    const int NK = K / 32;
    for (int kt = 0; kt < NK; kt++) {
        CP_WAIT1();
        __syncthreads();
        if (kt + 2 < NK) LOAD_STAGE((kt + 2) % 3, (kt + 2) * 32);
        else             CP_COMMIT();   // empty group keeps the wait invariant

        const uint32_t stg = sb + (kt % 3) * STG_B;
#pragma unroll
        for (int ks = 0; ks < 2; ks++) {
            uint32_t bh[4][4], bl[4][4];
#pragma unroll
            for (int p = 0; p < 4; p++) {
                uint32_t ba = stg + boff[ks][p];
                ldsm4(bh[p], ba);
                ldsm4(bl[p], ba ^ 64u);
            }
            uint32_t ah[2][4], al[2][4];
            {
                uint32_t aa = stg + aoff[ks][0];
                ldsm4(ah[0], aa);
                ldsm4(al[0], aa ^ 64u);
            }
#pragma unroll
            for (int m = 0; m < 4; m++) {
                const int cur = m & 1;
                if (m < 3) {               // prefetch next A frags over the MMAs
                    uint32_t aa = stg + aoff[ks][m + 1];
                    ldsm4(ah[cur ^ 1], aa);
                    ldsm4(al[cur ^ 1], aa ^ 64u);
                }
#pragma unroll
                for (int n = 0; n < 8; n++) {
                    const int p = n >> 1, q = n & 1;
                    mma16816(acc[m][n], ah[cur], bh[p][q], bh[p][q + 2]);
                    mma16816(acc[m][n], ah[cur], bl[p][q], bl[p][q + 2]);
                    mma16816(acc[m][n], al[cur], bh[p][q], bh[p][q + 2]);
                }
            }
        }
        __syncthreads();   // protect stage kt%3 before next iteration refills it
    }

    // ---- epilogue (ragged-N guarded) ----
#pragma unroll
    for (int m = 0; m < 4; m++) {
        const int row = m0 + wm * 64 + m * 16 + (lane >> 2);
#pragma unroll
        for (int n = 0; n < 8; n++) {
            const int col = n0 + wn * 64 + n * 8 + (lane & 3) * 2;
            if (col + 2 <= nvalid) {
                *(float2*)(C + (size_t)row * ldc + col)       = make_float2(acc[m][n][0], acc[m][n][1]);
                *(float2*)(C + (size_t)(row + 8) * ldc + col) = make_float2(acc[m][n][2], acc[m][n][3]);
            }
        }
    }
}

// ================= combined fp32 -> bf16 hi/lo split =================
__device__ __forceinline__ void split4(float4 v, __nv_bfloat16* hi, __nv_bfloat16* lo, int i)
{
    __nv_bfloat16 h0 = __float2bfloat16(v.x), h1 = __float2bfloat16(v.y);
    __nv_bfloat16 h2 = __float2bfloat16(v.z), h3 = __float2bfloat16(v.w);
    __nv_bfloat162* H = (__nv_bfloat162*)hi;
    __nv_bfloat162* L = (__nv_bfloat162*)lo;
    H[i*2+0] = __nv_bfloat162(h0, h1);
    H[i*2+1] = __nv_bfloat162(h2, h3);
    L[i*2+0] = __nv_bfloat162(__float2bfloat16(v.x - __bfloat162float(h0)),
                              __float2bfloat16(v.y - __bfloat162float(h1)));
    L[i*2+1] = __nv_bfloat162(__float2bfloat16(v.z - __bfloat162float(h2)),
                              __float2bfloat16(v.w - __bfloat162float(h3)));
}

#define N4_X  (NTOK * DM / 4)
#define N4_W1 (2 * DI * DM / 4)
#define N4_WO (DM * DI / 4)
#define N4_XP (RTOT * DI / 4)
#define N4_ALL (N4_X + N4_W1 + N4_WO + N4_XP)

__global__ void split_all_kernel(const float* __restrict__ x, const float* __restrict__ w1,
                                 const float* __restrict__ wo, const float* __restrict__ xp)
{
    int i = blockIdx.x * blockDim.x + threadIdx.x;
    if (i < N4_X) { split4(((const float4*)x)[i], g_xhi, g_xlo, i); return; }
    i -= N4_X;
    if (i < N4_W1) { split4(((const float4*)w1)[i], g_w1hi, g_w1lo, i); return; }
    i -= N4_W1;
    if (i < N4_WO) { split4(((const float4*)wo)[i], g_wohi, g_wolo, i); return; }
    i -= N4_WO;
    if (i < N4_XP) { split4(((const float4*)xp)[i], g_xphi, g_xplo, i); }
}

// ============ pipelined fp32 GEMM (dt GEMM, fused SSM prep) ============
template<int BM, int BN, int BK, int TM, int TN>
__global__ void __launch_bounds__((BM/TM)*(BN/TN))
gemm_pipe(const float* __restrict__ A, int lda,
          const float* __restrict__ B, int ldb,
          float* __restrict__ C, int ldc, int K,
          const float* __restrict__ dtb, float* __restrict__ dbu_out)
{
    constexpr int THREADS = (BM/TM) * (BN/TN);
    constexpr int KV = BK / 4;
    constexpr int NA = (BM * KV) / THREADS;
    constexpr int NB = (BN * KV) / THREADS;

    __shared__ float As[2][BK][BM + 4];
    __shared__ float Bs[2][BK][BN + 4];

    const int tid = threadIdx.x;
    const int m0 = blockIdx.y * BM;
    const int n0 = blockIdx.x * BN;
    const int tx = tid % (BN / TN);
    const int ty = tid / (BN / TN);

    float acc[TM][TN];
#pragma unroll
    for (int i = 0; i < TM; i++)
#pragma unroll
        for (int j = 0; j < TN; j++) acc[i][j] = 0.f;

    float4 stA[NA], stB[NB];
#pragma unroll
    for (int t = 0; t < NA; t++) {
        int i = tid + t * THREADS; int row = i / KV, kc = (i % KV) * 4;
        stA[t] = *reinterpret_cast<const float4*>(A + (size_t)(m0 + row) * lda + kc);
    }
#pragma unroll
    for (int t = 0; t < NB; t++) {
        int i = tid + t * THREADS; int row = i / KV, kc = (i % KV) * 4;
        stB[t] = *reinterpret_cast<const float4*>(B + (size_t)(n0 + row) * ldb + kc);
    }
#pragma unroll
    for (int t = 0; t < NA; t++) {
        int i = tid + t * THREADS; int row = i / KV, kc = (i % KV) * 4;
        As[0][kc+0][row] = stA[t].x; As[0][kc+1][row] = stA[t].y;
        As[0][kc+2][row] = stA[t].z; As[0][kc+3][row] = stA[t].w;
    }
#pragma unroll
    for (int t = 0; t < NB; t++) {
        int i = tid + t * THREADS; int row = i / KV, kc = (i % KV) * 4;
        Bs[0][kc+0][row] = stB[t].x; Bs[0][kc+1][row] = stB[t].y;
        Bs[0][kc+2][row] = stB[t].z; Bs[0][kc+3][row] = stB[t].w;
    }
    __syncthreads();

    const int nk = K / BK;
    for (int kt = 0; kt < nk; kt++) {
        const int cur = kt & 1, nxt = cur ^ 1;
        if (kt + 1 < nk) {
            const int k0 = (kt + 1) * BK;
#pragma unroll
            for (int t = 0; t < NA; t++) {
                int i = tid + t * THREADS; int row = i / KV, kc = (i % KV) * 4;
                stA[t] = *reinterpret_cast<const float4*>(A + (size_t)(m0 + row) * lda + k0 + kc);
            }
#pragma unroll
            for (int t = 0; t < NB; t++) {
                int i = tid + t * THREADS; int row = i / KV, kc = (i % KV) * 4;
                stB[t] = *reinterpret_cast<const float4*>(B + (size_t)(n0 + row) * ldb + k0 + kc);
            }
        }
#pragma unroll
        for (int kk = 0; kk < BK; kk++) {
            float ra[TM], rb[TN];
            const float4* pa = reinterpret_cast<const float4*>(&As[cur][kk][ty * TM]);
            const float4* pb = reinterpret_cast<const float4*>(&Bs[cur][kk][tx * TN]);
#pragma unroll
            for (int v = 0; v < TM / 4; v++) {
                float4 q = pa[v];
                ra[v*4+0]=q.x; ra[v*4+1]=q.y; ra[v*4+2]=q.z; ra[v*4+3]=q.w;
            }
#pragma unroll
            for (int v = 0; v < TN / 4; v++) {
                float4 q = pb[v];
                rb[v*4+0]=q.x; rb[v*4+1]=q.y; rb[v*4+2]=q.z; rb[v*4+3]=q.w;
            }
#pragma unroll
            for (int i = 0; i < TM; i++)
#pragma unroll
                for (int j = 0; j < TN; j++)
                    acc[i][j] = fmaf(ra[i], rb[j], acc[i][j]);
        }
        if (kt + 1 < nk) {
#pragma unroll
            for (int t = 0; t < NA; t++) {
                int i = tid + t * THREADS; int row = i / KV, kc = (i % KV) * 4;
                As[nxt][kc+0][row] = stA[t].x; As[nxt][kc+1][row] = stA[t].y;
                As[nxt][kc+2][row] = stA[t].z; As[nxt][kc+3][row] = stA[t].w;
            }
#pragma unroll
            for (int t = 0; t < NB; t++) {
                int i = tid + t * THREADS; int row = i / KV, kc = (i % KV) * 4;
                Bs[nxt][kc+0][row] = stB[t].x; Bs[nxt][kc+1][row] = stB[t].y;
                Bs[nxt][kc+2][row] = stB[t].z; Bs[nxt][kc+3][row] = stB[t].w;
            }
        }
        __syncthreads();
    }

    // fused SSM prep epilogue
#pragma unroll
    for (int i = 0; i < TM; i++) {
        int m = m0 + ty * TM + i;
        float Bsv = g_xdbl[(size_t)m * RPAD + DTR];
#pragma unroll
        for (int j = 0; j < TN; j++) {
            int n = n0 + tx * TN + j;
            float dtv   = acc[i][j] + dtb[n];
            float delta = (dtv > 20.f) ? dtv : log1pf(expf(dtv));
            float dA    = expf(delta * g_A[n]);
            float u     = g_xc[(size_t)m * DI + n];
            C[(size_t)m * ldc + n]       = dA;
            dbu_out[(size_t)m * ldc + n] = delta * Bsv * u;
        }
    }
}

// ---------------- depthwise conv (k=2) + SiLU, emits fp32 + bf16 hi/lo ----------------
__global__ void conv_silu_kernel(const float* __restrict__ cw, const float* __restrict__ cb)
{
    int idx = blockIdx.x * blockDim.x + threadIdx.x;
    if (idx >= NTOK * DI) return;
    int d = idx & (DI - 1);
    int tok = idx >> 10;
    int l = tok & (LL - 1);
    float cur  = g_xz[(size_t)tok * (2 * DI) + d];
    float prev = (l > 0) ? g_xz[(size_t)(tok - 1) * (2 * DI) + d] : 0.f;
    float v = fmaf(cw[2 * d], prev, fmaf(cw[2 * d + 1], cur, cb[d]));
    float s = v / (1.f + expf(-v));
    g_xc[idx] = s;
    __nv_bfloat16 h = __float2bfloat16(s);
    g_xchi[idx] = h;
    g_xclo[idx] = __float2bfloat16(s - __bfloat162float(h));
}

__global__ void precomp_A_kernel(const float* __restrict__ Alogs)
{
    int d = blockIdx.x * blockDim.x + threadIdx.x;
    if (d < DI) g_A[d] = -expf(Alogs[d]);
}

// ---------------- chunked scan ----------------
__global__ void scan_pass1_kernel()
{
    int t = blockIdx.x * blockDim.x + threadIdx.x;
    if (t >= BB * NCH * DI) return;
    int d = t & (DI - 1);
    int c = (t >> 10) & (NCH - 1);
    int b = t >> 13;
    size_t base = ((size_t)b * LL + (size_t)c * CH) * DI + d;
    float aprod = 1.f, h = 0.f;
#pragma unroll 4
    for (int l = 0; l < CH; l++) {
        float a  = g_dt [base + (size_t)l * DI];
        float bu = g_dbu[base + (size_t)l * DI];
        h = fmaf(a, h, bu);
        aprod *= a;
    }
    g_Ac[t] = aprod;
    g_Bc[t] = h;
}

__global__ void scan_pass2_kernel()
{
    int t = blockIdx.x * blockDim.x + threadIdx.x;
    if (t >= BB * DI) return;
    int d = t & (DI - 1);
    int b = t >> 10;
    float h = 0.f;
#pragma unroll
    for (int c = 0; c < NCH; c++) {
        int idx = ((b * NCH) + c) * DI + d;
        g_h0[idx] = h;
        h = fmaf(g_Ac[idx], h, g_Bc[idx]);
    }
}

__global__ void scan_pass3_kernel(const float* __restrict__ Ds)
{
    int t = blockIdx.x * blockDim.x + threadIdx.x;
    if (t >= BB * NCH * DI) return;
    int d = t & (DI - 1);
    int c = (t >> 10) & (NCH - 1);
    int b = t >> 13;
    float Dd = Ds[d];
    float h = g_h0[t];
    size_t tok0 = (size_t)b * LL + (size_t)c * CH;
    size_t base = tok0 * DI + d;
#pragma unroll 4
    for (int l = 0; l < CH; l++) {
        float a  = g_dt [base + (size_t)l * DI];
        float bu = g_dbu[base + (size_t)l * DI];
        float u  = g_xc [base + (size_t)l * DI];
        float Cs = g_xdbl[(tok0 + l) * RPAD + DTR + 1];
        h = fmaf(a, h, bu);
        g_y[base + (size_t)l * DI] = fmaf(h, Cs, u * Dd);
    }
}

// ---------------- LayerNorm + SiLU gate, fused bf16 split output ----------------
__global__ void __launch_bounds__(256) ln_gate_kernel(const float* __restrict__ lnw,
                                                      const float* __restrict__ lnb)
{
    int tok = blockIdx.x;
    int tid = threadIdx.x;
    size_t base = (size_t)tok * DI;

    float v[4];
    float s = 0.f, q = 0.f;
#pragma unroll
    for (int i = 0; i < 4; i++) {
        float x = g_y[base + tid + i * 256];
        v[i] = x; s += x; q += x * x;
    }
#pragma unroll
    for (int o = 16; o; o >>= 1) {
        s += __shfl_xor_sync(0xffffffffu, s, o);
        q += __shfl_xor_sync(0xffffffffu, q, o);
    }
    __shared__ float ss[8], sq[8];
    if ((tid & 31) == 0) { ss[tid >> 5] = s; sq[tid >> 5] = q; }
    __syncthreads();
    float S = 0.f, Q = 0.f;
#pragma unroll
    for (int w = 0; w < 8; w++) { S += ss[w]; Q += sq[w]; }

    float mu  = S * (1.f / DI);
    float var = Q * (1.f / DI) - mu * mu;
    float rs  = rsqrtf(var + 1e-5f);
#pragma unroll
    for (int i = 0; i < 4; i++) {
        int d = tid + i * 256;
        float z  = g_xz[(size_t)tok * (2 * DI) + DI + d];
        float gt = z / (1.f + expf(-z));
        float val = fmaf((v[i] - mu) * rs, lnw[d], lnb[d]) * gt;
        __nv_bfloat16 h = __float2bfloat16(val);
        g_yhi[base + d] = h;
        g_ylo[base + d] = __float2bfloat16(val - __bfloat162float(h));
    }
}

// ---------------- launch ----------------
extern "C" void kernel_launch(void* const* d_in, const int* in_sizes, int n_in,
                              void* d_out, int out_size)
{
    const float* x      = (const float*)d_in[0];
    const float* w_in   = (const float*)d_in[1];
    const float* conv_w = (const float*)d_in[2];
    const float* conv_b = (const float*)d_in[3];
    const float* xproj  = (const float*)d_in[4];
    const float* dtw    = (const float*)d_in[5];
    const float* dtb    = (const float*)d_in[6];
    const float* Alogs  = (const float*)d_in[7];
    const float* Ds     = (const float*)d_in[8];
    const float* lnw    = (const float*)d_in[9];
    const float* lnb    = (const float*)d_in[10];
    const float* wout   = (const float*)d_in[11];
    float* out = (float*)d_out;

    float *xz, *xdbl, *dtf, *dbu;
    __nv_bfloat16 *xhi, *xlo, *w1hi, *w1lo, *yhi, *ylo, *wohi, *wolo;
    __nv_bfloat16 *xchi, *xclo, *xphi, *xplo;
    cudaGetSymbolAddress((void**)&xz,   g_xz);
    cudaGetSymbolAddress((void**)&xdbl, g_xdbl);
    cudaGetSymbolAddress((void**)&dtf,  g_dt);
    cudaGetSymbolAddress((void**)&dbu,  g_dbu);
    cudaGetSymbolAddress((void**)&xhi,  g_xhi);
    cudaGetSymbolAddress((void**)&xlo,  g_xlo);
    cudaGetSymbolAddress((void**)&w1hi, g_w1hi);
    cudaGetSymbolAddress((void**)&w1lo, g_w1lo);
    cudaGetSymbolAddress((void**)&yhi,  g_yhi);
    cudaGetSymbolAddress((void**)&ylo,  g_ylo);
    cudaGetSymbolAddress((void**)&wohi, g_wohi);
    cudaGetSymbolAddress((void**)&wolo, g_wolo);
    cudaGetSymbolAddress((void**)&xchi, g_xchi);
    cudaGetSymbolAddress((void**)&xclo, g_xclo);
    cudaGetSymbolAddress((void**)&xphi, g_xphi);
    cudaGetSymbolAddress((void**)&xplo, g_xplo);

    const int SMEM_MMA = 3 * STG_B;   // 98304 bytes, 2 CTAs/SM
    cudaFuncSetAttribute(mma_gemm, cudaFuncAttributeMaxDynamicSharedMemorySize, SMEM_MMA);

    const int EW_BLOCKS = (NTOK * DI + 255) / 256;

    // 0) all fp32 -> bf16 hi/lo splits in one kernel
    split_all_kernel<<<(N4_ALL + 255) / 256, 256>>>(x, w_in, wout, xproj);

    // 1) xz = x @ w_in^T  (HMMA)
    mma_gemm<<<dim3(2 * DI / 128, NTOK / 128), 128, SMEM_MMA>>>(
        xhi, xlo, w1hi, w1lo, xz, 2 * DI, DM, 2 * DI);

    // 2) depthwise conv + silu  (fp32 + bf16 split outputs)
    conv_silu_kernel<<<EW_BLOCKS, 256>>>(conv_w, conv_b);

    // 3) x_dbl = xc @ xproj^T  (HMMA, padded B, ragged stores: nvalid=66)
    mma_gemm<<<dim3(1, NTOK / 128), 128, SMEM_MMA>>>(
        xchi, xclo, xphi, xplo, xdbl, RPAD, DI, RTOT);

    // 4) A = -exp(A_logs)
    precomp_A_kernel<<<4, 256>>>(Alogs);

    // 5) dt GEMM + fused SSM prep (fp32, K=64)
    gemm_pipe<128,128,16,8,8><<<dim3(DI/128, NTOK/128), 256>>>(
        xdbl, RPAD, dtw, DTR, dtf, DI, DTR, dtb, dbu);

    // 6) chunked scan
    scan_pass1_kernel<<<(BB * NCH * DI + 255) / 256, 256>>>();
    scan_pass2_kernel<<<(BB * DI + 255) / 256, 256>>>();
    scan_pass3_kernel<<<(BB * NCH * DI + 255) / 256, 256>>>(Ds);

    // 7) LayerNorm + gate, emits bf16 hi/lo
    ln_gate_kernel<<<NTOK, 256>>>(lnw, lnb);

    // 8) out = yln @ w_out^T  (HMMA)
    mma_gemm<<<dim3(DI / 128, NTOK / 128), 128, SMEM_MMA>>>(
        yhi, ylo, wohi, wolo, out, DM, DI, DI);
}

// round 10
// speedup vs baseline: 3.2677x; 1.0223x over previous
#include <cuda_runtime.h>
#include <cuda_bf16.h>
#include <math.h>
#include <stdint.h>

#define BB   4
#define LL   4096
#define DM   1024
#define DI   1024
#define DTR  64
#define RTOT 66
#define RPAD 68
#define NTOK (BB*LL)     // 16384
#define CH   512
#define NCH  (LL/CH)

// ---------------- scratch ----------------
__device__ __align__(16) float g_xz  [(size_t)NTOK * 2 * DI];
__device__ __align__(16) float g_xc  [(size_t)NTOK * DI];
__device__ __align__(16) float g_xdbl[(size_t)NTOK * RPAD];
__device__ __align__(16) float g_dt  [(size_t)NTOK * DI];
__device__ __align__(16) float g_dbu [(size_t)NTOK * DI];
__device__ __align__(16) float g_y   [(size_t)NTOK * DI];
__device__ __align__(16) float g_A   [DI];
__device__ __align__(16) float g_Ac  [BB * NCH * DI];
__device__ __align__(16) float g_Bc  [BB * NCH * DI];
__device__ __align__(16) float g_h0  [BB * NCH * DI];
// bf16 split buffers
__device__ __align__(16) __nv_bfloat16 g_xhi [(size_t)NTOK * DM];
__device__ __align__(16) __nv_bfloat16 g_xlo [(size_t)NTOK * DM];
__device__ __align__(16) __nv_bfloat16 g_w1hi[(size_t)2 * DI * DM];
__device__ __align__(16) __nv_bfloat16 g_w1lo[(size_t)2 * DI * DM];
__device__ __align__(16) __nv_bfloat16 g_yhi [(size_t)NTOK * DI];
__device__ __align__(16) __nv_bfloat16 g_ylo [(size_t)NTOK * DI];
__device__ __align__(16) __nv_bfloat16 g_wohi[(size_t)DM * DI];
__device__ __align__(16) __nv_bfloat16 g_wolo[(size_t)DM * DI];
// xc bf16 split (for HMMA x_dbl)
__device__ __align__(16) __nv_bfloat16 g_xchi[(size_t)NTOK * DI];
__device__ __align__(16) __nv_bfloat16 g_xclo[(size_t)NTOK * DI];
// x_proj split, zero-padded to 128 rows (rows 66..127 stay zero: static init)
__device__ __align__(16) __nv_bfloat16 g_xphi[(size_t)128 * DI];
__device__ __align__(16) __nv_bfloat16 g_xplo[(size_t)128 * DI];
// dts split [NTOK x 64] (A operand of dt GEMM; written by x_dbl epilogue)
__device__ __align__(16) __nv_bfloat16 g_dshi[(size_t)NTOK * DTR];
__device__ __align__(16) __nv_bfloat16 g_dslo[(size_t)NTOK * DTR];
// dt_projs_weight split [1024 x 64]
__device__ __align__(16) __nv_bfloat16 g_dwhi[(size_t)DI * DTR];
__device__ __align__(16) __nv_bfloat16 g_dwlo[(size_t)DI * DTR];

// ================= helpers =================
__device__ __forceinline__ uint32_t smem_u32(const void* p) {
    uint32_t a;
    asm("{ .reg .u64 t; cvta.to.shared.u64 t, %1; cvt.u32.u64 %0, t; }" : "=r"(a) : "l"(p));
    return a;
}
__device__ __forceinline__ void ldsm4(uint32_t* r, uint32_t addr) {
    asm volatile("ldmatrix.sync.aligned.m8n8.x4.shared.b16 {%0,%1,%2,%3}, [%4];"
                 : "=r"(r[0]), "=r"(r[1]), "=r"(r[2]), "=r"(r[3]) : "r"(addr));
}
__device__ __forceinline__ void mma16816(float* d, const uint32_t* a, uint32_t b0, uint32_t b1) {
    asm volatile("mma.sync.aligned.m16n8k16.row.col.f32.bf16.bf16.f32 "
                 "{%0,%1,%2,%3}, {%4,%5,%6,%7}, {%8,%9}, {%0,%1,%2,%3};"
                 : "+f"(d[0]), "+f"(d[1]), "+f"(d[2]), "+f"(d[3])
                 : "r"(a[0]), "r"(a[1]), "r"(a[2]), "r"(a[3]), "r"(b0), "r"(b1));
}
#define SWZ(o) ((o) ^ (((o) >> 3) & 0x70))
#define CP16(dst, src) asm volatile("cp.async.cg.shared.global [%0], [%1], 16;" :: "r"(dst), "l"(src))
#define CP_COMMIT()    asm volatile("cp.async.commit_group;" ::: "memory")
#define CP_WAIT1()     asm volatile("cp.async.wait_group 1;" ::: "memory")

// softplus/exp prep shared by dt epilogue
__device__ __forceinline__ void ssm_prep1(float accv, int r, int c, float Bsv)
{
    float dtv   = accv;
    float delta = (dtv > 20.f) ? dtv : log1pf(expf(dtv));
    float dA    = expf(delta * g_A[c]);
    float u     = g_xc[(size_t)r * DI + c];
    g_dt [(size_t)r * DI + c] = dA;
    g_dbu[(size_t)r * DI + c] = delta * Bsv * u;
}

// ============ HMMA split GEMM v4 ============
// C[M,N] = A[M,K] @ B[N,K]^T, fp32 pre-split bf16 hi/lo, 3-term accumulate.
// grid (N/128, M/128), 128 threads (4 warps 2x2, 64x64 warp tiles), BK=32.
// ONE barrier per chunk: the post-wait barrier of iteration kt+1 already orders
// "all warps finished reading stage kt" before the load overwriting it (kt+3).
// MODE 0: plain.  MODE 1: ragged-N stores + bf16 split of cols<64 (x_dbl).
// MODE 2: fused SSM prep epilogue (dt GEMM).
#define STG_B  32768
template<int MODE>
__global__ void __launch_bounds__(128)
mma_gemm(const __nv_bfloat16* __restrict__ Ahi, const __nv_bfloat16* __restrict__ Alo,
         const __nv_bfloat16* __restrict__ Bhi, const __nv_bfloat16* __restrict__ Blo,
         float* __restrict__ C, int ldc, int K, int nvalid,
         const float* __restrict__ dtb)
{
    extern __shared__ __align__(1024) char dynsm[];
    const uint32_t sb = smem_u32(dynsm);

    const int tid  = threadIdx.x;
    const int lane = tid & 31;
    const int wid  = tid >> 5;
    const int wm   = wid & 1;
    const int wn   = wid >> 1;
    const int m0   = blockIdx.y * 128;
    const int n0   = blockIdx.x * 128;

    float acc[4][8][4];
#pragma unroll
    for (int m = 0; m < 4; m++)
#pragma unroll
        for (int n = 0; n < 8; n++)
#pragma unroll
            for (int v = 0; v < 4; v++) acc[m][n][v] = 0.f;

    const int a_row = lane & 15;
    const int b_row = (lane & 7) + ((lane >> 3) & 1) * 8;
    const int cb    = (lane >> 4) * 16;

    uint32_t aoff[2][4], boff[2][4];
#pragma unroll
    for (int ks = 0; ks < 2; ks++) {
#pragma unroll
        for (int m = 0; m < 4; m++)
            aoff[ks][m] = SWZ((uint32_t)(wm * 64 + m * 16 + a_row) * 128 + ks * 32 + cb);
#pragma unroll
        for (int p = 0; p < 4; p++)
            boff[ks][p] = 16384u + SWZ((uint32_t)(wn * 64 + p * 16 + b_row) * 128 + ks * 32 + cb);
    }

#define LOAD_STAGE(s, koff) do {                                               \
    const uint32_t sdst = sb + (s) * STG_B;                                    \
    _Pragma("unroll")                                                          \
    for (int it = 0; it < 16; it++) {                                          \
        int i = tid + it * 128;                                                \
        int arr = i >> 10;                                                     \
        int j = i & 1023;                                                      \
        int row = j >> 3;                                                      \
        int half = (j >> 2) & 1, c = j & 3;                                    \
        const __nv_bfloat16* g = arr ? (half ? Blo : Bhi) : (half ? Alo : Ahi);\
        int rb = arr ? n0 : m0;                                                \
        const void* gp = g + (size_t)(rb + row) * K + (koff) + c * 8;          \
        uint32_t d = sdst + arr * 16384 + SWZ(row * 128 + half * 64 + c * 16); \
        CP16(d, gp);                                                           \
    }                                                                          \
    CP_COMMIT();                                                               \
} while (0)

    LOAD_STAGE(0, 0);
    LOAD_STAGE(1, 32);

    const int NK = K / 32;
    for (int kt = 0; kt < NK; kt++) {
        CP_WAIT1();
        __syncthreads();   // (a) all warps' stage-kt data landed; (b) all warps
                           // finished reading stage kt-1 (== the one kt+2 refills)
        if (kt + 2 < NK) LOAD_STAGE((kt + 2) % 3, (kt + 2) * 32);
        else             CP_COMMIT();   // empty group keeps the wait invariant

        const uint32_t stg = sb + (kt % 3) * STG_B;
#pragma unroll
        for (int ks = 0; ks < 2; ks++) {
            uint32_t bh[4][4], bl[4][4];
#pragma unroll
            for (int p = 0; p < 4; p++) {
                uint32_t ba = stg + boff[ks][p];
                ldsm4(bh[p], ba);
                ldsm4(bl[p], ba ^ 64u);
            }
            uint32_t ah[2][4], al[2][4];
            {
                uint32_t aa = stg + aoff[ks][0];
                ldsm4(ah[0], aa);
                ldsm4(al[0], aa ^ 64u);
            }
#pragma unroll
            for (int m = 0; m < 4; m++) {
                const int cur = m & 1;
                if (m < 3) {
                    uint32_t aa = stg + aoff[ks][m + 1];
                    ldsm4(ah[cur ^ 1], aa);
                    ldsm4(al[cur ^ 1], aa ^ 64u);
                }
#pragma unroll
                for (int n = 0; n < 8; n++) {
                    const int p = n >> 1, q = n & 1;
                    mma16816(acc[m][n], ah[cur], bh[p][q], bh[p][q + 2]);
                    mma16816(acc[m][n], ah[cur], bl[p][q], bl[p][q + 2]);
                    mma16816(acc[m][n], al[cur], bh[p][q], bh[p][q + 2]);
                }
            }
        }
    }

    // ---- epilogue ----
#pragma unroll
    for (int m = 0; m < 4; m++) {
        const int row = m0 + wm * 64 + m * 16 + (lane >> 2);
        float Bsv0, Bsv1;
        if constexpr (MODE == 2) {
            Bsv0 = g_xdbl[(size_t)row * RPAD + DTR];
            Bsv1 = g_xdbl[(size_t)(row + 8) * RPAD + DTR];
        }
#pragma unroll
        for (int n = 0; n < 8; n++) {
            const int col = n0 + wn * 64 + n * 8 + (lane & 3) * 2;
            if constexpr (MODE == 0) {
                *(float2*)(C + (size_t)row * ldc + col)       = make_float2(acc[m][n][0], acc[m][n][1]);
                *(float2*)(C + (size_t)(row + 8) * ldc + col) = make_float2(acc[m][n][2], acc[m][n][3]);
            } else if constexpr (MODE == 1) {
                if (col + 2 <= nvalid) {
                    *(float2*)(C + (size_t)row * ldc + col)       = make_float2(acc[m][n][0], acc[m][n][1]);
                    *(float2*)(C + (size_t)(row + 8) * ldc + col) = make_float2(acc[m][n][2], acc[m][n][3]);
                }
                if (col + 2 <= DTR) {   // dts bf16 split for the HMMA dt GEMM
#pragma unroll
                    for (int h = 0; h < 2; h++) {
                        int r = row + h * 8;
                        float v0 = acc[m][n][h * 2], v1 = acc[m][n][h * 2 + 1];
                        __nv_bfloat16 h0 = __float2bfloat16(v0), h1 = __float2bfloat16(v1);
                        *(__nv_bfloat162*)(g_dshi + (size_t)r * DTR + col) = __nv_bfloat162(h0, h1);
                        *(__nv_bfloat162*)(g_dslo + (size_t)r * DTR + col) =
                            __nv_bfloat162(__float2bfloat16(v0 - __bfloat162float(h0)),
                                           __float2bfloat16(v1 - __bfloat162float(h1)));
                    }
                }
            } else {                    // MODE 2: fused SSM prep
                float b0 = dtb[col], b1 = dtb[col + 1];
                ssm_prep1(acc[m][n][0] + b0, row,     col,     Bsv0);
                ssm_prep1(acc[m][n][1] + b1, row,     col + 1, Bsv0);
                ssm_prep1(acc[m][n][2] + b0, row + 8, col,     Bsv1);
                ssm_prep1(acc[m][n][3] + b1, row + 8, col + 1, Bsv1);
            }
        }
    }
}

// ================= combined fp32 -> bf16 hi/lo split =================
__device__ __forceinline__ void split4(float4 v, __nv_bfloat16* hi, __nv_bfloat16* lo, int i)
{
    __nv_bfloat16 h0 = __float2bfloat16(v.x), h1 = __float2bfloat16(v.y);
    __nv_bfloat16 h2 = __float2bfloat16(v.z), h3 = __float2bfloat16(v.w);
    __nv_bfloat162* H = (__nv_bfloat162*)hi;
    __nv_bfloat162* L = (__nv_bfloat162*)lo;
    H[i*2+0] = __nv_bfloat162(h0, h1);
    H[i*2+1] = __nv_bfloat162(h2, h3);
    L[i*2+0] = __nv_bfloat162(__float2bfloat16(v.x - __bfloat162float(h0)),
                              __float2bfloat16(v.y - __bfloat162float(h1)));
    L[i*2+1] = __nv_bfloat162(__float2bfloat16(v.z - __bfloat162float(h2)),
                              __float2bfloat16(v.w - __bfloat162float(h3)));
}

#define N4_X  (NTOK * DM / 4)
#define N4_W1 (2 * DI * DM / 4)
#define N4_WO (DM * DI / 4)
#define N4_XP (RTOT * DI / 4)
#define N4_DW (DI * DTR / 4)
#define N4_ALL (N4_X + N4_W1 + N4_WO + N4_XP + N4_DW)

__global__ void split_all_kernel(const float* __restrict__ x, const float* __restrict__ w1,
                                 const float* __restrict__ wo, const float* __restrict__ xp,
                                 const float* __restrict__ dw)
{
    int i = blockIdx.x * blockDim.x + threadIdx.x;
    if (i < N4_X) { split4(((const float4*)x)[i], g_xhi, g_xlo, i); return; }
    i -= N4_X;
    if (i < N4_W1) { split4(((const float4*)w1)[i], g_w1hi, g_w1lo, i); return; }
    i -= N4_W1;
    if (i < N4_WO) { split4(((const float4*)wo)[i], g_wohi, g_wolo, i); return; }
    i -= N4_WO;
    if (i < N4_XP) { split4(((const float4*)xp)[i], g_xphi, g_xplo, i); return; }
    i -= N4_XP;
    if (i < N4_DW) { split4(((const float4*)dw)[i], g_dwhi, g_dwlo, i); }
}

// ---------------- depthwise conv (k=2) + SiLU, emits fp32 + bf16 hi/lo ----------------
__global__ void conv_silu_kernel(const float* __restrict__ cw, const float* __restrict__ cb)
{
    int idx = blockIdx.x * blockDim.x + threadIdx.x;
    if (idx >= NTOK * DI) return;
    int d = idx & (DI - 1);
    int tok = idx >> 10;
    int l = tok & (LL - 1);
    float cur  = g_xz[(size_t)tok * (2 * DI) + d];
    float prev = (l > 0) ? g_xz[(size_t)(tok - 1) * (2 * DI) + d] : 0.f;
    float v = fmaf(cw[2 * d], prev, fmaf(cw[2 * d + 1], cur, cb[d]));
    float s = v / (1.f + expf(-v));
    g_xc[idx] = s;
    __nv_bfloat16 h = __float2bfloat16(s);
    g_xchi[idx] = h;
    g_xclo[idx] = __float2bfloat16(s - __bfloat162float(h));
}

__global__ void precomp_A_kernel(const float* __restrict__ Alogs)
{
    int d = blockIdx.x * blockDim.x + threadIdx.x;
    if (d < DI) g_A[d] = -expf(Alogs[d]);
}

// ---------------- chunked scan ----------------
__global__ void scan_pass1_kernel()
{
    int t = blockIdx.x * blockDim.x + threadIdx.x;
    if (t >= BB * NCH * DI) return;
    int d = t & (DI - 1);
    int c = (t >> 10) & (NCH - 1);
    int b = t >> 13;
    size_t base = ((size_t)b * LL + (size_t)c * CH) * DI + d;
    float aprod = 1.f, h = 0.f;
#pragma unroll 4
    for (int l = 0; l < CH; l++) {
        float a  = g_dt [base + (size_t)l * DI];
        float bu = g_dbu[base + (size_t)l * DI];
        h = fmaf(a, h, bu);
        aprod *= a;
    }
    g_Ac[t] = aprod;
    g_Bc[t] = h;
}

__global__ void scan_pass2_kernel()
{
    int t = blockIdx.x * blockDim.x + threadIdx.x;
    if (t >= BB * DI) return;
    int d = t & (DI - 1);
    int b = t >> 10;
    float h = 0.f;
#pragma unroll
    for (int c = 0; c < NCH; c++) {
        int idx = ((b * NCH) + c) * DI + d;
        g_h0[idx] = h;
        h = fmaf(g_Ac[idx], h, g_Bc[idx]);
    }
}

__global__ void scan_pass3_kernel(const float* __restrict__ Ds)
{
    int t = blockIdx.x * blockDim.x + threadIdx.x;
    if (t >= BB * NCH * DI) return;
    int d = t & (DI - 1);
    int c = (t >> 10) & (NCH - 1);
    int b = t >> 13;
    float Dd = Ds[d];
    float h = g_h0[t];
    size_t tok0 = (size_t)b * LL + (size_t)c * CH;
    size_t base = tok0 * DI + d;
#pragma unroll 4
    for (int l = 0; l < CH; l++) {
        float a  = g_dt [base + (size_t)l * DI];
        float bu = g_dbu[base + (size_t)l * DI];
        float u  = g_xc [base + (size_t)l * DI];
        float Cs = g_xdbl[(tok0 + l) * RPAD + DTR + 1];
        h = fmaf(a, h, bu);
        g_y[base + (size_t)l * DI] = fmaf(h, Cs, u * Dd);
    }
}

// ---------------- LayerNorm + SiLU gate, fused bf16 split output ----------------
__global__ void __launch_bounds__(256) ln_gate_kernel(const float* __restrict__ lnw,
                                                      const float* __restrict__ lnb)
{
    int tok = blockIdx.x;
    int tid = threadIdx.x;
    size_t base = (size_t)tok * DI;

    float v[4];
    float s = 0.f, q = 0.f;
#pragma unroll
    for (int i = 0; i < 4; i++) {
        float x = g_y[base + tid + i * 256];
        v[i] = x; s += x; q += x * x;
    }
#pragma unroll
    for (int o = 16; o; o >>= 1) {
        s += __shfl_xor_sync(0xffffffffu, s, o);
        q += __shfl_xor_sync(0xffffffffu, q, o);
    }
    __shared__ float ss[8], sq[8];
    if ((tid & 31) == 0) { ss[tid >> 5] = s; sq[tid >> 5] = q; }
    __syncthreads();
    float S = 0.f, Q = 0.f;
#pragma unroll
    for (int w = 0; w < 8; w++) { S += ss[w]; Q += sq[w]; }

    float mu  = S * (1.f / DI);
    float var = Q * (1.f / DI) - mu * mu;
    float rs  = rsqrtf(var + 1e-5f);
#pragma unroll
    for (int i = 0; i < 4; i++) {
        int d = tid + i * 256;
        float z  = g_xz[(size_t)tok * (2 * DI) + DI + d];
        float gt = z / (1.f + expf(-z));
        float val = fmaf((v[i] - mu) * rs, lnw[d], lnb[d]) * gt;
        __nv_bfloat16 h = __float2bfloat16(val);
        g_yhi[base + d] = h;
        g_ylo[base + d] = __float2bfloat16(val - __bfloat162float(h));
    }
}

// ---------------- launch ----------------
extern "C" void kernel_launch(void* const* d_in, const int* in_sizes, int n_in,
                              void* d_out, int out_size)
{
    const float* x      = (const float*)d_in[0];
    const float* w_in   = (const float*)d_in[1];
    const float* conv_w = (const float*)d_in[2];
    const float* conv_b = (const float*)d_in[3];
    const float* xproj  = (const float*)d_in[4];
    const float* dtw    = (const float*)d_in[5];
    const float* dtb    = (const float*)d_in[6];
    const float* Alogs  = (const float*)d_in[7];
    const float* Ds     = (const float*)d_in[8];
    const float* lnw    = (const float*)d_in[9];
    const float* lnb    = (const float*)d_in[10];
    const float* wout   = (const float*)d_in[11];
    float* out = (float*)d_out;

    float *xz, *xdbl, *dtf;
    __nv_bfloat16 *xhi, *xlo, *w1hi, *w1lo, *yhi, *ylo, *wohi, *wolo;
    __nv_bfloat16 *xchi, *xclo, *xphi, *xplo, *dshi, *dslo, *dwhi, *dwlo;
    cudaGetSymbolAddress((void**)&xz,   g_xz);
    cudaGetSymbolAddress((void**)&xdbl, g_xdbl);
    cudaGetSymbolAddress((void**)&dtf,  g_dt);
    cudaGetSymbolAddress((void**)&xhi,  g_xhi);
    cudaGetSymbolAddress((void**)&xlo,  g_xlo);
    cudaGetSymbolAddress((void**)&w1hi, g_w1hi);
    cudaGetSymbolAddress((void**)&w1lo, g_w1lo);
    cudaGetSymbolAddress((void**)&yhi,  g_yhi);
    cudaGetSymbolAddress((void**)&ylo,  g_ylo);
    cudaGetSymbolAddress((void**)&wohi, g_wohi);
    cudaGetSymbolAddress((void**)&wolo, g_wolo);
    cudaGetSymbolAddress((void**)&xchi, g_xchi);
    cudaGetSymbolAddress((void**)&xclo, g_xclo);
    cudaGetSymbolAddress((void**)&xphi, g_xphi);
    cudaGetSymbolAddress((void**)&xplo, g_xplo);
    cudaGetSymbolAddress((void**)&dshi, g_dshi);
    cudaGetSymbolAddress((void**)&dslo, g_dslo);
    cudaGetSymbolAddress((void**)&dwhi, g_dwhi);
    cudaGetSymbolAddress((void**)&dwlo, g_dwlo);

    const int SMEM_MMA = 3 * STG_B;   // 98304 bytes, 2 CTAs/SM
    cudaFuncSetAttribute(mma_gemm<0>, cudaFuncAttributeMaxDynamicSharedMemorySize, SMEM_MMA);
    cudaFuncSetAttribute(mma_gemm<1>, cudaFuncAttributeMaxDynamicSharedMemorySize, SMEM_MMA);
    cudaFuncSetAttribute(mma_gemm<2>, cudaFuncAttributeMaxDynamicSharedMemorySize, SMEM_MMA);

    const int EW_BLOCKS = (NTOK * DI + 255) / 256;

    // 0) all fp32 -> bf16 hi/lo splits in one kernel
    split_all_kernel<<<(N4_ALL + 255) / 256, 256>>>(x, w_in, wout, xproj, dtw);

    // 1) xz = x @ w_in^T  (HMMA)
    mma_gemm<0><<<dim3(2 * DI / 128, NTOK / 128), 128, SMEM_MMA>>>(
        xhi, xlo, w1hi, w1lo, xz, 2 * DI, DM, 0, nullptr);

    // 2) depthwise conv + silu  (fp32 + bf16 split outputs)
    conv_silu_kernel<<<EW_BLOCKS, 256>>>(conv_w, conv_b);

    // 3) x_dbl = xc @ xproj^T  (HMMA, ragged nvalid=66, dts bf16 split emitted)
    mma_gemm<1><<<dim3(1, NTOK / 128), 128, SMEM_MMA>>>(
        xchi, xclo, xphi, xplo, xdbl, RPAD, DI, RTOT, nullptr);

    // 4) A = -exp(A_logs)  (needed by dt epilogue)
    precomp_A_kernel<<<4, 256>>>(Alogs);

    // 5) dt GEMM (HMMA, K=64) + fused SSM prep epilogue -> g_dt, g_dbu
    mma_gemm<2><<<dim3(DI / 128, NTOK / 128), 128, SMEM_MMA>>>(
        dshi, dslo, dwhi, dwlo, dtf, DI, DTR, DI, dtb);

    // 6) chunked scan
    scan_pass1_kernel<<<(BB * NCH * DI + 255) / 256, 256>>>();
    scan_pass2_kernel<<<(BB * DI + 255) / 256, 256>>>();
    scan_pass3_kernel<<<(BB * NCH * DI + 255) / 256, 256>>>(Ds);

    // 7) LayerNorm + gate, emits bf16 hi/lo
    ln_gate_kernel<<<NTOK, 256>>>(lnw, lnb);

    // 8) out = yln @ w_out^T  (HMMA)
    mma_gemm<0><<<dim3(DI / 128, NTOK / 128), 128, SMEM_MMA>>>(
        yhi, ylo, wohi, wolo, out, DM, DI, 0, nullptr);
}

// round 11
// speedup vs baseline: 3.3177x; 1.0153x over previous
#include <cuda_runtime.h>
#include <cuda_bf16.h>
#include <math.h>
#include <stdint.h>

#define BB   4
#define LL   4096
#define DM   1024
#define DI   1024
#define DTR  64
#define RTOT 66
#define RPAD 68
#define NTOK (BB*LL)     // 16384
#define CH   512
#define NCH  (LL/CH)

// ---------------- scratch ----------------
__device__ __align__(16) float g_xz  [(size_t)NTOK * 2 * DI];
__device__ __align__(16) float g_xc  [(size_t)NTOK * DI];
__device__ __align__(16) float g_xdbl[(size_t)NTOK * RPAD];
__device__ __align__(16) float g_dt  [(size_t)NTOK * DI];
__device__ __align__(16) float g_dbu [(size_t)NTOK * DI];
__device__ __align__(16) float g_y   [(size_t)NTOK * DI];
__device__ __align__(16) float g_A   [DI];
__device__ __align__(16) float g_Ac  [BB * NCH * DI];
__device__ __align__(16) float g_Bc  [BB * NCH * DI];
// bf16 split buffers
__device__ __align__(16) __nv_bfloat16 g_xhi [(size_t)NTOK * DM];
__device__ __align__(16) __nv_bfloat16 g_xlo [(size_t)NTOK * DM];
__device__ __align__(16) __nv_bfloat16 g_w1hi[(size_t)2 * DI * DM];
__device__ __align__(16) __nv_bfloat16 g_w1lo[(size_t)2 * DI * DM];
__device__ __align__(16) __nv_bfloat16 g_yhi [(size_t)NTOK * DI];
__device__ __align__(16) __nv_bfloat16 g_ylo [(size_t)NTOK * DI];
__device__ __align__(16) __nv_bfloat16 g_wohi[(size_t)DM * DI];
__device__ __align__(16) __nv_bfloat16 g_wolo[(size_t)DM * DI];
// xc bf16 split (for HMMA x_dbl)
__device__ __align__(16) __nv_bfloat16 g_xchi[(size_t)NTOK * DI];
__device__ __align__(16) __nv_bfloat16 g_xclo[(size_t)NTOK * DI];
// x_proj split, zero-padded to 128 rows
__device__ __align__(16) __nv_bfloat16 g_xphi[(size_t)128 * DI];
__device__ __align__(16) __nv_bfloat16 g_xplo[(size_t)128 * DI];
// dts split [NTOK x 64]
__device__ __align__(16) __nv_bfloat16 g_dshi[(size_t)NTOK * DTR];
__device__ __align__(16) __nv_bfloat16 g_dslo[(size_t)NTOK * DTR];
// dt_projs_weight split [1024 x 64]
__device__ __align__(16) __nv_bfloat16 g_dwhi[(size_t)DI * DTR];
__device__ __align__(16) __nv_bfloat16 g_dwlo[(size_t)DI * DTR];

// ================= helpers =================
__device__ __forceinline__ uint32_t smem_u32(const void* p) {
    uint32_t a;
    asm("{ .reg .u64 t; cvta.to.shared.u64 t, %1; cvt.u32.u64 %0, t; }" : "=r"(a) : "l"(p));
    return a;
}
__device__ __forceinline__ void ldsm4(uint32_t* r, uint32_t addr) {
    asm volatile("ldmatrix.sync.aligned.m8n8.x4.shared.b16 {%0,%1,%2,%3}, [%4];"
                 : "=r"(r[0]), "=r"(r[1]), "=r"(r[2]), "=r"(r[3]) : "r"(addr));
}
__device__ __forceinline__ void mma16816(float* d, const uint32_t* a, uint32_t b0, uint32_t b1) {
    asm volatile("mma.sync.aligned.m16n8k16.row.col.f32.bf16.bf16.f32 "
                 "{%0,%1,%2,%3}, {%4,%5,%6,%7}, {%8,%9}, {%0,%1,%2,%3};"
                 : "+f"(d[0]), "+f"(d[1]), "+f"(d[2]), "+f"(d[3])
                 : "r"(a[0]), "r"(a[1]), "r"(a[2]), "r"(a[3]), "r"(b0), "r"(b1));
}
#define SWZ(o) ((o) ^ (((o) >> 3) & 0x70))
#define CP16(dst, src) asm volatile("cp.async.cg.shared.global [%0], [%1], 16;" :: "r"(dst), "l"(src))
#define CP_COMMIT()    asm volatile("cp.async.commit_group;" ::: "memory")
#define CP_WAIT1()     asm volatile("cp.async.wait_group 1;" ::: "memory")

// fast silu: one-shot precision (~1e-6 rel), 2 MUFU, minimal issue cost
__device__ __forceinline__ float silu_fast(float v) {
    return __fdividef(v, 1.f + __expf(-v));
}

// dt epilogue prep. Compounding-error-sensitive parts kept careful:
// delta's ABS error multiplies into the scan exponent -> precise log1pf.
// __expf per-factor log error ~2^-21 random -> sqrt(window)*eps ~1e-5 total. OK.
__device__ __forceinline__ void ssm_prep1(float dtv, int r, int c, float Bsv)
{
    float t     = __expf(dtv);
    float delta = (dtv > 15.f) ? dtv : log1pf(t);
    float dA    = __expf(delta * g_A[c]);
    float u     = g_xc[(size_t)r * DI + c];
    g_dt [(size_t)r * DI + c] = dA;
    g_dbu[(size_t)r * DI + c] = delta * Bsv * u;
}

// ============ HMMA split GEMM v4 ============
// MODE 0: plain. MODE 1: ragged-N + dts bf16 split. MODE 2: fused SSM prep.
#define STG_B  32768
template<int MODE>
__global__ void __launch_bounds__(128)
mma_gemm(const __nv_bfloat16* __restrict__ Ahi, const __nv_bfloat16* __restrict__ Alo,
         const __nv_bfloat16* __restrict__ Bhi, const __nv_bfloat16* __restrict__ Blo,
         float* __restrict__ C, int ldc, int K, int nvalid,
         const float* __restrict__ dtb)
{
    extern __shared__ __align__(1024) char dynsm[];
    const uint32_t sb = smem_u32(dynsm);

    const int tid  = threadIdx.x;
    const int lane = tid & 31;
    const int wid  = tid >> 5;
    const int wm   = wid & 1;
    const int wn   = wid >> 1;
    const int m0   = blockIdx.y * 128;
    const int n0   = blockIdx.x * 128;

    float acc[4][8][4];
#pragma unroll
    for (int m = 0; m < 4; m++)
#pragma unroll
        for (int n = 0; n < 8; n++)
#pragma unroll
            for (int v = 0; v < 4; v++) acc[m][n][v] = 0.f;

    const int a_row = lane & 15;
    const int b_row = (lane & 7) + ((lane >> 3) & 1) * 8;
    const int cb    = (lane >> 4) * 16;

    uint32_t aoff[2][4], boff[2][4];
#pragma unroll
    for (int ks = 0; ks < 2; ks++) {
#pragma unroll
        for (int m = 0; m < 4; m++)
            aoff[ks][m] = SWZ((uint32_t)(wm * 64 + m * 16 + a_row) * 128 + ks * 32 + cb);
#pragma unroll
        for (int p = 0; p < 4; p++)
            boff[ks][p] = 16384u + SWZ((uint32_t)(wn * 64 + p * 16 + b_row) * 128 + ks * 32 + cb);
    }

#define LOAD_STAGE(s, koff) do {                                               \
    const uint32_t sdst = sb + (s) * STG_B;                                    \
    _Pragma("unroll")                                                          \
    for (int it = 0; it < 16; it++) {                                          \
        int i = tid + it * 128;                                                \
        int arr = i >> 10;                                                     \
        int j = i & 1023;                                                      \
        int row = j >> 3;                                                      \
        int half = (j >> 2) & 1, c = j & 3;                                    \
        const __nv_bfloat16* g = arr ? (half ? Blo : Bhi) : (half ? Alo : Ahi);\
        int rb = arr ? n0 : m0;                                                \
        const void* gp = g + (size_t)(rb + row) * K + (koff) + c * 8;          \
        uint32_t d = sdst + arr * 16384 + SWZ(row * 128 + half * 64 + c * 16); \
        CP16(d, gp);                                                           \
    }                                                                          \
    CP_COMMIT();                                                               \
} while (0)

    LOAD_STAGE(0, 0);
    LOAD_STAGE(1, 32);

    const int NK = K / 32;
    for (int kt = 0; kt < NK; kt++) {
        CP_WAIT1();
        __syncthreads();
        if (kt + 2 < NK) LOAD_STAGE((kt + 2) % 3, (kt + 2) * 32);
        else             CP_COMMIT();   // empty group keeps the wait invariant

        const uint32_t stg = sb + (kt % 3) * STG_B;
#pragma unroll
        for (int ks = 0; ks < 2; ks++) {
            uint32_t bh[4][4], bl[4][4];
#pragma unroll
            for (int p = 0; p < 4; p++) {
                uint32_t ba = stg + boff[ks][p];
                ldsm4(bh[p], ba);
                ldsm4(bl[p], ba ^ 64u);
            }
            uint32_t ah[2][4], al[2][4];
            {
                uint32_t aa = stg + aoff[ks][0];
                ldsm4(ah[0], aa);
                ldsm4(al[0], aa ^ 64u);
            }
#pragma unroll
            for (int m = 0; m < 4; m++) {
                const int cur = m & 1;
                if (m < 3) {
                    uint32_t aa = stg + aoff[ks][m + 1];
                    ldsm4(ah[cur ^ 1], aa);
                    ldsm4(al[cur ^ 1], aa ^ 64u);
                }
#pragma unroll
                for (int n = 0; n < 8; n++) {
                    const int p = n >> 1, q = n & 1;
                    mma16816(acc[m][n], ah[cur], bh[p][q], bh[p][q + 2]);
                    mma16816(acc[m][n], ah[cur], bl[p][q], bl[p][q + 2]);
                    mma16816(acc[m][n], al[cur], bh[p][q], bh[p][q + 2]);
                }
            }
        }
    }

    // ---- epilogue ----
#pragma unroll
    for (int m = 0; m < 4; m++) {
        const int row = m0 + wm * 64 + m * 16 + (lane >> 2);
        float Bsv0, Bsv1;
        if constexpr (MODE == 2) {
            Bsv0 = g_xdbl[(size_t)row * RPAD + DTR];
            Bsv1 = g_xdbl[(size_t)(row + 8) * RPAD + DTR];
        }
#pragma unroll
        for (int n = 0; n < 8; n++) {
            const int col = n0 + wn * 64 + n * 8 + (lane & 3) * 2;
            if constexpr (MODE == 0) {
                *(float2*)(C + (size_t)row * ldc + col)       = make_float2(acc[m][n][0], acc[m][n][1]);
                *(float2*)(C + (size_t)(row + 8) * ldc + col) = make_float2(acc[m][n][2], acc[m][n][3]);
            } else if constexpr (MODE == 1) {
                if (col + 2 <= nvalid) {
                    *(float2*)(C + (size_t)row * ldc + col)       = make_float2(acc[m][n][0], acc[m][n][1]);
                    *(float2*)(C + (size_t)(row + 8) * ldc + col) = make_float2(acc[m][n][2], acc[m][n][3]);
                }
                if (col + 2 <= DTR) {
#pragma unroll
                    for (int h = 0; h < 2; h++) {
                        int r = row + h * 8;
                        float v0 = acc[m][n][h * 2], v1 = acc[m][n][h * 2 + 1];
                        __nv_bfloat16 h0 = __float2bfloat16(v0), h1 = __float2bfloat16(v1);
                        *(__nv_bfloat162*)(g_dshi + (size_t)r * DTR + col) = __nv_bfloat162(h0, h1);
                        *(__nv_bfloat162*)(g_dslo + (size_t)r * DTR + col) =
                            __nv_bfloat162(__float2bfloat16(v0 - __bfloat162float(h0)),
                                           __float2bfloat16(v1 - __bfloat162float(h1)));
                    }
                }
            } else {                    // MODE 2: fused SSM prep
                float b0 = dtb[col], b1 = dtb[col + 1];
                ssm_prep1(acc[m][n][0] + b0, row,     col,     Bsv0);
                ssm_prep1(acc[m][n][1] + b1, row,     col + 1, Bsv0);
                ssm_prep1(acc[m][n][2] + b0, row + 8, col,     Bsv1);
                ssm_prep1(acc[m][n][3] + b1, row + 8, col + 1, Bsv1);
            }
        }
    }
}

// ================= combined fp32 -> bf16 hi/lo split (+ A precompute) =================
__device__ __forceinline__ void split4(float4 v, __nv_bfloat16* hi, __nv_bfloat16* lo, int i)
{
    __nv_bfloat16 h0 = __float2bfloat16(v.x), h1 = __float2bfloat16(v.y);
    __nv_bfloat16 h2 = __float2bfloat16(v.z), h3 = __float2bfloat16(v.w);
    __nv_bfloat162* H = (__nv_bfloat162*)hi;
    __nv_bfloat162* L = (__nv_bfloat162*)lo;
    H[i*2+0] = __nv_bfloat162(h0, h1);
    H[i*2+1] = __nv_bfloat162(h2, h3);
    L[i*2+0] = __nv_bfloat162(__float2bfloat16(v.x - __bfloat162float(h0)),
                              __float2bfloat16(v.y - __bfloat162float(h1)));
    L[i*2+1] = __nv_bfloat162(__float2bfloat16(v.z - __bfloat162float(h2)),
                              __float2bfloat16(v.w - __bfloat162float(h3)));
}

#define N4_X  (NTOK * DM / 4)
#define N4_W1 (2 * DI * DM / 4)
#define N4_WO (DM * DI / 4)
#define N4_XP (RTOT * DI / 4)
#define N4_DW (DI * DTR / 4)
#define N4_A  (DI / 4)
#define N4_ALL (N4_X + N4_W1 + N4_WO + N4_XP + N4_DW + N4_A)

__global__ void split_all_kernel(const float* __restrict__ x, const float* __restrict__ w1,
                                 const float* __restrict__ wo, const float* __restrict__ xp,
                                 const float* __restrict__ dw, const float* __restrict__ Alogs)
{
    int i = blockIdx.x * blockDim.x + threadIdx.x;
    if (i < N4_X) { split4(((const float4*)x)[i], g_xhi, g_xlo, i); return; }
    i -= N4_X;
    if (i < N4_W1) { split4(((const float4*)w1)[i], g_w1hi, g_w1lo, i); return; }
    i -= N4_W1;
    if (i < N4_WO) { split4(((const float4*)wo)[i], g_wohi, g_wolo, i); return; }
    i -= N4_WO;
    if (i < N4_XP) { split4(((const float4*)xp)[i], g_xphi, g_xplo, i); return; }
    i -= N4_XP;
    if (i < N4_DW) { split4(((const float4*)dw)[i], g_dwhi, g_dwlo, i); return; }
    i -= N4_DW;
    if (i < N4_A) {
        float4 a = ((const float4*)Alogs)[i];
        g_A[i*4+0] = -expf(a.x); g_A[i*4+1] = -expf(a.y);
        g_A[i*4+2] = -expf(a.z); g_A[i*4+3] = -expf(a.w);
    }
}

// ---------------- depthwise conv (k=2) + SiLU, vectorized x4 ----------------
__global__ void conv_silu_kernel(const float* __restrict__ cw, const float* __restrict__ cb)
{
    int idx = blockIdx.x * blockDim.x + threadIdx.x;   // over NTOK*DI/4
    if (idx >= NTOK * DI / 4) return;
    int d4  = idx & (DI / 4 - 1);
    int tok = idx >> 8;
    int l   = tok & (LL - 1);
    int d   = d4 * 4;

    float4 cur  = *(const float4*)(g_xz + (size_t)tok * (2 * DI) + d);
    float4 prev = make_float4(0.f, 0.f, 0.f, 0.f);
    if (l > 0) prev = *(const float4*)(g_xz + (size_t)(tok - 1) * (2 * DI) + d);
    float4 w0 = *(const float4*)(cw + 2 * d);       // [w(d,0) w(d,1) w(d+1,0) w(d+1,1)]
    float4 w1 = *(const float4*)(cw + 2 * d + 4);
    float4 b  = *(const float4*)(cb + d);

    float s0 = silu_fast(fmaf(w0.x, prev.x, fmaf(w0.y, cur.x, b.x)));
    float s1 = silu_fast(fmaf(w0.z, prev.y, fmaf(w0.w, cur.y, b.y)));
    float s2 = silu_fast(fmaf(w1.x, prev.z, fmaf(w1.y, cur.z, b.z)));
    float s3 = silu_fast(fmaf(w1.z, prev.w, fmaf(w1.w, cur.w, b.w)));

    *(float4*)(g_xc + (size_t)tok * DI + d) = make_float4(s0, s1, s2, s3);

    __nv_bfloat16 h0 = __float2bfloat16(s0), h1 = __float2bfloat16(s1);
    __nv_bfloat16 h2 = __float2bfloat16(s2), h3 = __float2bfloat16(s3);
    __nv_bfloat162* H = (__nv_bfloat162*)(g_xchi + (size_t)tok * DI + d);
    __nv_bfloat162* L = (__nv_bfloat162*)(g_xclo + (size_t)tok * DI + d);
    H[0] = __nv_bfloat162(h0, h1);
    H[1] = __nv_bfloat162(h2, h3);
    L[0] = __nv_bfloat162(__float2bfloat16(s0 - __bfloat162float(h0)),
                          __float2bfloat16(s1 - __bfloat162float(h1)));
    L[1] = __nv_bfloat162(__float2bfloat16(s2 - __bfloat162float(h2)),
                          __float2bfloat16(s3 - __bfloat162float(h3)));
}

// ---------------- chunked scan ----------------
__global__ void scan_pass1_kernel()
{
    int t = blockIdx.x * blockDim.x + threadIdx.x;
    if (t >= BB * NCH * DI) return;
    int d = t & (DI - 1);
    int c = (t >> 10) & (NCH - 1);
    int b = t >> 13;
    size_t base = ((size_t)b * LL + (size_t)c * CH) * DI + d;
    float aprod = 1.f, h = 0.f;
#pragma unroll 4
    for (int l = 0; l < CH; l++) {
        float a  = g_dt [base + (size_t)l * DI];
        float bu = g_dbu[base + (size_t)l * DI];
        h = fmaf(a, h, bu);
        aprod *= a;
    }
    g_Ac[t] = aprod;
    g_Bc[t] = h;
}

// pass 3 with inlined chunk-state chain (pass 2 eliminated)
__global__ void scan_pass3_kernel(const float* __restrict__ Ds)
{
    int t = blockIdx.x * blockDim.x + threadIdx.x;
    if (t >= BB * NCH * DI) return;
    int d = t & (DI - 1);
    int c = (t >> 10) & (NCH - 1);
    int b = t >> 13;
    float Dd = Ds[d];

    // entering state h0: chain previous chunks (<= 7 coalesced loads each)
    float h = 0.f;
    for (int j = 0; j < c; j++) {
        int idx = ((b * NCH) + j) * DI + d;
        h = fmaf(g_Ac[idx], h, g_Bc[idx]);
    }

    size_t tok0 = (size_t)b * LL + (size_t)c * CH;
    size_t base = tok0 * DI + d;
#pragma unroll 4
    for (int l = 0; l < CH; l++) {
        float a  = g_dt [base + (size_t)l * DI];
        float bu = g_dbu[base + (size_t)l * DI];
        float u  = g_xc [base + (size_t)l * DI];
        float Cs = g_xdbl[(tok0 + l) * RPAD + DTR + 1];
        h = fmaf(a, h, bu);
        g_y[base + (size_t)l * DI] = fmaf(h, Cs, u * Dd);
    }
}

// ---------------- LayerNorm + SiLU gate, fused bf16 split output ----------------
__global__ void __launch_bounds__(256) ln_gate_kernel(const float* __restrict__ lnw,
                                                      const float* __restrict__ lnb)
{
    int tok = blockIdx.x;
    int tid = threadIdx.x;
    size_t base = (size_t)tok * DI;

    float v[4];
    float s = 0.f, q = 0.f;
#pragma unroll
    for (int i = 0; i < 4; i++) {
        float x = g_y[base + tid + i * 256];
        v[i] = x; s += x; q += x * x;
    }
#pragma unroll
    for (int o = 16; o; o >>= 1) {
        s += __shfl_xor_sync(0xffffffffu, s, o);
        q += __shfl_xor_sync(0xffffffffu, q, o);
    }
    __shared__ float ss[8], sq[8];
    if ((tid & 31) == 0) { ss[tid >> 5] = s; sq[tid >> 5] = q; }
    __syncthreads();
    float S = 0.f, Q = 0.f;
#pragma unroll
    for (int w = 0; w < 8; w++) { S += ss[w]; Q += sq[w]; }

    float mu  = S * (1.f / DI);
    float var = Q * (1.f / DI) - mu * mu;
    float rs  = rsqrtf(var + 1e-5f);
#pragma unroll
    for (int i = 0; i < 4; i++) {
        int d = tid + i * 256;
        float z  = g_xz[(size_t)tok * (2 * DI) + DI + d];
        float gt = silu_fast(z);
        float val = fmaf((v[i] - mu) * rs, lnw[d], lnb[d]) * gt;
        __nv_bfloat16 h = __float2bfloat16(val);
        g_yhi[base + d] = h;
        g_ylo[base + d] = __float2bfloat16(val - __bfloat162float(h));
    }
}

// ---------------- launch ----------------
extern "C" void kernel_launch(void* const* d_in, const int* in_sizes, int n_in,
                              void* d_out, int out_size)
{
    const float* x      = (const float*)d_in[0];
    const float* w_in   = (const float*)d_in[1];
    const float* conv_w = (const float*)d_in[2];
    const float* conv_b = (const float*)d_in[3];
    const float* xproj  = (const float*)d_in[4];
    const float* dtw    = (const float*)d_in[5];
    const float* dtb    = (const float*)d_in[6];
    const float* Alogs  = (const float*)d_in[7];
    const float* Ds     = (const float*)d_in[8];
    const float* lnw    = (const float*)d_in[9];
    const float* lnb    = (const float*)d_in[10];
    const float* wout   = (const float*)d_in[11];
    float* out = (float*)d_out;

    float *xz, *xdbl, *dtf;
    __nv_bfloat16 *xhi, *xlo, *w1hi, *w1lo, *yhi, *ylo, *wohi, *wolo;
    __nv_bfloat16 *xchi, *xclo, *xphi, *xplo, *dshi, *dslo, *dwhi, *dwlo;
    cudaGetSymbolAddress((void**)&xz,   g_xz);
    cudaGetSymbolAddress((void**)&xdbl, g_xdbl);
    cudaGetSymbolAddress((void**)&dtf,  g_dt);
    cudaGetSymbolAddress((void**)&xhi,  g_xhi);
    cudaGetSymbolAddress((void**)&xlo,  g_xlo);
    cudaGetSymbolAddress((void**)&w1hi, g_w1hi);
    cudaGetSymbolAddress((void**)&w1lo, g_w1lo);
    cudaGetSymbolAddress((void**)&yhi,  g_yhi);
    cudaGetSymbolAddress((void**)&ylo,  g_ylo);
    cudaGetSymbolAddress((void**)&wohi, g_wohi);
    cudaGetSymbolAddress((void**)&wolo, g_wolo);
    cudaGetSymbolAddress((void**)&xchi, g_xchi);
    cudaGetSymbolAddress((void**)&xclo, g_xclo);
    cudaGetSymbolAddress((void**)&xphi, g_xphi);
    cudaGetSymbolAddress((void**)&xplo, g_xplo);
    cudaGetSymbolAddress((void**)&dshi, g_dshi);
    cudaGetSymbolAddress((void**)&dslo, g_dslo);
    cudaGetSymbolAddress((void**)&dwhi, g_dwhi);
    cudaGetSymbolAddress((void**)&dwlo, g_dwlo);

    const int SMEM_MMA = 3 * STG_B;   // 98304 bytes, 2 CTAs/SM
    cudaFuncSetAttribute(mma_gemm<0>, cudaFuncAttributeMaxDynamicSharedMemorySize, SMEM_MMA);
    cudaFuncSetAttribute(mma_gemm<1>, cudaFuncAttributeMaxDynamicSharedMemorySize, SMEM_MMA);
    cudaFuncSetAttribute(mma_gemm<2>, cudaFuncAttributeMaxDynamicSharedMemorySize, SMEM_MMA);

    // 0) all fp32 -> bf16 hi/lo splits + A precompute, one kernel
    split_all_kernel<<<(N4_ALL + 255) / 256, 256>>>(x, w_in, wout, xproj, dtw, Alogs);

    // 1) xz = x @ w_in^T  (HMMA)
    mma_gemm<0><<<dim3(2 * DI / 128, NTOK / 128), 128, SMEM_MMA>>>(
        xhi, xlo, w1hi, w1lo, xz, 2 * DI, DM, 0, nullptr);

    // 2) depthwise conv + silu  (vectorized x4)
    conv_silu_kernel<<<(NTOK * DI / 4 + 255) / 256, 256>>>(conv_w, conv_b);

    // 3) x_dbl = xc @ xproj^T  (HMMA, ragged nvalid=66, dts bf16 split emitted)
    mma_gemm<1><<<dim3(1, NTOK / 128), 128, SMEM_MMA>>>(
        xchi, xclo, xphi, xplo, xdbl, RPAD, DI, RTOT, nullptr);

    // 4) dt GEMM (HMMA, K=64) + fused SSM prep epilogue -> g_dt, g_dbu
    mma_gemm<2><<<dim3(DI / 128, NTOK / 128), 128, SMEM_MMA>>>(
        dshi, dslo, dwhi, dwlo, dtf, DI, DTR, DI, dtb);

    // 5) chunked scan (pass2 folded into pass3)
    scan_pass1_kernel<<<(BB * NCH * DI + 255) / 256, 256>>>();
    scan_pass3_kernel<<<(BB * NCH * DI + 255) / 256, 256>>>(Ds);

    // 6) LayerNorm + gate, emits bf16 hi/lo
    ln_gate_kernel<<<NTOK, 256>>>(lnw, lnb);

    // 7) out = yln @ w_out^T  (HMMA)
    mma_gemm<0><<<dim3(DI / 128, NTOK / 128), 128, SMEM_MMA>>>(
        yhi, ylo, wohi, wolo, out, DM, DI, 0, nullptr);
}

// round 12
// speedup vs baseline: 3.3783x; 1.0183x over previous
#include <cuda_runtime.h>
#include <cuda_bf16.h>
#include <math.h>
#include <stdint.h>

#define BB   4
#define LL   4096
#define DM   1024
#define DI   1024
#define DTR  64
#define RTOT 66
#define RPAD 68
#define NTOK (BB*LL)     // 16384
#define CH   512
#define NCH  (LL/CH)

// ---------------- scratch ----------------
__device__ __align__(16) float g_xz  [(size_t)NTOK * 2 * DI];
__device__ __align__(16) float g_xdbl[(size_t)NTOK * RPAD];
__device__ __align__(16) float g_dt  [(size_t)NTOK * DI];
__device__ __align__(16) float g_dbu [(size_t)NTOK * DI];
__device__ __align__(16) float g_y   [(size_t)NTOK * DI];
__device__ __align__(16) float g_A   [DI];
__device__ __align__(16) float g_Ac  [BB * NCH * DI];
__device__ __align__(16) float g_Bc  [BB * NCH * DI];
// bf16 split buffers
__device__ __align__(16) __nv_bfloat16 g_xhi [(size_t)NTOK * DM];
__device__ __align__(16) __nv_bfloat16 g_xlo [(size_t)NTOK * DM];
__device__ __align__(16) __nv_bfloat16 g_w1hi[(size_t)2 * DI * DM];
__device__ __align__(16) __nv_bfloat16 g_w1lo[(size_t)2 * DI * DM];
__device__ __align__(16) __nv_bfloat16 g_yhi [(size_t)NTOK * DI];
__device__ __align__(16) __nv_bfloat16 g_ylo [(size_t)NTOK * DI];
__device__ __align__(16) __nv_bfloat16 g_wohi[(size_t)DM * DI];
__device__ __align__(16) __nv_bfloat16 g_wolo[(size_t)DM * DI];
// xc bf16 split (GEMM operand AND the only copy of xc; u = hi + lo)
__device__ __align__(16) __nv_bfloat16 g_xchi[(size_t)NTOK * DI];
__device__ __align__(16) __nv_bfloat16 g_xclo[(size_t)NTOK * DI];
// x_proj split, zero-padded to 128 rows
__device__ __align__(16) __nv_bfloat16 g_xphi[(size_t)128 * DI];
__device__ __align__(16) __nv_bfloat16 g_xplo[(size_t)128 * DI];
// dts split [NTOK x 64]
__device__ __align__(16) __nv_bfloat16 g_dshi[(size_t)NTOK * DTR];
__device__ __align__(16) __nv_bfloat16 g_dslo[(size_t)NTOK * DTR];
// dt_projs_weight split [1024 x 64]
__device__ __align__(16) __nv_bfloat16 g_dwhi[(size_t)DI * DTR];
__device__ __align__(16) __nv_bfloat16 g_dwlo[(size_t)DI * DTR];

// ================= helpers =================
__device__ __forceinline__ uint32_t smem_u32(const void* p) {
    uint32_t a;
    asm("{ .reg .u64 t; cvta.to.shared.u64 t, %1; cvt.u32.u64 %0, t; }" : "=r"(a) : "l"(p));
    return a;
}
__device__ __forceinline__ void ldsm4(uint32_t* r, uint32_t addr) {
    asm volatile("ldmatrix.sync.aligned.m8n8.x4.shared.b16 {%0,%1,%2,%3}, [%4];"
                 : "=r"(r[0]), "=r"(r[1]), "=r"(r[2]), "=r"(r[3]) : "r"(addr));
}
__device__ __forceinline__ void mma16816(float* d, const uint32_t* a, uint32_t b0, uint32_t b1) {
    asm volatile("mma.sync.aligned.m16n8k16.row.col.f32.bf16.bf16.f32 "
                 "{%0,%1,%2,%3}, {%4,%5,%6,%7}, {%8,%9}, {%0,%1,%2,%3};"
                 : "+f"(d[0]), "+f"(d[1]), "+f"(d[2]), "+f"(d[3])
                 : "r"(a[0]), "r"(a[1]), "r"(a[2]), "r"(a[3]), "r"(b0), "r"(b1));
}
#define SWZ(o) ((o) ^ (((o) >> 3) & 0x70))
#define CP16(dst, src) asm volatile("cp.async.cg.shared.global [%0], [%1], 16;" :: "r"(dst), "l"(src))
#define CP_COMMIT()    asm volatile("cp.async.commit_group;" ::: "memory")
#define CP_WAIT1()     asm volatile("cp.async.wait_group 1;" ::: "memory")

// fast silu: one-shot precision (~1e-6 rel)
__device__ __forceinline__ float silu_fast(float v) {
    return __fdividef(v, 1.f + __expf(-v));
}

// dt epilogue prep (delta via precise log1pf: its abs error compounds in the scan)
__device__ __forceinline__ void ssm_prep1(float dtv, int r, int c, float Bsv)
{
    float t     = __expf(dtv);
    float delta = (dtv > 15.f) ? dtv : log1pf(t);
    float dA    = __expf(delta * g_A[c]);
    size_t off  = (size_t)r * DI + c;
    float u     = __bfloat162float(g_xchi[off]) + __bfloat162float(g_xclo[off]);
    g_dt [off] = dA;
    g_dbu[off] = delta * Bsv * u;
}

// ============ HMMA split GEMM v4 ============
// MODE 0: plain. MODE 1: ragged-N + dts bf16 split. MODE 2: fused SSM prep.
#define STG_B  32768
template<int MODE>
__global__ void __launch_bounds__(128)
mma_gemm(const __nv_bfloat16* __restrict__ Ahi, const __nv_bfloat16* __restrict__ Alo,
         const __nv_bfloat16* __restrict__ Bhi, const __nv_bfloat16* __restrict__ Blo,
         float* __restrict__ C, int ldc, int K, int nvalid,
         const float* __restrict__ dtb)
{
    extern __shared__ __align__(1024) char dynsm[];
    const uint32_t sb = smem_u32(dynsm);

    const int tid  = threadIdx.x;
    const int lane = tid & 31;
    const int wid  = tid >> 5;
    const int wm   = wid & 1;
    const int wn   = wid >> 1;
    const int m0   = blockIdx.y * 128;
    const int n0   = blockIdx.x * 128;

    float acc[4][8][4];
#pragma unroll
    for (int m = 0; m < 4; m++)
#pragma unroll
        for (int n = 0; n < 8; n++)
#pragma unroll
            for (int v = 0; v < 4; v++) acc[m][n][v] = 0.f;

    const int a_row = lane & 15;
    const int b_row = (lane & 7) + ((lane >> 3) & 1) * 8;
    const int cb    = (lane >> 4) * 16;

    uint32_t aoff[2][4], boff[2][4];
#pragma unroll
    for (int ks = 0; ks < 2; ks++) {
#pragma unroll
        for (int m = 0; m < 4; m++)
            aoff[ks][m] = SWZ((uint32_t)(wm * 64 + m * 16 + a_row) * 128 + ks * 32 + cb);
#pragma unroll
        for (int p = 0; p < 4; p++)
            boff[ks][p] = 16384u + SWZ((uint32_t)(wn * 64 + p * 16 + b_row) * 128 + ks * 32 + cb);
    }

#define LOAD_STAGE(s, koff) do {                                               \
    const uint32_t sdst = sb + (s) * STG_B;                                    \
    _Pragma("unroll")                                                          \
    for (int it = 0; it < 16; it++) {                                          \
        int i = tid + it * 128;                                                \
        int arr = i >> 10;                                                     \
        int j = i & 1023;                                                      \
        int row = j >> 3;                                                      \
        int half = (j >> 2) & 1, c = j & 3;                                    \
        const __nv_bfloat16* g = arr ? (half ? Blo : Bhi) : (half ? Alo : Ahi);\
        int rb = arr ? n0 : m0;                                                \
        const void* gp = g + (size_t)(rb + row) * K + (koff) + c * 8;          \
        uint32_t d = sdst + arr * 16384 + SWZ(row * 128 + half * 64 + c * 16); \
        CP16(d, gp);                                                           \
    }                                                                          \
    CP_COMMIT();                                                               \
} while (0)

    LOAD_STAGE(0, 0);
    LOAD_STAGE(1, 32);

    const int NK = K / 32;
    for (int kt = 0; kt < NK; kt++) {
        CP_WAIT1();
        __syncthreads();
        if (kt + 2 < NK) LOAD_STAGE((kt + 2) % 3, (kt + 2) * 32);
        else             CP_COMMIT();   // empty group keeps the wait invariant

        const uint32_t stg = sb + (kt % 3) * STG_B;
#pragma unroll
        for (int ks = 0; ks < 2; ks++) {
            uint32_t bh[4][4], bl[4][4];
#pragma unroll
            for (int p = 0; p < 4; p++) {
                uint32_t ba = stg + boff[ks][p];
                ldsm4(bh[p], ba);
                ldsm4(bl[p], ba ^ 64u);
            }
            uint32_t ah[2][4], al[2][4];
            {
                uint32_t aa = stg + aoff[ks][0];
                ldsm4(ah[0], aa);
                ldsm4(al[0], aa ^ 64u);
            }
#pragma unroll
            for (int m = 0; m < 4; m++) {
                const int cur = m & 1;
                if (m < 3) {
                    uint32_t aa = stg + aoff[ks][m + 1];
                    ldsm4(ah[cur ^ 1], aa);
                    ldsm4(al[cur ^ 1], aa ^ 64u);
                }
#pragma unroll
                for (int n = 0; n < 8; n++) {
                    const int p = n >> 1, q = n & 1;
                    mma16816(acc[m][n], ah[cur], bh[p][q], bh[p][q + 2]);
                    mma16816(acc[m][n], ah[cur], bl[p][q], bl[p][q + 2]);
                    mma16816(acc[m][n], al[cur], bh[p][q], bh[p][q + 2]);
                }
            }
        }
    }

    // ---- epilogue ----
#pragma unroll
    for (int m = 0; m < 4; m++) {
        const int row = m0 + wm * 64 + m * 16 + (lane >> 2);
        float Bsv0, Bsv1;
        if constexpr (MODE == 2) {
            Bsv0 = g_xdbl[(size_t)row * RPAD + DTR];
            Bsv1 = g_xdbl[(size_t)(row + 8) * RPAD + DTR];
        }
#pragma unroll
        for (int n = 0; n < 8; n++) {
            const int col = n0 + wn * 64 + n * 8 + (lane & 3) * 2;
            if constexpr (MODE == 0) {
                *(float2*)(C + (size_t)row * ldc + col)       = make_float2(acc[m][n][0], acc[m][n][1]);
                *(float2*)(C + (size_t)(row + 8) * ldc + col) = make_float2(acc[m][n][2], acc[m][n][3]);
            } else if constexpr (MODE == 1) {
                if (col + 2 <= nvalid) {
                    *(float2*)(C + (size_t)row * ldc + col)       = make_float2(acc[m][n][0], acc[m][n][1]);
                    *(float2*)(C + (size_t)(row + 8) * ldc + col) = make_float2(acc[m][n][2], acc[m][n][3]);
                }
                if (col + 2 <= DTR) {
#pragma unroll
                    for (int h = 0; h < 2; h++) {
                        int r = row + h * 8;
                        float v0 = acc[m][n][h * 2], v1 = acc[m][n][h * 2 + 1];
                        __nv_bfloat16 h0 = __float2bfloat16(v0), h1 = __float2bfloat16(v1);
                        *(__nv_bfloat162*)(g_dshi + (size_t)r * DTR + col) = __nv_bfloat162(h0, h1);
                        *(__nv_bfloat162*)(g_dslo + (size_t)r * DTR + col) =
                            __nv_bfloat162(__float2bfloat16(v0 - __bfloat162float(h0)),
                                           __float2bfloat16(v1 - __bfloat162float(h1)));
                    }
                }
            } else {                    // MODE 2: fused SSM prep
                float b0 = dtb[col], b1 = dtb[col + 1];
                ssm_prep1(acc[m][n][0] + b0, row,     col,     Bsv0);
                ssm_prep1(acc[m][n][1] + b1, row,     col + 1, Bsv0);
                ssm_prep1(acc[m][n][2] + b0, row + 8, col,     Bsv1);
                ssm_prep1(acc[m][n][3] + b1, row + 8, col + 1, Bsv1);
            }
        }
    }
}

// ================= combined fp32 -> bf16 hi/lo split (+ A precompute) =================
__device__ __forceinline__ void split4(float4 v, __nv_bfloat16* hi, __nv_bfloat16* lo, int i)
{
    __nv_bfloat16 h0 = __float2bfloat16(v.x), h1 = __float2bfloat16(v.y);
    __nv_bfloat16 h2 = __float2bfloat16(v.z), h3 = __float2bfloat16(v.w);
    __nv_bfloat162* H = (__nv_bfloat162*)hi;
    __nv_bfloat162* L = (__nv_bfloat162*)lo;
    H[i*2+0] = __nv_bfloat162(h0, h1);
    H[i*2+1] = __nv_bfloat162(h2, h3);
    L[i*2+0] = __nv_bfloat162(__float2bfloat16(v.x - __bfloat162float(h0)),
                              __float2bfloat16(v.y - __bfloat162float(h1)));
    L[i*2+1] = __nv_bfloat162(__float2bfloat16(v.z - __bfloat162float(h2)),
                              __float2bfloat16(v.w - __bfloat162float(h3)));
}

#define N4_X  (NTOK * DM / 4)
#define N4_W1 (2 * DI * DM / 4)
#define N4_WO (DM * DI / 4)
#define N4_XP (RTOT * DI / 4)
#define N4_DW (DI * DTR / 4)
#define N4_A  (DI / 4)
#define N4_ALL (N4_X + N4_W1 + N4_WO + N4_XP + N4_DW + N4_A)

__global__ void split_all_kernel(const float* __restrict__ x, const float* __restrict__ w1,
                                 const float* __restrict__ wo, const float* __restrict__ xp,
                                 const float* __restrict__ dw, const float* __restrict__ Alogs)
{
    int i = blockIdx.x * blockDim.x + threadIdx.x;
    if (i < N4_X) { split4(((const float4*)x)[i], g_xhi, g_xlo, i); return; }
    i -= N4_X;
    if (i < N4_W1) { split4(((const float4*)w1)[i], g_w1hi, g_w1lo, i); return; }
    i -= N4_W1;
    if (i < N4_WO) { split4(((const float4*)wo)[i], g_wohi, g_wolo, i); return; }
    i -= N4_WO;
    if (i < N4_XP) { split4(((const float4*)xp)[i], g_xphi, g_xplo, i); return; }
    i -= N4_XP;
    if (i < N4_DW) { split4(((const float4*)dw)[i], g_dwhi, g_dwlo, i); return; }
    i -= N4_DW;
    if (i < N4_A) {
        float4 a = ((const float4*)Alogs)[i];
        g_A[i*4+0] = -expf(a.x); g_A[i*4+1] = -expf(a.y);
        g_A[i*4+2] = -expf(a.z); g_A[i*4+3] = -expf(a.w);
    }
}

// ---------------- depthwise conv (k=2) + SiLU, vectorized x4, bf16-split output ----------------
__global__ void conv_silu_kernel(const float* __restrict__ cw, const float* __restrict__ cb)
{
    int idx = blockIdx.x * blockDim.x + threadIdx.x;   // over NTOK*DI/4
    if (idx >= NTOK * DI / 4) return;
    int d4  = idx & (DI / 4 - 1);
    int tok = idx >> 8;
    int l   = tok & (LL - 1);
    int d   = d4 * 4;

    float4 cur  = *(const float4*)(g_xz + (size_t)tok * (2 * DI) + d);
    float4 prev = make_float4(0.f, 0.f, 0.f, 0.f);
    if (l > 0) prev = *(const float4*)(g_xz + (size_t)(tok - 1) * (2 * DI) + d);
    float4 w0 = *(const float4*)(cw + 2 * d);
    float4 w1 = *(const float4*)(cw + 2 * d + 4);
    float4 b  = *(const float4*)(cb + d);

    float s0 = silu_fast(fmaf(w0.x, prev.x, fmaf(w0.y, cur.x, b.x)));
    float s1 = silu_fast(fmaf(w0.z, prev.y, fmaf(w0.w, cur.y, b.y)));
    float s2 = silu_fast(fmaf(w1.x, prev.z, fmaf(w1.y, cur.z, b.z)));
    float s3 = silu_fast(fmaf(w1.z, prev.w, fmaf(w1.w, cur.w, b.w)));

    __nv_bfloat16 h0 = __float2bfloat16(s0), h1 = __float2bfloat16(s1);
    __nv_bfloat16 h2 = __float2bfloat16(s2), h3 = __float2bfloat16(s3);
    __nv_bfloat162* H = (__nv_bfloat162*)(g_xchi + (size_t)tok * DI + d);
    __nv_bfloat162* L = (__nv_bfloat162*)(g_xclo + (size_t)tok * DI + d);
    H[0] = __nv_bfloat162(h0, h1);
    H[1] = __nv_bfloat162(h2, h3);
    L[0] = __nv_bfloat162(__float2bfloat16(s0 - __bfloat162float(h0)),
                          __float2bfloat16(s1 - __bfloat162float(h1)));
    L[1] = __nv_bfloat162(__float2bfloat16(s2 - __bfloat162float(h2)),
                          __float2bfloat16(s3 - __bfloat162float(h3)));
}

// ---------------- chunked scan, vectorized x2 over d ----------------
__global__ void scan_pass1_kernel()
{
    int t = blockIdx.x * blockDim.x + threadIdx.x;   // over BB*NCH*DI/2
    if (t >= BB * NCH * DI / 2) return;
    int d = (t & (DI / 2 - 1)) * 2;
    int c = (t >> 9) & (NCH - 1);
    int b = t >> 12;
    size_t base = ((size_t)b * LL + (size_t)c * CH) * DI + d;
    float ap0 = 1.f, ap1 = 1.f, h0 = 0.f, h1 = 0.f;
#pragma unroll 4
    for (int l = 0; l < CH; l++) {
        float2 a  = *(const float2*)(g_dt  + base + (size_t)l * DI);
        float2 bu = *(const float2*)(g_dbu + base + (size_t)l * DI);
        h0 = fmaf(a.x, h0, bu.x);
        h1 = fmaf(a.y, h1, bu.y);
        ap0 *= a.x; ap1 *= a.y;
    }
    size_t cidx = ((size_t)(b * NCH) + c) * DI + d;
    *(float2*)(g_Ac + cidx) = make_float2(ap0, ap1);
    *(float2*)(g_Bc + cidx) = make_float2(h0, h1);
}

// pass 3: inlined chunk chain + emit y, vectorized x2
__global__ void scan_pass3_kernel(const float* __restrict__ Ds)
{
    int t = blockIdx.x * blockDim.x + threadIdx.x;
    if (t >= BB * NCH * DI / 2) return;
    int d = (t & (DI / 2 - 1)) * 2;
    int c = (t >> 9) & (NCH - 1);
    int b = t >> 12;
    float2 Dd = *(const float2*)(Ds + d);

    float h0 = 0.f, h1 = 0.f;
    for (int j = 0; j < c; j++) {
        size_t idx = ((size_t)(b * NCH) + j) * DI + d;
        float2 A = *(const float2*)(g_Ac + idx);
        float2 B = *(const float2*)(g_Bc + idx);
        h0 = fmaf(A.x, h0, B.x);
        h1 = fmaf(A.y, h1, B.y);
    }

    size_t tok0 = (size_t)b * LL + (size_t)c * CH;
    size_t base = tok0 * DI + d;
#pragma unroll 4
    for (int l = 0; l < CH; l++) {
        size_t off = base + (size_t)l * DI;
        float2 a  = *(const float2*)(g_dt  + off);
        float2 bu = *(const float2*)(g_dbu + off);
        __nv_bfloat162 uh = *(const __nv_bfloat162*)(g_xchi + off);
        __nv_bfloat162 ul = *(const __nv_bfloat162*)(g_xclo + off);
        float Cs = g_xdbl[(tok0 + l) * RPAD + DTR + 1];
        h0 = fmaf(a.x, h0, bu.x);
        h1 = fmaf(a.y, h1, bu.y);
        float u0 = __bfloat162float(uh.x) + __bfloat162float(ul.x);
        float u1 = __bfloat162float(uh.y) + __bfloat162float(ul.y);
        *(float2*)(g_y + off) = make_float2(fmaf(h0, Cs, u0 * Dd.x),
                                            fmaf(h1, Cs, u1 * Dd.y));
    }
}

// ---------------- LayerNorm + SiLU gate, contiguous float4 per thread ----------------
__global__ void __launch_bounds__(256) ln_gate_kernel(const float* __restrict__ lnw,
                                                      const float* __restrict__ lnb)
{
    int tok = blockIdx.x;
    int tid = threadIdx.x;
    size_t base = (size_t)tok * DI;
    int d = tid * 4;

    float4 v = *(const float4*)(g_y + base + d);
    float s = v.x + v.y + v.z + v.w;
    float q = v.x * v.x + v.y * v.y + v.z * v.z + v.w * v.w;
#pragma unroll
    for (int o = 16; o; o >>= 1) {
        s += __shfl_xor_sync(0xffffffffu, s, o);
        q += __shfl_xor_sync(0xffffffffu, q, o);
    }
    __shared__ float ss[8], sq[8];
    if ((tid & 31) == 0) { ss[tid >> 5] = s; sq[tid >> 5] = q; }
    __syncthreads();
    float S = 0.f, Q = 0.f;
#pragma unroll
    for (int w = 0; w < 8; w++) { S += ss[w]; Q += sq[w]; }

    float mu  = S * (1.f / DI);
    float var = Q * (1.f / DI) - mu * mu;
    float rs  = rsqrtf(var + 1e-5f);

    float4 z = *(const float4*)(g_xz + (size_t)tok * (2 * DI) + DI + d);
    float4 w4 = *(const float4*)(lnw + d);
    float4 b4 = *(const float4*)(lnb + d);

    float o0 = fmaf((v.x - mu) * rs, w4.x, b4.x) * silu_fast(z.x);
    float o1 = fmaf((v.y - mu) * rs, w4.y, b4.y) * silu_fast(z.y);
    float o2 = fmaf((v.z - mu) * rs, w4.z, b4.z) * silu_fast(z.z);
    float o3 = fmaf((v.w - mu) * rs, w4.w, b4.w) * silu_fast(z.w);

    __nv_bfloat16 h0 = __float2bfloat16(o0), h1 = __float2bfloat16(o1);
    __nv_bfloat16 h2 = __float2bfloat16(o2), h3 = __float2bfloat16(o3);
    __nv_bfloat162* H = (__nv_bfloat162*)(g_yhi + base + d);
    __nv_bfloat162* L = (__nv_bfloat162*)(g_ylo + base + d);
    H[0] = __nv_bfloat162(h0, h1);
    H[1] = __nv_bfloat162(h2, h3);
    L[0] = __nv_bfloat162(__float2bfloat16(o0 - __bfloat162float(h0)),
                          __float2bfloat16(o1 - __bfloat162float(h1)));
    L[1] = __nv_bfloat162(__float2bfloat16(o2 - __bfloat162float(h2)),
                          __float2bfloat16(o3 - __bfloat162float(h3)));
}

// ---------------- launch ----------------
extern "C" void kernel_launch(void* const* d_in, const int* in_sizes, int n_in,
                              void* d_out, int out_size)
{
    const float* x      = (const float*)d_in[0];
    const float* w_in   = (const float*)d_in[1];
    const float* conv_w = (const float*)d_in[2];
    const float* conv_b = (const float*)d_in[3];
    const float* xproj  = (const float*)d_in[4];
    const float* dtw    = (const float*)d_in[5];
    const float* dtb    = (const float*)d_in[6];
    const float* Alogs  = (const float*)d_in[7];
    const float* Ds     = (const float*)d_in[8];
    const float* lnw    = (const float*)d_in[9];
    const float* lnb    = (const float*)d_in[10];
    const float* wout   = (const float*)d_in[11];
    float* out = (float*)d_out;

    float *xz, *xdbl, *dtf;
    __nv_bfloat16 *xhi, *xlo, *w1hi, *w1lo, *yhi, *ylo, *wohi, *wolo;
    __nv_bfloat16 *xchi, *xclo, *xphi, *xplo, *dshi, *dslo, *dwhi, *dwlo;
    cudaGetSymbolAddress((void**)&xz,   g_xz);
    cudaGetSymbolAddress((void**)&xdbl, g_xdbl);
    cudaGetSymbolAddress((void**)&dtf,  g_dt);
    cudaGetSymbolAddress((void**)&xhi,  g_xhi);
    cudaGetSymbolAddress((void**)&xlo,  g_xlo);
    cudaGetSymbolAddress((void**)&w1hi, g_w1hi);
    cudaGetSymbolAddress((void**)&w1lo, g_w1lo);
    cudaGetSymbolAddress((void**)&yhi,  g_yhi);
    cudaGetSymbolAddress((void**)&ylo,  g_ylo);
    cudaGetSymbolAddress((void**)&wohi, g_wohi);
    cudaGetSymbolAddress((void**)&wolo, g_wolo);
    cudaGetSymbolAddress((void**)&xchi, g_xchi);
    cudaGetSymbolAddress((void**)&xclo, g_xclo);
    cudaGetSymbolAddress((void**)&xphi, g_xphi);
    cudaGetSymbolAddress((void**)&xplo, g_xplo);
    cudaGetSymbolAddress((void**)&dshi, g_dshi);
    cudaGetSymbolAddress((void**)&dslo, g_dslo);
    cudaGetSymbolAddress((void**)&dwhi, g_dwhi);
    cudaGetSymbolAddress((void**)&dwlo, g_dwlo);

    const int SMEM_MMA = 3 * STG_B;   // 98304 bytes, 2 CTAs/SM
    cudaFuncSetAttribute(mma_gemm<0>, cudaFuncAttributeMaxDynamicSharedMemorySize, SMEM_MMA);
    cudaFuncSetAttribute(mma_gemm<1>, cudaFuncAttributeMaxDynamicSharedMemorySize, SMEM_MMA);
    cudaFuncSetAttribute(mma_gemm<2>, cudaFuncAttributeMaxDynamicSharedMemorySize, SMEM_MMA);

    // 0) all fp32 -> bf16 hi/lo splits + A precompute
    split_all_kernel<<<(N4_ALL + 255) / 256, 256>>>(x, w_in, wout, xproj, dtw, Alogs);

    // 1) xz = x @ w_in^T  (HMMA)
    mma_gemm<0><<<dim3(2 * DI / 128, NTOK / 128), 128, SMEM_MMA>>>(
        xhi, xlo, w1hi, w1lo, xz, 2 * DI, DM, 0, nullptr);

    // 2) depthwise conv + silu  (bf16 split output only)
    conv_silu_kernel<<<(NTOK * DI / 4 + 255) / 256, 256>>>(conv_w, conv_b);

    // 3) x_dbl = xc @ xproj^T  (HMMA, ragged nvalid=66, dts bf16 split emitted)
    mma_gemm<1><<<dim3(1, NTOK / 128), 128, SMEM_MMA>>>(
        xchi, xclo, xphi, xplo, xdbl, RPAD, DI, RTOT, nullptr);

    // 4) dt GEMM (HMMA, K=64) + fused SSM prep epilogue -> g_dt, g_dbu
    mma_gemm<2><<<dim3(DI / 128, NTOK / 128), 128, SMEM_MMA>>>(
        dshi, dslo, dwhi, dwlo, dtf, DI, DTR, DI, dtb);

    // 5) chunked scan (x2 vectorized)
    scan_pass1_kernel<<<(BB * NCH * DI / 2 + 255) / 256, 256>>>();
    scan_pass3_kernel<<<(BB * NCH * DI / 2 + 255) / 256, 256>>>(Ds);

    // 6) LayerNorm + gate, emits bf16 hi/lo
    ln_gate_kernel<<<NTOK, 256>>>(lnw, lnb);

    // 7) out = yln @ w_out^T  (HMMA)
    mma_gemm<0><<<dim3(DI / 128, NTOK / 128), 128, SMEM_MMA>>>(
        yhi, ylo, wohi, wolo, out, DM, DI, 0, nullptr);
}

// round 17
// speedup vs baseline: 4.0748x; 1.2061x over previous
#include <cuda_runtime.h>
#include <cuda_bf16.h>
#include <math.h>
#include <stdint.h>

#define BB   4
#define LL   4096
#define DM   1024
#define DI   1024
#define DTR  64
#define RTOT 66
#define RPAD 68
#define NTOK (BB*LL)     // 16384
#define CH   128         // scan chunk == dt-GEMM M-tile
#define NCH  (LL/CH)     // 32

// ---------------- scratch ----------------
__device__ __align__(16) float g_xz  [(size_t)NTOK * 2 * DI];
__device__ __align__(16) float g_xdbl[(size_t)NTOK * RPAD];
__device__ __align__(16) float g_P   [(size_t)NTOK * DI];   // prefix prod(dA) within chunk
__device__ __align__(16) float g_hl  [(size_t)NTOK * DI];   // zero-state local scan within chunk
__device__ __align__(16) float g_A   [DI];
__device__ __align__(16) float g_h0  [BB * NCH * DI];       // state entering each chunk
// bf16 split buffers
__device__ __align__(16) __nv_bfloat16 g_xhi [(size_t)NTOK * DM];
__device__ __align__(16) __nv_bfloat16 g_xlo [(size_t)NTOK * DM];
__device__ __align__(16) __nv_bfloat16 g_w1hi[(size_t)2 * DI * DM];
__device__ __align__(16) __nv_bfloat16 g_w1lo[(size_t)2 * DI * DM];
__device__ __align__(16) __nv_bfloat16 g_yhi [(size_t)NTOK * DI];
__device__ __align__(16) __nv_bfloat16 g_ylo [(size_t)NTOK * DI];
__device__ __align__(16) __nv_bfloat16 g_wohi[(size_t)DM * DI];
__device__ __align__(16) __nv_bfloat16 g_wolo[(size_t)DM * DI];
// xc bf16 split (GEMM operand AND only copy of xc; u = hi + lo)
__device__ __align__(16) __nv_bfloat16 g_xchi[(size_t)NTOK * DI];
__device__ __align__(16) __nv_bfloat16 g_xclo[(size_t)NTOK * DI];
// x_proj split, zero-padded to 128 rows
__device__ __align__(16) __nv_bfloat16 g_xphi[(size_t)128 * DI];
__device__ __align__(16) __nv_bfloat16 g_xplo[(size_t)128 * DI];
// dts split [NTOK x 64]
__device__ __align__(16) __nv_bfloat16 g_dshi[(size_t)NTOK * DTR];
__device__ __align__(16) __nv_bfloat16 g_dslo[(size_t)NTOK * DTR];
// dt_projs_weight split [1024 x 64]
__device__ __align__(16) __nv_bfloat16 g_dwhi[(size_t)DI * DTR];
__device__ __align__(16) __nv_bfloat16 g_dwlo[(size_t)DI * DTR];

// ================= helpers =================
__device__ __forceinline__ uint32_t smem_u32(const void* p) {
    uint32_t a;
    asm("{ .reg .u64 t; cvta.to.shared.u64 t, %1; cvt.u32.u64 %0, t; }" : "=r"(a) : "l"(p));
    return a;
}
__device__ __forceinline__ void ldsm4(uint32_t* r, uint32_t addr) {
    asm volatile("ldmatrix.sync.aligned.m8n8.x4.shared.b16 {%0,%1,%2,%3}, [%4];"
                 : "=r"(r[0]), "=r"(r[1]), "=r"(r[2]), "=r"(r[3]) : "r"(addr));
}
__device__ __forceinline__ void mma16816(float* d, const uint32_t* a, uint32_t b0, uint32_t b1) {
    asm volatile("mma.sync.aligned.m16n8k16.row.col.f32.bf16.bf16.f32 "
                 "{%0,%1,%2,%3}, {%4,%5,%6,%7}, {%8,%9}, {%0,%1,%2,%3};"
                 : "+f"(d[0]), "+f"(d[1]), "+f"(d[2]), "+f"(d[3])
                 : "r"(a[0]), "r"(a[1]), "r"(a[2]), "r"(a[3]), "r"(b0), "r"(b1));
}
#define SWZ(o) ((o) ^ (((o) >> 3) & 0x70))
#define CP16(dst, src) asm volatile("cp.async.cg.shared.global [%0], [%1], 16;" :: "r"(dst), "l"(src))
#define CP_COMMIT()    asm volatile("cp.async.commit_group;" ::: "memory")
#define CP_WAIT1()     asm volatile("cp.async.wait_group 1;" ::: "memory")
#define CP_WAIT0()     asm volatile("cp.async.wait_group 0;" ::: "memory")

__device__ __forceinline__ float silu_fast(float v) {
    return __fdividef(v, 1.f + __expf(-v));
}

// dtv -> (dA, dbu) for the scan (delta via precise log1pf; error compounds)
__device__ __forceinline__ void prep_da_dbu(float dtv, int r, int c, float Bsv,
                                            float* dA_out, float* dbu_out)
{
    float t     = __expf(dtv);
    float delta = (dtv > 15.f) ? dtv : log1pf(t);
    float dA    = __expf(delta * g_A[c]);
    size_t off  = (size_t)r * DI + c;
    float u     = __bfloat162float(g_xchi[off]) + __bfloat162float(g_xclo[off]);
    *dA_out  = dA;
    *dbu_out = delta * Bsv * u;
}

// ============ HMMA split GEMM v5 ============
// MODE 0: plain. MODE 1: ragged-N + dts bf16 split (x_dbl).
// MODE 2: dt GEMM -> in-epilogue chunk scan: writes g_P (prefix prod dA) and
//         g_hl (zero-state local scan) for its 128-token x 128-col tile.
#define STG_B  32768
#define SPITCH 66
template<int MODE>
__global__ void __launch_bounds__(128)
mma_gemm(const __nv_bfloat16* __restrict__ Ahi, const __nv_bfloat16* __restrict__ Alo,
         const __nv_bfloat16* __restrict__ Bhi, const __nv_bfloat16* __restrict__ Blo,
         float* __restrict__ C, int ldc, int K, int nvalid,
         const float* __restrict__ dtb)
{
    extern __shared__ __align__(1024) char dynsm[];
    const uint32_t sb = smem_u32(dynsm);

    const int tid  = threadIdx.x;
    const int lane = tid & 31;
    const int wid  = tid >> 5;
    const int wm   = wid & 1;
    const int wn   = wid >> 1;
    const int m0   = blockIdx.y * 128;
    const int n0   = blockIdx.x * 128;

    float acc[4][8][4];
#pragma unroll
    for (int m = 0; m < 4; m++)
#pragma unroll
        for (int n = 0; n < 8; n++)
#pragma unroll
            for (int v = 0; v < 4; v++) acc[m][n][v] = 0.f;

    const int a_row = lane & 15;
    const int b_row = (lane & 7) + ((lane >> 3) & 1) * 8;
    const int cb    = (lane >> 4) * 16;

    uint32_t aoff[2][4], boff[2][4];
#pragma unroll
    for (int ks = 0; ks < 2; ks++) {
#pragma unroll
        for (int m = 0; m < 4; m++)
            aoff[ks][m] = SWZ((uint32_t)(wm * 64 + m * 16 + a_row) * 128 + ks * 32 + cb);
#pragma unroll
        for (int p = 0; p < 4; p++)
            boff[ks][p] = 16384u + SWZ((uint32_t)(wn * 64 + p * 16 + b_row) * 128 + ks * 32 + cb);
    }

#define LOAD_STAGE(s, koff) do {                                               \
    const uint32_t sdst = sb + (s) * STG_B;                                    \
    _Pragma("unroll")                                                          \
    for (int it = 0; it < 16; it++) {                                          \
        int i = tid + it * 128;                                                \
        int arr = i >> 10;                                                     \
        int j = i & 1023;                                                      \
        int row = j >> 3;                                                      \
        int half = (j >> 2) & 1, c = j & 3;                                    \
        const __nv_bfloat16* g = arr ? (half ? Blo : Bhi) : (half ? Alo : Ahi);\
        int rb = arr ? n0 : m0;                                                \
        const void* gp = g + (size_t)(rb + row) * K + (koff) + c * 8;          \
        uint32_t d = sdst + arr * 16384 + SWZ(row * 128 + half * 64 + c * 16); \
        CP16(d, gp);                                                           \
    }                                                                          \
    CP_COMMIT();                                                               \
} while (0)

    LOAD_STAGE(0, 0);
    LOAD_STAGE(1, 32);

    const int NK = K / 32;
    for (int kt = 0; kt < NK; kt++) {
        CP_WAIT1();
        __syncthreads();   // (a) stage-kt data landed; (b) all warps done reading
                           // the stage the next load would overwrite
        if (kt + 2 < NK) LOAD_STAGE((kt + 2) % 3, (kt + 2) * 32);
        else             CP_COMMIT();   // empty group keeps the wait invariant

        const uint32_t stg = sb + (kt % 3) * STG_B;
#pragma unroll
        for (int ks = 0; ks < 2; ks++) {
            uint32_t bh[4][4], bl[4][4];
#pragma unroll
            for (int p = 0; p < 4; p++) {
                uint32_t ba = stg + boff[ks][p];
                ldsm4(bh[p], ba);
                ldsm4(bl[p], ba ^ 64u);
            }
            uint32_t ah[2][4], al[2][4];
            {
                uint32_t aa = stg + aoff[ks][0];
                ldsm4(ah[0], aa);
                ldsm4(al[0], aa ^ 64u);
            }
#pragma unroll
            for (int m = 0; m < 4; m++) {
                const int cur = m & 1;
                if (m < 3) {
                    uint32_t aa = stg + aoff[ks][m + 1];
                    ldsm4(ah[cur ^ 1], aa);
                    ldsm4(al[cur ^ 1], aa ^ 64u);
                }
#pragma unroll
                for (int n = 0; n < 8; n++) {
                    const int p = n >> 1, q = n & 1;
                    mma16816(acc[m][n], ah[cur], bh[p][q], bh[p][q + 2]);
                    mma16816(acc[m][n], ah[cur], bl[p][q], bl[p][q + 2]);
                    mma16816(acc[m][n], al[cur], bh[p][q], bh[p][q + 2]);
                }
            }
        }
    }

    // ---- epilogue ----
    if constexpr (MODE == 2) {
        CP_WAIT0();        // guarantee zero cp.async writes in flight before smem reuse
        // In-tile scan: chunk == this CTA's 128 tokens, for its 128 d-columns.
        float* sdA  = (float*)dynsm;            // [128][SPITCH]
        float* sdbu = sdA + 128 * SPITCH;
#pragma unroll 1
        for (int half = 0; half < 2; half++) {
            __syncthreads();   // dynsm free: all warps past mainloop / prev half
            if (wn == half) {
#pragma unroll
                for (int m = 0; m < 4; m++) {
                    int rl0 = wm * 64 + m * 16 + (lane >> 2);
                    int rl1 = rl0 + 8;
                    float Bsv0 = g_xdbl[(size_t)(m0 + rl0) * RPAD + DTR];
                    float Bsv1 = g_xdbl[(size_t)(m0 + rl1) * RPAD + DTR];
#pragma unroll
                    for (int n = 0; n < 8; n++) {
                        int cl  = n * 8 + (lane & 3) * 2;   // 0..63 within half
                        int col = n0 + half * 64 + cl;
                        float b0 = dtb[col], b1 = dtb[col + 1];
                        prep_da_dbu(acc[m][n][0] + b0, m0 + rl0, col,     Bsv0,
                                    &sdA[rl0 * SPITCH + cl],     &sdbu[rl0 * SPITCH + cl]);
                        prep_da_dbu(acc[m][n][1] + b1, m0 + rl0, col + 1, Bsv0,
                                    &sdA[rl0 * SPITCH + cl + 1], &sdbu[rl0 * SPITCH + cl + 1]);
                        prep_da_dbu(acc[m][n][2] + b0, m0 + rl1, col,     Bsv1,
                                    &sdA[rl1 * SPITCH + cl],     &sdbu[rl1 * SPITCH + cl]);
                        prep_da_dbu(acc[m][n][3] + b1, m0 + rl1, col + 1, Bsv1,
                                    &sdA[rl1 * SPITCH + cl + 1], &sdbu[rl1 * SPITCH + cl + 1]);
                    }
                }
            }
            __syncthreads();
            if (tid < 64) {           // serial scan per column (conflict-free)
                int col = tid;
                float P = 1.f, h = 0.f;
#pragma unroll 4
                for (int t = 0; t < 128; t++) {
                    float a  = sdA [t * SPITCH + col];
                    float bu = sdbu[t * SPITCH + col];
                    h = fmaf(a, h, bu);
                    P *= a;
                    sdA [t * SPITCH + col] = P;   // overwrite in place
                    sdbu[t * SPITCH + col] = h;
                }
            }
            __syncthreads();
            for (int i = tid; i < 128 * 64; i += 128) {
                int t = i >> 6, cc = i & 63;
                size_t off = (size_t)(m0 + t) * DI + n0 + half * 64 + cc;
                g_P [off] = sdA [t * SPITCH + cc];
                g_hl[off] = sdbu[t * SPITCH + cc];
            }
        }
        return;
    }

#pragma unroll
    for (int m = 0; m < 4; m++) {
        const int row = m0 + wm * 64 + m * 16 + (lane >> 2);
#pragma unroll
        for (int n = 0; n < 8; n++) {
            const int col = n0 + wn * 64 + n * 8 + (lane & 3) * 2;
            if constexpr (MODE == 0) {
                *(float2*)(C + (size_t)row * ldc + col)       = make_float2(acc[m][n][0], acc[m][n][1]);
                *(float2*)(C + (size_t)(row + 8) * ldc + col) = make_float2(acc[m][n][2], acc[m][n][3]);
            } else {   // MODE 1
                if (col + 2 <= nvalid) {
                    *(float2*)(C + (size_t)row * ldc + col)       = make_float2(acc[m][n][0], acc[m][n][1]);
                    *(float2*)(C + (size_t)(row + 8) * ldc + col) = make_float2(acc[m][n][2], acc[m][n][3]);
                }
                if (col + 2 <= DTR) {
#pragma unroll
                    for (int h = 0; h < 2; h++) {
                        int r = row + h * 8;
                        float v0 = acc[m][n][h * 2], v1 = acc[m][n][h * 2 + 1];
                        __nv_bfloat16 h0 = __float2bfloat16(v0), h1 = __float2bfloat16(v1);
                        *(__nv_bfloat162*)(g_dshi + (size_t)r * DTR + col) = __nv_bfloat162(h0, h1);
                        *(__nv_bfloat162*)(g_dslo + (size_t)r * DTR + col) =
                            __nv_bfloat162(__float2bfloat16(v0 - __bfloat162float(h0)),
                                           __float2bfloat16(v1 - __bfloat162float(h1)));
                    }
                }
            }
        }
    }
}

// ================= combined fp32 -> bf16 hi/lo split (+ A precompute) =================
__device__ __forceinline__ void split4(float4 v, __nv_bfloat16* hi, __nv_bfloat16* lo, int i)
{
    __nv_bfloat16 h0 = __float2bfloat16(v.x), h1 = __float2bfloat16(v.y);
    __nv_bfloat16 h2 = __float2bfloat16(v.z), h3 = __float2bfloat16(v.w);
    __nv_bfloat162* H = (__nv_bfloat162*)hi;
    __nv_bfloat162* L = (__nv_bfloat162*)lo;
    H[i*2+0] = __nv_bfloat162(h0, h1);
    H[i*2+1] = __nv_bfloat162(h2, h3);
    L[i*2+0] = __nv_bfloat162(__float2bfloat16(v.x - __bfloat162float(h0)),
                              __float2bfloat16(v.y - __bfloat162float(h1)));
    L[i*2+1] = __nv_bfloat162(__float2bfloat16(v.z - __bfloat162float(h2)),
                              __float2bfloat16(v.w - __bfloat162float(h3)));
}

#define N4_X  (NTOK * DM / 4)
#define N4_W1 (2 * DI * DM / 4)
#define N4_WO (DM * DI / 4)
#define N4_XP (RTOT * DI / 4)
#define N4_DW (DI * DTR / 4)
#define N4_A  (DI / 4)
#define N4_ALL (N4_X + N4_W1 + N4_WO + N4_XP + N4_DW + N4_A)

__global__ void split_all_kernel(const float* __restrict__ x, const float* __restrict__ w1,
                                 const float* __restrict__ wo, const float* __restrict__ xp,
                                 const float* __restrict__ dw, const float* __restrict__ Alogs)
{
    int i = blockIdx.x * blockDim.x + threadIdx.x;
    if (i < N4_X) { split4(((const float4*)x)[i], g_xhi, g_xlo, i); return; }
    i -= N4_X;
    if (i < N4_W1) { split4(((const float4*)w1)[i], g_w1hi, g_w1lo, i); return; }
    i -= N4_W1;
    if (i < N4_WO) { split4(((const float4*)wo)[i], g_wohi, g_wolo, i); return; }
    i -= N4_WO;
    if (i < N4_XP) { split4(((const float4*)xp)[i], g_xphi, g_xplo, i); return; }
    i -= N4_XP;
    if (i < N4_DW) { split4(((const float4*)dw)[i], g_dwhi, g_dwlo, i); return; }
    i -= N4_DW;
    if (i < N4_A) {
        float4 a = ((const float4*)Alogs)[i];
        g_A[i*4+0] = -expf(a.x); g_A[i*4+1] = -expf(a.y);
        g_A[i*4+2] = -expf(a.z); g_A[i*4+3] = -expf(a.w);
    }
}

// ---------------- depthwise conv (k=2) + SiLU, vectorized x4, bf16-split output ----------------
__global__ void conv_silu_kernel(const float* __restrict__ cw, const float* __restrict__ cb)
{
    int idx = blockIdx.x * blockDim.x + threadIdx.x;
    if (idx >= NTOK * DI / 4) return;
    int d4  = idx & (DI / 4 - 1);
    int tok = idx >> 8;
    int l   = tok & (LL - 1);
    int d   = d4 * 4;

    float4 cur  = *(const float4*)(g_xz + (size_t)tok * (2 * DI) + d);
    float4 prev = make_float4(0.f, 0.f, 0.f, 0.f);
    if (l > 0) prev = *(const float4*)(g_xz + (size_t)(tok - 1) * (2 * DI) + d);
    float4 w0 = *(const float4*)(cw + 2 * d);
    float4 w1 = *(const float4*)(cw + 2 * d + 4);
    float4 b  = *(const float4*)(cb + d);

    float s0 = silu_fast(fmaf(w0.x, prev.x, fmaf(w0.y, cur.x, b.x)));
    float s1 = silu_fast(fmaf(w0.z, prev.y, fmaf(w0.w, cur.y, b.y)));
    float s2 = silu_fast(fmaf(w1.x, prev.z, fmaf(w1.y, cur.z, b.z)));
    float s3 = silu_fast(fmaf(w1.z, prev.w, fmaf(w1.w, cur.w, b.w)));

    __nv_bfloat16 h0 = __float2bfloat16(s0), h1 = __float2bfloat16(s1);
    __nv_bfloat16 h2 = __float2bfloat16(s2), h3 = __float2bfloat16(s3);
    __nv_bfloat162* H = (__nv_bfloat162*)(g_xchi + (size_t)tok * DI + d);
    __nv_bfloat162* L = (__nv_bfloat162*)(g_xclo + (size_t)tok * DI + d);
    H[0] = __nv_bfloat162(h0, h1);
    H[1] = __nv_bfloat162(h2, h3);
    L[0] = __nv_bfloat162(__float2bfloat16(s0 - __bfloat162float(h0)),
                          __float2bfloat16(s1 - __bfloat162float(h1)));
    L[1] = __nv_bfloat162(__float2bfloat16(s2 - __bfloat162float(h2)),
                          __float2bfloat16(s3 - __bfloat162float(h3)));
}

// ---------------- chunk-state chain: h0 per (b, chunk, d) ----------------
__global__ void scan_chain_kernel()
{
    int t = blockIdx.x * blockDim.x + threadIdx.x;   // BB*DI threads
    if (t >= BB * DI) return;
    int d = t & (DI - 1);
    int b = t >> 10;
    float h = 0.f;
#pragma unroll
    for (int c = 0; c < NCH; c++) {
        g_h0[((size_t)(b * NCH) + c) * DI + d] = h;
        size_t last = ((size_t)b * LL + c * CH + (CH - 1)) * DI + d;
        h = fmaf(g_P[last], h, g_hl[last]);
    }
}

// ---------------- fused y + LayerNorm + SiLU gate + bf16 split ----------------
__global__ void __launch_bounds__(256) ln_gate_kernel(const float* __restrict__ lnw,
                                                      const float* __restrict__ lnb,
                                                      const float* __restrict__ Ds)
{
    int tok = blockIdx.x;
    int tid = threadIdx.x;
    size_t base = (size_t)tok * DI;
    int d = tid * 4;
    int b = tok >> 12;                 // / LL
    int c = (tok & (LL - 1)) >> 7;     // / CH
    size_t h0off = ((size_t)(b * NCH) + c) * DI + d;

    // reconstruct y = (hl + h0*P)*Cs + u*D
    float4 P  = *(const float4*)(g_P  + base + d);
    float4 hl = *(const float4*)(g_hl + base + d);
    float4 h0v = *(const float4*)(g_h0 + h0off);
    __nv_bfloat162 uh0 = *(const __nv_bfloat162*)(g_xchi + base + d);
    __nv_bfloat162 uh1 = *(const __nv_bfloat162*)(g_xchi + base + d + 2);
    __nv_bfloat162 ul0 = *(const __nv_bfloat162*)(g_xclo + base + d);
    __nv_bfloat162 ul1 = *(const __nv_bfloat162*)(g_xclo + base + d + 2);
    float Cs = g_xdbl[(size_t)tok * RPAD + DTR + 1];
    float4 Dd = *(const float4*)(Ds + d);

    float4 v;
    v.x = fmaf(fmaf(h0v.x, P.x, hl.x), Cs,
               (__bfloat162float(uh0.x) + __bfloat162float(ul0.x)) * Dd.x);
    v.y = fmaf(fmaf(h0v.y, P.y, hl.y), Cs,
               (__bfloat162float(uh0.y) + __bfloat162float(ul0.y)) * Dd.y);
    v.z = fmaf(fmaf(h0v.z, P.z, hl.z), Cs,
               (__bfloat162float(uh1.x) + __bfloat162float(ul1.x)) * Dd.z);
    v.w = fmaf(fmaf(h0v.w, P.w, hl.w), Cs,
               (__bfloat162float(uh1.y) + __bfloat162float(ul1.y)) * Dd.w);

    float s = v.x + v.y + v.z + v.w;
    float q = v.x * v.x + v.y * v.y + v.z * v.z + v.w * v.w;
#pragma unroll
    for (int o = 16; o; o >>= 1) {
        s += __shfl_xor_sync(0xffffffffu, s, o);
        q += __shfl_xor_sync(0xffffffffu, q, o);
    }
    __shared__ float ss[8], sq[8];
    if ((tid & 31) == 0) { ss[tid >> 5] = s; sq[tid >> 5] = q; }
    __syncthreads();
    float S = 0.f, Q = 0.f;
#pragma unroll
    for (int w = 0; w < 8; w++) { S += ss[w]; Q += sq[w]; }

    float mu  = S * (1.f / DI);
    float var = Q * (1.f / DI) - mu * mu;
    float rs  = rsqrtf(var + 1e-5f);

    float4 z  = *(const float4*)(g_xz + (size_t)tok * (2 * DI) + DI + d);
    float4 w4 = *(const float4*)(lnw + d);
    float4 b4 = *(const float4*)(lnb + d);

    float o0 = fmaf((v.x - mu) * rs, w4.x, b4.x) * silu_fast(z.x);
    float o1 = fmaf((v.y - mu) * rs, w4.y, b4.y) * silu_fast(z.y);
    float o2 = fmaf((v.z - mu) * rs, w4.z, b4.z) * silu_fast(z.z);
    float o3 = fmaf((v.w - mu) * rs, w4.w, b4.w) * silu_fast(z.w);

    __nv_bfloat16 h0b = __float2bfloat16(o0), h1b = __float2bfloat16(o1);
    __nv_bfloat16 h2b = __float2bfloat16(o2), h3b = __float2bfloat16(o3);
    __nv_bfloat162* H = (__nv_bfloat162*)(g_yhi + base + d);
    __nv_bfloat162* L = (__nv_bfloat162*)(g_ylo + base + d);
    H[0] = __nv_bfloat162(h0b, h1b);
    H[1] = __nv_bfloat162(h2b, h3b);
    L[0] = __nv_bfloat162(__float2bfloat16(o0 - __bfloat162float(h0b)),
                          __float2bfloat16(o1 - __bfloat162float(h1b)));
    L[1] = __nv_bfloat162(__float2bfloat16(o2 - __bfloat162float(h2b)),
                          __float2bfloat16(o3 - __bfloat162float(h3b)));
}

// ---------------- launch ----------------
extern "C" void kernel_launch(void* const* d_in, const int* in_sizes, int n_in,
                              void* d_out, int out_size)
{
    const float* x      = (const float*)d_in[0];
    const float* w_in   = (const float*)d_in[1];
    const float* conv_w = (const float*)d_in[2];
    const float* conv_b = (const float*)d_in[3];
    const float* xproj  = (const float*)d_in[4];
    const float* dtw    = (const float*)d_in[5];
    const float* dtb    = (const float*)d_in[6];
    const float* Alogs  = (const float*)d_in[7];
    const float* Ds     = (const float*)d_in[8];
    const float* lnw    = (const float*)d_in[9];
    const float* lnb    = (const float*)d_in[10];
    const float* wout   = (const float*)d_in[11];
    float* out = (float*)d_out;

    float *xz, *xdbl;
    __nv_bfloat16 *xhi, *xlo, *w1hi, *w1lo, *yhi, *ylo, *wohi, *wolo;
    __nv_bfloat16 *xchi, *xclo, *xphi, *xplo, *dshi, *dslo, *dwhi, *dwlo;
    cudaGetSymbolAddress((void**)&xz,   g_xz);
    cudaGetSymbolAddress((void**)&xdbl, g_xdbl);
    cudaGetSymbolAddress((void**)&xhi,  g_xhi);
    cudaGetSymbolAddress((void**)&xlo,  g_xlo);
    cudaGetSymbolAddress((void**)&w1hi, g_w1hi);
    cudaGetSymbolAddress((void**)&w1lo, g_w1lo);
    cudaGetSymbolAddress((void**)&yhi,  g_yhi);
    cudaGetSymbolAddress((void**)&ylo,  g_ylo);
    cudaGetSymbolAddress((void**)&wohi, g_wohi);
    cudaGetSymbolAddress((void**)&wolo, g_wolo);
    cudaGetSymbolAddress((void**)&xchi, g_xchi);
    cudaGetSymbolAddress((void**)&xclo, g_xclo);
    cudaGetSymbolAddress((void**)&xphi, g_xphi);
    cudaGetSymbolAddress((void**)&xplo, g_xplo);
    cudaGetSymbolAddress((void**)&dshi, g_dshi);
    cudaGetSymbolAddress((void**)&dslo, g_dslo);
    cudaGetSymbolAddress((void**)&dwhi, g_dwhi);
    cudaGetSymbolAddress((void**)&dwlo, g_dwlo);

    const int SMEM_MMA = 3 * STG_B;   // 98304 bytes, 2 CTAs/SM
    cudaFuncSetAttribute(mma_gemm<0>, cudaFuncAttributeMaxDynamicSharedMemorySize, SMEM_MMA);
    cudaFuncSetAttribute(mma_gemm<1>, cudaFuncAttributeMaxDynamicSharedMemorySize, SMEM_MMA);
    cudaFuncSetAttribute(mma_gemm<2>, cudaFuncAttributeMaxDynamicSharedMemorySize, SMEM_MMA);

    // 0) all fp32 -> bf16 hi/lo splits + A precompute
    split_all_kernel<<<(N4_ALL + 255) / 256, 256>>>(x, w_in, wout, xproj, dtw, Alogs);

    // 1) xz = x @ w_in^T  (HMMA)
    mma_gemm<0><<<dim3(2 * DI / 128, NTOK / 128), 128, SMEM_MMA>>>(
        xhi, xlo, w1hi, w1lo, xz, 2 * DI, DM, 0, nullptr);

    // 2) depthwise conv + silu
    conv_silu_kernel<<<(NTOK * DI / 4 + 255) / 256, 256>>>(conv_w, conv_b);

    // 3) x_dbl = xc @ xproj^T  (HMMA, ragged nvalid=66, dts bf16 split emitted)
    mma_gemm<1><<<dim3(1, NTOK / 128), 128, SMEM_MMA>>>(
        xchi, xclo, xphi, xplo, xdbl, RPAD, DI, RTOT, nullptr);

    // 4) dt GEMM (HMMA, K=64) + fused SSM prep + in-epilogue chunk scan -> g_P, g_hl
    mma_gemm<2><<<dim3(DI / 128, NTOK / 128), 128, SMEM_MMA>>>(
        dshi, dslo, dwhi, dwlo, nullptr, 0, DTR, 0, dtb);

    // 5) chunk-state chain -> g_h0
    scan_chain_kernel<<<(BB * DI + 255) / 256, 256>>>();

    // 6) fused y + LayerNorm + gate -> bf16 hi/lo
    ln_gate_kernel<<<NTOK, 256>>>(lnw, lnb, Ds);

    // 7) out = yln @ w_out^T  (HMMA)
    mma_gemm<0><<<dim3(DI / 128, NTOK / 128), 128, SMEM_MMA>>>(
        yhi, ylo, wohi, wolo, out, DM, DI, 0, nullptr);
}